// round 10
// baseline (speedup 1.0000x reference)
#include <cuda_runtime.h>
#include <cuda_bf16.h>
#include <cstdint>
#include <math.h>

#define NV 10000
#define NF 80000
#define NE 160000

#define ER 272
#define EA_LO 17408
#define EW_LO128 34816
#define EW_LO64  17408

#define GR 272
#define GA_LO 34816
#define GW_LO 69632

__device__ float g_var_h[NV * 64];
__device__ float g_fac_h[NF * 64];
__device__ float g_nm_var[NV * 64];
__device__ float g_nm_fac[NF * 64];
__device__ __nv_bfloat16 g_var_hhi[NV * 64];
__device__ __nv_bfloat16 g_var_hlo[NV * 64];
__device__ __nv_bfloat16 g_fac_hhi[NF * 64];
__device__ __nv_bfloat16 g_fac_hlo[NF * 64];
__device__ __nv_bfloat16 g_f2v_fhi[NE * 4];
__device__ __nv_bfloat16 g_f2v_flo[NE * 4];
__device__ __nv_bfloat16 g_v2f_fhi[NE * 4];
__device__ __nv_bfloat16 g_v2f_flo[NE * 4];
__device__ __align__(256) unsigned char g_wpack_f2v[174080];
__device__ __align__(256) unsigned char g_wpack_v2f[174080];
__device__ __align__(256) unsigned char g_wgru_gf[139264];
__device__ __align__(256) unsigned char g_wgru_gv[139264];

__device__ __forceinline__ uint32_t smem_u32(const void* p) {
    uint32_t a;
    asm("{ .reg .u64 t; cvta.to.shared.u64 t, %1; cvt.u32.u64 %0, t; }" : "=r"(a) : "l"(p));
    return a;
}
#define MBARRIER_INIT(mbar, cnt) \
    asm volatile("mbarrier.init.shared.b64 [%0], %1;" :: "r"(mbar), "r"(cnt) : "memory")
#define MBARRIER_EXPECT_TX(mbar, bytes) \
    asm volatile("mbarrier.arrive.expect_tx.shared.b64 _, [%0], %1;" :: "r"(mbar), "r"(bytes) : "memory")
#define MBARRIER_WAIT_PARITY(mbar, ph) do { \
    asm volatile("{\n\t.reg .pred P1;\n\t" \
        "W_%=:\n\tmbarrier.try_wait.parity.acquire.cta.shared::cta.b64 P1, [%0], %1, 0x989680;\n\t" \
        "@P1 bra.uni D_%=;\n\tbra.uni W_%=;\n\tD_%=:\n\t}" \
        :: "r"(mbar), "r"(ph) : "memory"); \
} while (0)
#define LANE_BAR(id) asm volatile("bar.sync %0, 256;" :: "r"(id) : "memory")

__device__ __forceinline__ void bulk_copy_g2s(uint32_t dst, const void* src,
                                              uint32_t bytes, uint32_t mbar) {
    asm volatile(
        "cp.async.bulk.shared::cluster.global.mbarrier::complete_tx::bytes [%0], [%1], %2, [%3];"
        :: "r"(dst), "l"(src), "r"(bytes), "r"(mbar) : "memory");
}
__device__ __forceinline__ void ldsm4(uint32_t addr, uint32_t* r) {
    asm volatile("ldmatrix.sync.aligned.m8n8.x4.shared.b16 {%0,%1,%2,%3}, [%4];"
        : "=r"(r[0]), "=r"(r[1]), "=r"(r[2]), "=r"(r[3]) : "r"(addr));
}
__device__ __forceinline__ void mma16816(float* d, const uint32_t* a, const uint32_t* b) {
    asm volatile("mma.sync.aligned.m16n8k16.row.col.f32.bf16.bf16.f32 "
        "{%0,%1,%2,%3}, {%4,%5,%6,%7}, {%8,%9}, {%0,%1,%2,%3};"
        : "+f"(d[0]), "+f"(d[1]), "+f"(d[2]), "+f"(d[3])
        : "r"(a[0]), "r"(a[1]), "r"(a[2]), "r"(a[3]), "r"(b[0]), "r"(b[1]));
}
__device__ __forceinline__ void mma16808(float* d, const uint32_t* a, uint32_t b) {
    asm volatile("mma.sync.aligned.m16n8k8.row.col.f32.bf16.bf16.f32 "
        "{%0,%1,%2,%3}, {%4,%5}, {%6}, {%0,%1,%2,%3};"
        : "+f"(d[0]), "+f"(d[1]), "+f"(d[2]), "+f"(d[3])
        : "r"(a[0]), "r"(a[1]), "r"(b));
}

__global__ void zero_kernel(float* __restrict__ p, int n) {
    int i = blockIdx.x * blockDim.x + threadIdx.x;
    for (; i < n; i += gridDim.x * blockDim.x) p[i] = 0.0f;
}

__global__ void pack_split_kernel(__nv_bfloat16* __restrict__ hi_out,
                                  __nv_bfloat16* __restrict__ lo_out,
                                  const float* __restrict__ src, int n) {
    for (int i = blockIdx.x * blockDim.x + threadIdx.x; i < n;
         i += gridDim.x * blockDim.x) {
        float v = src[i];
        __nv_bfloat16 hi = __float2bfloat16(v);
        hi_out[i] = hi;
        lo_out[i] = __float2bfloat16(v - __bfloat162float(hi));
    }
}

__global__ void pack_weights_kernel(unsigned char* __restrict__ dst,
                                    const float* __restrict__ W,
                                    int nrows, int kin) {
    const int total = nrows * 136;
    const int plane = nrows * ER;
    for (int i = blockIdx.x * blockDim.x + threadIdx.x; i < total;
         i += gridDim.x * blockDim.x) {
        int n = i / 136, k = i - n * 136;
        float v = (k < kin) ? W[n * kin + k] : 0.0f;
        __nv_bfloat16 hi = __float2bfloat16(v);
        __nv_bfloat16 lo = __float2bfloat16(v - __bfloat162float(hi));
        uint32_t off = (uint32_t)n * ER + (uint32_t)k * 2;
        *(__nv_bfloat16*)(dst + off) = hi;
        *(__nv_bfloat16*)(dst + plane + off) = lo;
    }
}

__global__ void pack_gru_kernel(unsigned char* __restrict__ dst,
                                const float* __restrict__ wih,
                                const float* __restrict__ whh) {
    const int total = 256 * 136;
    for (int i = blockIdx.x * blockDim.x + threadIdx.x; i < total;
         i += gridDim.x * blockDim.x) {
        int r = i / 136, k = i - r * 136;
        float v = 0.0f;
        if (k < 128) {
            if (r < 128)       v = (k < 64) ? wih[r * 64 + k] : whh[r * 64 + (k - 64)];
            else if (r < 192)  { if (k < 64)  v = wih[r * 64 + k]; }
            else               { if (k >= 64) v = whh[(r - 64) * 64 + (k - 64)]; }
        }
        __nv_bfloat16 hi = __float2bfloat16(v);
        __nv_bfloat16 lo = __float2bfloat16(v - __bfloat162float(hi));
        uint32_t off = (uint32_t)r * GR + (uint32_t)k * 2;
        *(__nv_bfloat16*)(dst + off) = hi;
        *(__nv_bfloat16*)(dst + GW_LO + off) = lo;
    }
}

template<int KCH, int NPAIR>
__device__ __forceinline__ void layer_mma_s(
    uint32_t aA, uint32_t aW, uint32_t rstr, uint32_t aLo, uint32_t wLo,
    int lane, int mbase, int nbase, float* acc)
{
    const uint32_t aRow = aA + (uint32_t)(mbase + (lane & 15)) * rstr + ((lane >> 4) << 4);
    const uint32_t bRow = aW + (uint32_t)(nbase + (lane & 7) + ((lane >> 4) << 3)) * rstr
                        + (((lane >> 3) & 1) << 4);
    #pragma unroll
    for (int kc = 0; kc < KCH; kc++) {
        uint32_t ah[8], al[8];
        ldsm4(aRow + kc * 32, ah);
        ldsm4(aRow + 16 * rstr + kc * 32, ah + 4);
        ldsm4(aRow + aLo + kc * 32, al);
        ldsm4(aRow + aLo + 16 * rstr + kc * 32, al + 4);
        #pragma unroll
        for (int np = 0; np < NPAIR; np++) {
            uint32_t bh[4], bl[4];
            ldsm4(bRow + np * 16 * rstr + kc * 32, bh);
            ldsm4(bRow + wLo + np * 16 * rstr + kc * 32, bl);
            #pragma unroll
            for (int m = 0; m < 2; m++) {
                #pragma unroll
                for (int h = 0; h < 2; h++) {
                    float* d = acc + ((m * NPAIR + np) * 2 + h) * 4;
                    mma16816(d, ah + m * 4, bh + h * 2);
                    mma16816(d, ah + m * 4, bl + h * 2);
                    mma16816(d, al + m * 4, bh + h * 2);
                }
            }
        }
    }
}

__device__ __forceinline__ void layer1_tail(
    uint32_t aA, uint32_t aW, int lane, int mbase, int nbase, float* acc)
{
    const uint32_t aAddr = aA + (uint32_t)(mbase + lane) * ER + 256;
    const uint32_t bAddr = aW + (uint32_t)(nbase + lane) * ER + 256;
    uint32_t ah[4], al[4], bh[4], bl[4];
    ldsm4(aAddr, ah);
    ldsm4(aAddr + EA_LO, al);
    ldsm4(bAddr, bh);
    ldsm4(bAddr + EW_LO128, bl);
    #pragma unroll
    for (int m = 0; m < 2; m++)
        #pragma unroll
        for (int n4 = 0; n4 < 4; n4++) {
            float* d = acc + ((m * 2 + (n4 >> 1)) * 2 + (n4 & 1)) * 4;
            mma16808(d, ah + 2 * m, bh[n4]);
            mma16808(d, ah + 2 * m, bl[n4]);
            mma16808(d, al + 2 * m, bh[n4]);
        }
}

__device__ __forceinline__ void epi12(unsigned char* Ab, const float* bias,
                                      int lane, int mbase, int nbase, const float* acc)
{
    #pragma unroll
    for (int m = 0; m < 2; m++)
        #pragma unroll
        for (int np = 0; np < 2; np++)
            #pragma unroll
            for (int h = 0; h < 2; h++) {
                const float* d = acc + ((m * 2 + np) * 2 + h) * 4;
                int c = nbase + np * 16 + h * 8 + 2 * (lane & 3);
                int r = mbase + m * 16 + (lane >> 2);
                float b0 = bias[c], b1 = bias[c + 1];
                float v0 = fmaxf(d[0] + b0, 0.f), v1 = fmaxf(d[1] + b1, 0.f);
                float v2 = fmaxf(d[2] + b0, 0.f), v3 = fmaxf(d[3] + b1, 0.f);
                __nv_bfloat162 hA = __floats2bfloat162_rn(v0, v1);
                __nv_bfloat162 lA = __floats2bfloat162_rn(v0 - __low2float(hA),
                                                          v1 - __high2float(hA));
                __nv_bfloat162 hB = __floats2bfloat162_rn(v2, v3);
                __nv_bfloat162 lB = __floats2bfloat162_rn(v2 - __low2float(hB),
                                                          v3 - __high2float(hB));
                uint32_t o0 = (uint32_t)r * ER + (uint32_t)c * 2;
                uint32_t o1 = o0 + 8u * ER;
                *(uint32_t*)(Ab + o0)         = *(uint32_t*)&hA;
                *(uint32_t*)(Ab + EA_LO + o0) = *(uint32_t*)&lA;
                *(uint32_t*)(Ab + o1)         = *(uint32_t*)&hB;
                *(uint32_t*)(Ab + EA_LO + o1) = *(uint32_t*)&lB;
            }
}

// ---------------- edge MLP: two 128-thread... (two 256-thread lanes) --------
// Lane = 256 threads = 8 warps, own 64-edge tile, R9 warp grid (2m x 4n).
// W stream shared: W1->bufA, W2->bufB, W3->bufA (after one joint sync).
#define SM_BUFA 69632
#define SM_BUFB 139264
#define SM_IDX  208896
#define SM_BIAS 209408
#define SM_MB   210688
#define EDGE_SMEM_BYTES 210720
template<int DIR>
__global__ __launch_bounds__(512, 1) void edge_mma_kernel(
    const __nv_bfloat16* __restrict__ Ahi, const __nv_bfloat16* __restrict__ Alo,
    const __nv_bfloat16* __restrict__ Bhi, const __nv_bfloat16* __restrict__ Blo,
    const int* __restrict__ idxArr,
    const __nv_bfloat16* __restrict__ fhi, const __nv_bfloat16* __restrict__ flo,
    const unsigned char* __restrict__ wsrc,
    const float* __restrict__ b1, const float* __restrict__ b2,
    const float* __restrict__ b3,
    float* __restrict__ nm)
{
    extern __shared__ __align__(256) unsigned char sm[];
    const uint32_t smb = smem_u32(sm);
    const int tid  = threadIdx.x;
    const int ln   = tid >> 8;
    const int ltid = tid & 255;
    const int barid = ln + 1;

    const int e0 = (blockIdx.x * 2 + ln) * 64;
    const int p0 = e0 >> 1;

    unsigned char* smA = sm + ln * 34816;
    const uint32_t smbA = smb + ln * 34816;
    int*   idx    = (int*)(sm + SM_IDX) + ln * 64;
    float* bias_s = (float*)(sm + SM_BIAS);
    const uint32_t mb0 = smb + SM_MB;
    const uint32_t mb1 = smb + SM_MB + 8;

    if (tid == 0) { MBARRIER_INIT(mb0, 1u); MBARRIER_INIT(mb1, 1u); }
    __syncthreads();
    if (tid == 0) {
        MBARRIER_EXPECT_TX(mb0, 69632u);
        bulk_copy_g2s(smb + SM_BUFA, wsrc, 69632u, mb0);
        MBARRIER_EXPECT_TX(mb1, 69632u);
        bulk_copy_g2s(smb + SM_BUFB, wsrc + 69632, 69632u, mb1);
    }
    if (ltid < 64) idx[ltid] = idxArr[e0 + ltid];
    for (int i = tid; i < 320; i += 512)
        bias_s[i] = (i < 128) ? b1[i] : (i < 256 ? b2[i - 128] : b3[i - 256]);
    LANE_BAR(barid);

    {
        int r = ltid >> 3, q = ltid & 7;
        const __nv_bfloat16* srcH = (DIR == 0) ? Ahi : Bhi;
        const __nv_bfloat16* srcL = (DIR == 0) ? Alo : Blo;
        uint4 hv = *(const uint4*)(srcH + (size_t)(p0 + r) * 64 + q * 8);
        uint4 lv = *(const uint4*)(srcL + (size_t)(p0 + r) * 64 + q * 8);
        uint32_t cb = (DIR == 0) ? 0u : 128u;
        uint32_t o0 = (uint32_t)(2 * r)     * ER + cb + q * 16;
        uint32_t o1 = (uint32_t)(2 * r + 1) * ER + cb + q * 16;
        *(uint4*)(smA + o0)         = hv;  *(uint4*)(smA + o1)         = hv;
        *(uint4*)(smA + EA_LO + o0) = lv;  *(uint4*)(smA + EA_LO + o1) = lv;
    }
    for (int i = ltid; i < 512; i += 256) {
        int e = i >> 3, q = i & 7;
        int s = idx[e];
        const __nv_bfloat16* srcH = (DIR == 0) ? Bhi : Ahi;
        const __nv_bfloat16* srcL = (DIR == 0) ? Blo : Alo;
        uint4 hv = *(const uint4*)(srcH + (size_t)s * 64 + q * 8);
        uint4 lv = *(const uint4*)(srcL + (size_t)s * 64 + q * 8);
        uint32_t cb = (DIR == 0) ? 128u : 0u;
        uint32_t o = (uint32_t)e * ER + cb + q * 16;
        *(uint4*)(smA + o)         = hv;
        *(uint4*)(smA + EA_LO + o) = lv;
    }
    if (ltid < 64) {
        int e = ltid;
        int rowIdx = (DIR == 0) ? (p0 + (e >> 1)) : idx[e];
        int colIdx = (DIR == 0) ? idx[e] : (p0 + (e >> 1));
        uint2 rh = *(const uint2*)(fhi + (size_t)rowIdx * 4);
        uint2 ch = *(const uint2*)(fhi + (size_t)colIdx * 4);
        uint2 rl = *(const uint2*)(flo + (size_t)rowIdx * 4);
        uint2 cl = *(const uint2*)(flo + (size_t)colIdx * 4);
        uint32_t o = (uint32_t)e * ER + 256;
        *(uint4*)(smA + o)         = make_uint4(rh.x, rh.y, ch.x, ch.y);
        *(uint4*)(smA + EA_LO + o) = make_uint4(rl.x, rl.y, cl.x, cl.y);
    }
    LANE_BAR(barid);

    const int w = ltid >> 5, lane = ltid & 31;   // 8 warps/lane, 2m x 4n
    const int mbase = (w & 1) * 32;
    const int nb32  = (w >> 1) * 32;
    const int nb16  = (w >> 1) * 16;
    float acc[32];

    // ---- layer 1: K=136, N=128, W in bufA ----
    MBARRIER_WAIT_PARITY(mb0, 0);
    #pragma unroll
    for (int i = 0; i < 32; i++) acc[i] = 0.f;
    layer_mma_s<8, 2>(smbA, smb + SM_BUFA, ER, EA_LO, EW_LO128, lane, mbase, nb32, acc);
    layer1_tail(smbA, smb + SM_BUFA, lane, mbase, nb32, acc);

    __syncthreads();   // JOINT: both lanes done reading bufA -> W3 may overwrite
    if (tid == 0) {
        MBARRIER_EXPECT_TX(mb0, 34816u);
        bulk_copy_g2s(smb + SM_BUFA, wsrc + 139264, 34816u, mb0);
    }
    epi12(smA, bias_s, lane, mbase, nb32, acc);
    LANE_BAR(barid);

    // ---- layer 2: K=128, N=128, W in bufB ----
    MBARRIER_WAIT_PARITY(mb1, 0);
    #pragma unroll
    for (int i = 0; i < 32; i++) acc[i] = 0.f;
    layer_mma_s<8, 2>(smbA, smb + SM_BUFB, ER, EA_LO, EW_LO128, lane, mbase, nb32, acc);
    LANE_BAR(barid);
    epi12(smA, bias_s + 128, lane, mbase, nb32, acc);
    LANE_BAR(barid);

    // ---- layer 3: K=128, N=64, W in bufA (phase 1) ----
    MBARRIER_WAIT_PARITY(mb0, 1);
    #pragma unroll
    for (int i = 0; i < 16; i++) acc[i] = 0.f;
    layer_mma_s<8, 1>(smbA, smb + SM_BUFA, ER, EA_LO, EW_LO64, lane, mbase, nb16, acc);

    if (DIR == 0) {
        #pragma unroll
        for (int m = 0; m < 2; m++)
            #pragma unroll
            for (int h = 0; h < 2; h++) {
                const float* d = acc + (m * 2 + h) * 4;
                int c = nb16 + h * 8 + 2 * (lane & 3);
                int r = mbase + m * 16 + (lane >> 2);
                float b0 = bias_s[256 + c], b1v = bias_s[256 + c + 1];
                float* q0 = nm + (size_t)idx[r] * 64 + c;
                float* q1 = nm + (size_t)idx[r + 8] * 64 + c;
                atomicAdd(q0,     d[0] + b0);
                atomicAdd(q0 + 1, d[1] + b1v);
                atomicAdd(q1,     d[2] + b0);
                atomicAdd(q1 + 1, d[3] + b1v);
            }
    } else {
        LANE_BAR(barid);
        float* st = (float*)smA;
        #pragma unroll
        for (int m = 0; m < 2; m++)
            #pragma unroll
            for (int h = 0; h < 2; h++) {
                const float* d = acc + (m * 2 + h) * 4;
                int c = nb16 + h * 8 + 2 * (lane & 3);
                int r = mbase + m * 16 + (lane >> 2);
                float b0 = bias_s[256 + c], b1v = bias_s[256 + c + 1];
                st[r * 68 + c]           = d[0] + b0;
                st[r * 68 + c + 1]       = d[1] + b1v;
                st[(r + 8) * 68 + c]     = d[2] + b0;
                st[(r + 8) * 68 + c + 1] = d[3] + b1v;
            }
        LANE_BAR(barid);
        for (int i = ltid; i < 2048; i += 256) {
            int r = i >> 6, c = i & 63;
            nm[(size_t)(p0 + r) * 64 + c] = st[(2 * r) * 68 + c] + st[(2 * r + 1) * 68 + c];
        }
    }
}

// ---------------- HMMA GRU (unchanged from R9) ------------------------------
#define GSM_W    69632
#define GSM_BIAS 208896
#define GSM_MBW  209920
#define GRU_SMEM_BYTES 209952
__global__ __launch_bounds__(512, 1) void gru_mma_kernel(
    float* __restrict__ h,
    __nv_bfloat16* __restrict__ h_hi, __nv_bfloat16* __restrict__ h_lo,
    float* __restrict__ x,
    const unsigned char* __restrict__ wsrc,
    const float* __restrict__ bih, const float* __restrict__ bhh,
    int nrows)
{
    extern __shared__ __align__(256) unsigned char sm[];
    const uint32_t smb = smem_u32(sm);
    const int tid = threadIdx.x;
    const int r0 = blockIdx.x * 128;

    float* bias_s = (float*)(sm + GSM_BIAS);
    float* gs     = (float*)(sm + GSM_W);
    const uint32_t mbw = smb + GSM_MBW;

    if (tid == 0) MBARRIER_INIT(mbw, 1u);
    __syncthreads();
    if (tid == 0) {
        MBARRIER_EXPECT_TX(mbw, 139264u);
        bulk_copy_g2s(smb + GSM_W, wsrc, 139264u, mbw);
    }
    for (int i = tid; i < 256; i += 512) {
        float v;
        if (i < 128)      v = bih[i] + bhh[i];
        else if (i < 192) v = bih[i];
        else              v = bhh[i - 64];
        bias_s[i] = v;
    }

    for (int i = tid; i < 128 * 32; i += 512) {
        int e = i >> 5, q = i & 31;
        int rr = r0 + e;
        int rc = rr < nrows ? rr : nrows - 1;
        float4 xv;
        if (q < 16) {
            xv = *(const float4*)(x + (size_t)rc * 64 + q * 4);
            if (rr < nrows) *(float4*)(x + (size_t)rc * 64 + q * 4) = make_float4(0.f, 0.f, 0.f, 0.f);
        } else {
            xv = *(const float4*)(h + (size_t)rc * 64 + (q - 16) * 4);
        }
        __nv_bfloat162 h01 = __floats2bfloat162_rn(xv.x, xv.y);
        __nv_bfloat162 h23 = __floats2bfloat162_rn(xv.z, xv.w);
        __nv_bfloat162 l01 = __floats2bfloat162_rn(xv.x - __low2float(h01), xv.y - __high2float(h01));
        __nv_bfloat162 l23 = __floats2bfloat162_rn(xv.z - __low2float(h23), xv.w - __high2float(h23));
        uint32_t off = (uint32_t)e * GR + (uint32_t)q * 8;
        *(uint2*)(sm + off)         = make_uint2(*(uint32_t*)&h01, *(uint32_t*)&h23);
        *(uint2*)(sm + GA_LO + off) = make_uint2(*(uint32_t*)&l01, *(uint32_t*)&l23);
    }
    __syncthreads();

    const int w = tid >> 5, lane = tid & 31;
    const int mbase = (w & 3) * 32;
    const int nbase = (w >> 2) * 64;
    float acc[64];
    #pragma unroll
    for (int i = 0; i < 64; i++) acc[i] = 0.f;

    MBARRIER_WAIT_PARITY(mbw, 0);
    layer_mma_s<8, 4>(smb, smb + GSM_W, GR, GA_LO, GW_LO, lane, mbase, nbase, acc);
    __syncthreads();

    #pragma unroll
    for (int m = 0; m < 2; m++)
        #pragma unroll
        for (int np = 0; np < 4; np++)
            #pragma unroll
            for (int hh = 0; hh < 2; hh++) {
                const float* d = acc + ((m * 4 + np) * 2 + hh) * 4;
                int c = nbase + np * 16 + hh * 8 + 2 * (lane & 3);
                int r = mbase + m * 16 + (lane >> 2);
                gs[r * 256 + c]           = d[0];
                gs[r * 256 + c + 1]       = d[1];
                gs[(r + 8) * 256 + c]     = d[2];
                gs[(r + 8) * 256 + c + 1] = d[3];
            }
    __syncthreads();

    for (int i = tid; i < 128 * 64; i += 512) {
        int e = i >> 6, d = i & 63;
        int r = r0 + e;
        if (r >= nrows) continue;
        const float* g = gs + e * 256;
        float pr = g[d]       + bias_s[d];
        float pz = g[64 + d]  + bias_s[64 + d];
        float in = g[128 + d] + bias_s[128 + d];
        float hn = g[192 + d] + bias_s[192 + d];
        float rr = 1.f / (1.f + expf(-pr));
        float zz = 1.f / (1.f + expf(-pz));
        float nn = tanhf(in + rr * hn);
        float hv = h[(size_t)r * 64 + d];
        float hnew = (1.f - zz) * nn + zz * hv;
        h[(size_t)r * 64 + d] = hnew;
        __nv_bfloat16 hb = __float2bfloat16(hnew);
        h_hi[(size_t)r * 64 + d] = hb;
        h_lo[(size_t)r * 64 + d] = __float2bfloat16(hnew - __bfloat162float(hb));
    }
}

// ---------------- readout (unchanged) ----------------
__global__ __launch_bounds__(256) void readout_kernel(
    const float* __restrict__ h,
    const float* __restrict__ W1, const float* __restrict__ b1,
    const float* __restrict__ W2, const float* __restrict__ b2,
    const float* __restrict__ W3, const float* __restrict__ b3,
    float* __restrict__ out, int nrows)
{
    __shared__ float hs[32 * 68];
    __shared__ float l1s[32 * 132];
    __shared__ float l2s[32 * 132];
    __shared__ float lg[64];

    const int tid = threadIdx.x;
    const int r0  = blockIdx.x * 32;

    for (int i = tid; i < 32 * 64; i += 256) {
        int e = i >> 6, k = i & 63;
        int r = r0 + e;
        hs[e * 68 + k] = (r < nrows) ? h[(size_t)r * 64 + k] : 0.f;
    }
    __syncthreads();

    const int warp = tid >> 5, lane = tid & 31;
    #pragma unroll
    for (int jc = 0; jc < 4; jc++) {
        const int j0 = warp * 16 + jc * 4;
        float a[4] = {0.f, 0.f, 0.f, 0.f};
        #pragma unroll
        for (int k = 0; k < 64; k += 4) {
            float4 xv = *(const float4*)(hs + lane * 68 + k);
            #pragma unroll
            for (int jj = 0; jj < 4; jj++) {
                float4 wv = *(const float4*)(W1 + (size_t)(j0 + jj) * 64 + k);
                a[jj] += wv.x * xv.x + wv.y * xv.y + wv.z * xv.z + wv.w * xv.w;
            }
        }
        #pragma unroll
        for (int jj = 0; jj < 4; jj++)
            l1s[lane * 132 + j0 + jj] = fmaxf(a[jj] + b1[j0 + jj], 0.f);
    }
    __syncthreads();
    #pragma unroll
    for (int jc = 0; jc < 4; jc++) {
        const int j0 = warp * 16 + jc * 4;
        float a[4] = {0.f, 0.f, 0.f, 0.f};
        #pragma unroll 2
        for (int k = 0; k < 128; k += 4) {
            float4 xv = *(const float4*)(l1s + lane * 132 + k);
            #pragma unroll
            for (int jj = 0; jj < 4; jj++) {
                float4 wv = *(const float4*)(W2 + (size_t)(j0 + jj) * 128 + k);
                a[jj] += wv.x * xv.x + wv.y * xv.y + wv.z * xv.z + wv.w * xv.w;
            }
        }
        #pragma unroll
        for (int jj = 0; jj < 4; jj++)
            l2s[lane * 132 + j0 + jj] = fmaxf(a[jj] + b2[j0 + jj], 0.f);
    }
    __syncthreads();
    if (tid < 64) {
        int e = tid >> 1, j = tid & 1;
        float a = 0.f;
        #pragma unroll 4
        for (int k = 0; k < 128; k += 4) {
            float4 xv = *(const float4*)(l2s + e * 132 + k);
            float4 wv = *(const float4*)(W3 + (size_t)j * 128 + k);
            a += wv.x * xv.x + wv.y * xv.y + wv.z * xv.z + wv.w * xv.w;
        }
        lg[e * 2 + j] = a + b3[j];
    }
    __syncthreads();
    if (tid < 64) {
        int e = tid >> 1, j = tid & 1;
        int r = r0 + e;
        if (r < nrows) {
            float self  = lg[e * 2 + j];
            float other = lg[e * 2 + (j ^ 1)];
            out[(size_t)r * 2 + j] = 1.f / (1.f + expf(other - self));
        }
    }
}

extern "C" void kernel_launch(void* const* d_in, const int* in_sizes, int n_in,
                              void* d_out, int out_size)
{
    const int*   f2v_col  = (const int*)d_in[1];
    const int*   v2f_row  = (const int*)d_in[2];
    const float* f2v_feat = (const float*)d_in[4];
    const float* v2f_feat = (const float*)d_in[5];
    const float* f2v_w1 = (const float*)d_in[6];   const float* f2v_b1 = (const float*)d_in[7];
    const float* f2v_w2 = (const float*)d_in[8];   const float* f2v_b2 = (const float*)d_in[9];
    const float* f2v_w3 = (const float*)d_in[10];  const float* f2v_b3 = (const float*)d_in[11];
    const float* v2f_w1 = (const float*)d_in[12];  const float* v2f_b1 = (const float*)d_in[13];
    const float* v2f_w2 = (const float*)d_in[14];  const float* v2f_b2 = (const float*)d_in[15];
    const float* v2f_w3 = (const float*)d_in[16];  const float* v2f_b3 = (const float*)d_in[17];
    const float* gf_wih = (const float*)d_in[18];  const float* gf_whh = (const float*)d_in[19];
    const float* gf_bih = (const float*)d_in[20];  const float* gf_bhh = (const float*)d_in[21];
    const float* gv_wih = (const float*)d_in[22];  const float* gv_whh = (const float*)d_in[23];
    const float* gv_bih = (const float*)d_in[24];  const float* gv_bhh = (const float*)d_in[25];
    const float* ro_w1  = (const float*)d_in[26];  const float* ro_b1  = (const float*)d_in[27];
    const float* ro_w2  = (const float*)d_in[28];  const float* ro_b2  = (const float*)d_in[29];
    const float* ro_w3  = (const float*)d_in[30];  const float* ro_b3  = (const float*)d_in[31];
    float* out = (float*)d_out;

    float *var_h, *fac_h, *nm_var, *nm_fac;
    __nv_bfloat16 *var_hhi, *var_hlo, *fac_hhi, *fac_hlo;
    __nv_bfloat16 *f2v_fhi, *f2v_flo, *v2f_fhi, *v2f_flo;
    unsigned char *wp_f2v, *wp_v2f, *wg_gf, *wg_gv;
    cudaGetSymbolAddress((void**)&var_h,   g_var_h);
    cudaGetSymbolAddress((void**)&fac_h,   g_fac_h);
    cudaGetSymbolAddress((void**)&nm_var,  g_nm_var);
    cudaGetSymbolAddress((void**)&nm_fac,  g_nm_fac);
    cudaGetSymbolAddress((void**)&var_hhi, g_var_hhi);
    cudaGetSymbolAddress((void**)&var_hlo, g_var_hlo);
    cudaGetSymbolAddress((void**)&fac_hhi, g_fac_hhi);
    cudaGetSymbolAddress((void**)&fac_hlo, g_fac_hlo);
    cudaGetSymbolAddress((void**)&f2v_fhi, g_f2v_fhi);
    cudaGetSymbolAddress((void**)&f2v_flo, g_f2v_flo);
    cudaGetSymbolAddress((void**)&v2f_fhi, g_v2f_fhi);
    cudaGetSymbolAddress((void**)&v2f_flo, g_v2f_flo);
    cudaGetSymbolAddress((void**)&wp_f2v,  g_wpack_f2v);
    cudaGetSymbolAddress((void**)&wp_v2f,  g_wpack_v2f);
    cudaGetSymbolAddress((void**)&wg_gf,   g_wgru_gf);
    cudaGetSymbolAddress((void**)&wg_gv,   g_wgru_gv);

    cudaFuncSetAttribute(edge_mma_kernel<0>, cudaFuncAttributeMaxDynamicSharedMemorySize, EDGE_SMEM_BYTES);
    cudaFuncSetAttribute(edge_mma_kernel<1>, cudaFuncAttributeMaxDynamicSharedMemorySize, EDGE_SMEM_BYTES);
    cudaFuncSetAttribute(gru_mma_kernel,     cudaFuncAttributeMaxDynamicSharedMemorySize, GRU_SMEM_BYTES);

    pack_weights_kernel<<<32, 256>>>(wp_f2v,           f2v_w1, 128, 136);
    pack_weights_kernel<<<32, 256>>>(wp_f2v + 69632,   f2v_w2, 128, 128);
    pack_weights_kernel<<<32, 256>>>(wp_f2v + 139264,  f2v_w3,  64, 128);
    pack_weights_kernel<<<32, 256>>>(wp_v2f,           v2f_w1, 128, 136);
    pack_weights_kernel<<<32, 256>>>(wp_v2f + 69632,   v2f_w2, 128, 128);
    pack_weights_kernel<<<32, 256>>>(wp_v2f + 139264,  v2f_w3,  64, 128);
    pack_gru_kernel<<<32, 256>>>(wg_gf, gf_wih, gf_whh);
    pack_gru_kernel<<<32, 256>>>(wg_gv, gv_wih, gv_whh);
    pack_split_kernel<<<64, 256>>>(f2v_fhi, f2v_flo, f2v_feat, NE * 4);
    pack_split_kernel<<<64, 256>>>(v2f_fhi, v2f_flo, v2f_feat, NE * 4);

    zero_kernel<<<256, 256>>>(var_h, NV * 64);
    zero_kernel<<<512, 256>>>(fac_h, NF * 64);
    zero_kernel<<<256, 256>>>(nm_var, NV * 64);
    zero_kernel<<<256, 256>>>((float*)var_hhi, NV * 32);
    zero_kernel<<<256, 256>>>((float*)var_hlo, NV * 32);
    zero_kernel<<<512, 256>>>((float*)fac_hhi, NF * 32);
    zero_kernel<<<512, 256>>>((float*)fac_hlo, NF * 32);

    for (int s = 0; s < 5; s++) {
        edge_mma_kernel<0><<<NE / 128, 512, EDGE_SMEM_BYTES>>>(
            fac_hhi, fac_hlo, var_hhi, var_hlo, f2v_col, f2v_fhi, f2v_flo,
            wp_f2v, f2v_b1, f2v_b2, f2v_b3, nm_var);
        gru_mma_kernel<<<(NV + 127) / 128, 512, GRU_SMEM_BYTES>>>(
            var_h, var_hhi, var_hlo, nm_var, wg_gf, gf_bih, gf_bhh, NV);

        edge_mma_kernel<1><<<NE / 128, 512, EDGE_SMEM_BYTES>>>(
            var_hhi, var_hlo, fac_hhi, fac_hlo, v2f_row, v2f_fhi, v2f_flo,
            wp_v2f, v2f_b1, v2f_b2, v2f_b3, nm_fac);
        gru_mma_kernel<<<NF / 128, 512, GRU_SMEM_BYTES>>>(
            fac_h, fac_hhi, fac_hlo, nm_fac, wg_gv, gv_bih, gv_bhh, NF);
    }

    readout_kernel<<<(NV + 31) / 32, 256>>>(
        var_h, ro_w1, ro_b1, ro_w2, ro_b2, ro_w3, ro_b3, out, NV);
}

// round 11
// speedup vs baseline: 1.0563x; 1.0563x over previous
#include <cuda_runtime.h>
#include <cuda_bf16.h>
#include <cstdint>
#include <math.h>

#define NV 10000
#define NF 80000
#define NE 160000
#define NTILES 2500
#define EGRID 296

#define ER 272
#define EA_LO 17408
#define EW_LO128 34816
#define EW_LO64  17408

#define GR 272
#define GA_LO 34816
#define GW_LO 69632

__device__ float g_var_h[NV * 64];
__device__ float g_fac_h[NF * 64];
__device__ float g_nm_var[NV * 64];
__device__ float g_nm_fac[NF * 64];
__device__ __nv_bfloat16 g_var_hhi[NV * 64];
__device__ __nv_bfloat16 g_var_hlo[NV * 64];
__device__ __nv_bfloat16 g_fac_hhi[NF * 64];
__device__ __nv_bfloat16 g_fac_hlo[NF * 64];
__device__ __nv_bfloat16 g_f2v_fhi[NE * 4];
__device__ __nv_bfloat16 g_f2v_flo[NE * 4];
__device__ __nv_bfloat16 g_v2f_fhi[NE * 4];
__device__ __nv_bfloat16 g_v2f_flo[NE * 4];
__device__ __align__(256) unsigned char g_wpack_f2v[174080];
__device__ __align__(256) unsigned char g_wpack_v2f[174080];
__device__ __align__(256) unsigned char g_wgru_gf[139264];
__device__ __align__(256) unsigned char g_wgru_gv[139264];

__device__ __forceinline__ uint32_t smem_u32(const void* p) {
    uint32_t a;
    asm("{ .reg .u64 t; cvta.to.shared.u64 t, %1; cvt.u32.u64 %0, t; }" : "=r"(a) : "l"(p));
    return a;
}
#define MBARRIER_INIT(mbar, cnt) \
    asm volatile("mbarrier.init.shared.b64 [%0], %1;" :: "r"(mbar), "r"(cnt) : "memory")
#define MBARRIER_EXPECT_TX(mbar, bytes) \
    asm volatile("mbarrier.arrive.expect_tx.shared.b64 _, [%0], %1;" :: "r"(mbar), "r"(bytes) : "memory")
#define MBARRIER_WAIT_PARITY(mbar, ph) do { \
    asm volatile("{\n\t.reg .pred P1;\n\t" \
        "W_%=:\n\tmbarrier.try_wait.parity.acquire.cta.shared::cta.b64 P1, [%0], %1, 0x989680;\n\t" \
        "@P1 bra.uni D_%=;\n\tbra.uni W_%=;\n\tD_%=:\n\t}" \
        :: "r"(mbar), "r"(ph) : "memory"); \
} while (0)

__device__ __forceinline__ void bulk_copy_g2s(uint32_t dst, const void* src,
                                              uint32_t bytes, uint32_t mbar) {
    asm volatile(
        "cp.async.bulk.shared::cluster.global.mbarrier::complete_tx::bytes [%0], [%1], %2, [%3];"
        :: "r"(dst), "l"(src), "r"(bytes), "r"(mbar) : "memory");
}
__device__ __forceinline__ void ldsm4(uint32_t addr, uint32_t* r) {
    asm volatile("ldmatrix.sync.aligned.m8n8.x4.shared.b16 {%0,%1,%2,%3}, [%4];"
        : "=r"(r[0]), "=r"(r[1]), "=r"(r[2]), "=r"(r[3]) : "r"(addr));
}
__device__ __forceinline__ void mma16816(float* d, const uint32_t* a, const uint32_t* b) {
    asm volatile("mma.sync.aligned.m16n8k16.row.col.f32.bf16.bf16.f32 "
        "{%0,%1,%2,%3}, {%4,%5,%6,%7}, {%8,%9}, {%0,%1,%2,%3};"
        : "+f"(d[0]), "+f"(d[1]), "+f"(d[2]), "+f"(d[3])
        : "r"(a[0]), "r"(a[1]), "r"(a[2]), "r"(a[3]), "r"(b[0]), "r"(b[1]));
}
__device__ __forceinline__ void mma16808(float* d, const uint32_t* a, uint32_t b) {
    asm volatile("mma.sync.aligned.m16n8k8.row.col.f32.bf16.bf16.f32 "
        "{%0,%1,%2,%3}, {%4,%5}, {%6}, {%0,%1,%2,%3};"
        : "+f"(d[0]), "+f"(d[1]), "+f"(d[2]), "+f"(d[3])
        : "r"(a[0]), "r"(a[1]), "r"(b));
}

__global__ void zero_kernel(float* __restrict__ p, int n) {
    int i = blockIdx.x * blockDim.x + threadIdx.x;
    for (; i < n; i += gridDim.x * blockDim.x) p[i] = 0.0f;
}

__global__ void pack_split_kernel(__nv_bfloat16* __restrict__ hi_out,
                                  __nv_bfloat16* __restrict__ lo_out,
                                  const float* __restrict__ src, int n) {
    for (int i = blockIdx.x * blockDim.x + threadIdx.x; i < n;
         i += gridDim.x * blockDim.x) {
        float v = src[i];
        __nv_bfloat16 hi = __float2bfloat16(v);
        hi_out[i] = hi;
        lo_out[i] = __float2bfloat16(v - __bfloat162float(hi));
    }
}

__global__ void pack_weights_kernel(unsigned char* __restrict__ dst,
                                    const float* __restrict__ W,
                                    int nrows, int kin) {
    const int total = nrows * 136;
    const int plane = nrows * ER;
    for (int i = blockIdx.x * blockDim.x + threadIdx.x; i < total;
         i += gridDim.x * blockDim.x) {
        int n = i / 136, k = i - n * 136;
        float v = (k < kin) ? W[n * kin + k] : 0.0f;
        __nv_bfloat16 hi = __float2bfloat16(v);
        __nv_bfloat16 lo = __float2bfloat16(v - __bfloat162float(hi));
        uint32_t off = (uint32_t)n * ER + (uint32_t)k * 2;
        *(__nv_bfloat16*)(dst + off) = hi;
        *(__nv_bfloat16*)(dst + plane + off) = lo;
    }
}

__global__ void pack_gru_kernel(unsigned char* __restrict__ dst,
                                const float* __restrict__ wih,
                                const float* __restrict__ whh) {
    const int total = 256 * 136;
    for (int i = blockIdx.x * blockDim.x + threadIdx.x; i < total;
         i += gridDim.x * blockDim.x) {
        int r = i / 136, k = i - r * 136;
        float v = 0.0f;
        if (k < 128) {
            if (r < 128)       v = (k < 64) ? wih[r * 64 + k] : whh[r * 64 + (k - 64)];
            else if (r < 192)  { if (k < 64)  v = wih[r * 64 + k]; }
            else               { if (k >= 64) v = whh[(r - 64) * 64 + (k - 64)]; }
        }
        __nv_bfloat16 hi = __float2bfloat16(v);
        __nv_bfloat16 lo = __float2bfloat16(v - __bfloat162float(hi));
        uint32_t off = (uint32_t)r * GR + (uint32_t)k * 2;
        *(__nv_bfloat16*)(dst + off) = hi;
        *(__nv_bfloat16*)(dst + GW_LO + off) = lo;
    }
}

template<int KCH, int NPAIR>
__device__ __forceinline__ void layer_mma_s(
    uint32_t aA, uint32_t aW, uint32_t rstr, uint32_t aLo, uint32_t wLo,
    int lane, int mbase, int nbase, float* acc)
{
    const uint32_t aRow = aA + (uint32_t)(mbase + (lane & 15)) * rstr + ((lane >> 4) << 4);
    const uint32_t bRow = aW + (uint32_t)(nbase + (lane & 7) + ((lane >> 4) << 3)) * rstr
                        + (((lane >> 3) & 1) << 4);
    #pragma unroll
    for (int kc = 0; kc < KCH; kc++) {
        uint32_t ah[8], al[8];
        ldsm4(aRow + kc * 32, ah);
        ldsm4(aRow + 16 * rstr + kc * 32, ah + 4);
        ldsm4(aRow + aLo + kc * 32, al);
        ldsm4(aRow + aLo + 16 * rstr + kc * 32, al + 4);
        #pragma unroll
        for (int np = 0; np < NPAIR; np++) {
            uint32_t bh[4], bl[4];
            ldsm4(bRow + np * 16 * rstr + kc * 32, bh);
            ldsm4(bRow + wLo + np * 16 * rstr + kc * 32, bl);
            #pragma unroll
            for (int m = 0; m < 2; m++) {
                #pragma unroll
                for (int h = 0; h < 2; h++) {
                    float* d = acc + ((m * NPAIR + np) * 2 + h) * 4;
                    mma16816(d, ah + m * 4, bh + h * 2);
                    mma16816(d, ah + m * 4, bl + h * 2);
                    mma16816(d, al + m * 4, bh + h * 2);
                }
            }
        }
    }
}

__device__ __forceinline__ void layer1_tail(
    uint32_t aA, uint32_t aW, int lane, int mbase, int nbase, float* acc)
{
    const uint32_t aAddr = aA + (uint32_t)(mbase + lane) * ER + 256;
    const uint32_t bAddr = aW + (uint32_t)(nbase + lane) * ER + 256;
    uint32_t ah[4], al[4], bh[4], bl[4];
    ldsm4(aAddr, ah);
    ldsm4(aAddr + EA_LO, al);
    ldsm4(bAddr, bh);
    ldsm4(bAddr + EW_LO128, bl);
    #pragma unroll
    for (int m = 0; m < 2; m++)
        #pragma unroll
        for (int n4 = 0; n4 < 4; n4++) {
            float* d = acc + ((m * 2 + (n4 >> 1)) * 2 + (n4 & 1)) * 4;
            mma16808(d, ah + 2 * m, bh[n4]);
            mma16808(d, ah + 2 * m, bl[n4]);
            mma16808(d, al + 2 * m, bh[n4]);
        }
}

__device__ __forceinline__ void epi12(unsigned char* Ab, const float* bias,
                                      int lane, int mbase, int nbase, const float* acc)
{
    #pragma unroll
    for (int m = 0; m < 2; m++)
        #pragma unroll
        for (int np = 0; np < 2; np++)
            #pragma unroll
            for (int h = 0; h < 2; h++) {
                const float* d = acc + ((m * 2 + np) * 2 + h) * 4;
                int c = nbase + np * 16 + h * 8 + 2 * (lane & 3);
                int r = mbase + m * 16 + (lane >> 2);
                float b0 = bias[c], b1 = bias[c + 1];
                float v0 = fmaxf(d[0] + b0, 0.f), v1 = fmaxf(d[1] + b1, 0.f);
                float v2 = fmaxf(d[2] + b0, 0.f), v3 = fmaxf(d[3] + b1, 0.f);
                __nv_bfloat162 hA = __floats2bfloat162_rn(v0, v1);
                __nv_bfloat162 lA = __floats2bfloat162_rn(v0 - __low2float(hA),
                                                          v1 - __high2float(hA));
                __nv_bfloat162 hB = __floats2bfloat162_rn(v2, v3);
                __nv_bfloat162 lB = __floats2bfloat162_rn(v2 - __low2float(hB),
                                                          v3 - __high2float(hB));
                uint32_t o0 = (uint32_t)r * ER + (uint32_t)c * 2;
                uint32_t o1 = o0 + 8u * ER;
                *(uint32_t*)(Ab + o0)         = *(uint32_t*)&hA;
                *(uint32_t*)(Ab + EA_LO + o0) = *(uint32_t*)&lA;
                *(uint32_t*)(Ab + o1)         = *(uint32_t*)&hB;
                *(uint32_t*)(Ab + EA_LO + o1) = *(uint32_t*)&lB;
            }
}

// ---------------- persistent edge MLP: R9 pipeline, grid-strided tiles ------
// smem: A hi+lo [34816] | W buf [69632] | idx[256] | bias[1280] | mbar[16]
#define SM_W    34816
#define SM_IDX  104448
#define SM_BIAS 104960
#define SM_MBW  106240
#define EDGE_SMEM_BYTES 106272
template<int DIR>
__global__ __launch_bounds__(256, 2) void edge_mma_kernel(
    const __nv_bfloat16* __restrict__ Ahi, const __nv_bfloat16* __restrict__ Alo,
    const __nv_bfloat16* __restrict__ Bhi, const __nv_bfloat16* __restrict__ Blo,
    const int* __restrict__ idxArr,
    const __nv_bfloat16* __restrict__ fhi, const __nv_bfloat16* __restrict__ flo,
    const unsigned char* __restrict__ wsrc,
    const float* __restrict__ b1, const float* __restrict__ b2,
    const float* __restrict__ b3,
    float* __restrict__ nm)
{
    extern __shared__ __align__(256) unsigned char sm[];
    const uint32_t smb = smem_u32(sm);
    const int tid = threadIdx.x;

    int*   idx    = (int*)(sm + SM_IDX);
    float* bias_s = (float*)(sm + SM_BIAS);
    const uint32_t mbw = smb + SM_MBW;

    if (tid == 0) MBARRIER_INIT(mbw, 1u);
    for (int i = tid; i < 320; i += 256)
        bias_s[i] = (i < 128) ? b1[i] : (i < 256 ? b2[i - 128] : b3[i - 256]);

    const int w = tid >> 5, lane = tid & 31;
    const int mbase = (w & 1) * 32;
    const int nb32  = (w >> 1) * 32;
    const int nb16  = (w >> 1) * 16;
    float acc[32];
    uint32_t ph = 0;   // mbarrier parity: 3 completions per tile -> net flip

    for (int t = blockIdx.x; t < NTILES; t += EGRID) {
        const int e0 = t * 64;
        const int p0 = e0 >> 1;

        __syncthreads();   // prev tile fully consumed (smA, idx); also covers init
        if (tid == 0) {
            MBARRIER_EXPECT_TX(mbw, 69632u);
            bulk_copy_g2s(smb + SM_W, wsrc, 69632u, mbw);
        }
        if (tid < 64) idx[tid] = idxArr[e0 + tid];
        __syncthreads();   // idx visible to gather

        // ---- gather (pure bf16 copies) ----
        {
            int r = tid >> 3, q = tid & 7;
            const __nv_bfloat16* srcH = (DIR == 0) ? Ahi : Bhi;
            const __nv_bfloat16* srcL = (DIR == 0) ? Alo : Blo;
            uint4 hv = *(const uint4*)(srcH + (size_t)(p0 + r) * 64 + q * 8);
            uint4 lv = *(const uint4*)(srcL + (size_t)(p0 + r) * 64 + q * 8);
            uint32_t cb = (DIR == 0) ? 0u : 128u;
            uint32_t o0 = (uint32_t)(2 * r)     * ER + cb + q * 16;
            uint32_t o1 = (uint32_t)(2 * r + 1) * ER + cb + q * 16;
            *(uint4*)(sm + o0)         = hv;  *(uint4*)(sm + o1)         = hv;
            *(uint4*)(sm + EA_LO + o0) = lv;  *(uint4*)(sm + EA_LO + o1) = lv;
        }
        for (int i = tid; i < 512; i += 256) {
            int e = i >> 3, q = i & 7;
            int s = idx[e];
            const __nv_bfloat16* srcH = (DIR == 0) ? Bhi : Ahi;
            const __nv_bfloat16* srcL = (DIR == 0) ? Blo : Alo;
            uint4 hv = *(const uint4*)(srcH + (size_t)s * 64 + q * 8);
            uint4 lv = *(const uint4*)(srcL + (size_t)s * 64 + q * 8);
            uint32_t cb = (DIR == 0) ? 128u : 0u;
            uint32_t o = (uint32_t)e * ER + cb + q * 16;
            *(uint4*)(sm + o)         = hv;
            *(uint4*)(sm + EA_LO + o) = lv;
        }
        if (tid < 64) {
            int e = tid;
            int rowIdx = (DIR == 0) ? (p0 + (e >> 1)) : idx[e];
            int colIdx = (DIR == 0) ? idx[e] : (p0 + (e >> 1));
            uint2 rh = *(const uint2*)(fhi + (size_t)rowIdx * 4);
            uint2 ch = *(const uint2*)(fhi + (size_t)colIdx * 4);
            uint2 rl = *(const uint2*)(flo + (size_t)rowIdx * 4);
            uint2 cl = *(const uint2*)(flo + (size_t)colIdx * 4);
            uint32_t o = (uint32_t)e * ER + 256;
            *(uint4*)(sm + o)         = make_uint4(rh.x, rh.y, ch.x, ch.y);
            *(uint4*)(sm + EA_LO + o) = make_uint4(rl.x, rl.y, cl.x, cl.y);
        }
        __syncthreads();

        // ---- layer 1: K=136, N=128 ----
        MBARRIER_WAIT_PARITY(mbw, ph);
        #pragma unroll
        for (int i = 0; i < 32; i++) acc[i] = 0.f;
        layer_mma_s<8, 2>(smb, smb + SM_W, ER, EA_LO, EW_LO128, lane, mbase, nb32, acc);
        layer1_tail(smb, smb + SM_W, lane, mbase, nb32, acc);
        __syncthreads();
        if (tid == 0) {
            MBARRIER_EXPECT_TX(mbw, 69632u);
            bulk_copy_g2s(smb + SM_W, wsrc + 69632, 69632u, mbw);
        }
        epi12(sm, bias_s, lane, mbase, nb32, acc);
        __syncthreads();

        // ---- layer 2: K=128, N=128 ----
        MBARRIER_WAIT_PARITY(mbw, ph ^ 1);
        #pragma unroll
        for (int i = 0; i < 32; i++) acc[i] = 0.f;
        layer_mma_s<8, 2>(smb, smb + SM_W, ER, EA_LO, EW_LO128, lane, mbase, nb32, acc);
        __syncthreads();
        if (tid == 0) {
            MBARRIER_EXPECT_TX(mbw, 34816u);
            bulk_copy_g2s(smb + SM_W, wsrc + 139264, 34816u, mbw);
        }
        epi12(sm, bias_s + 128, lane, mbase, nb32, acc);
        __syncthreads();

        // ---- layer 3: K=128, N=64 ----
        MBARRIER_WAIT_PARITY(mbw, ph);
        #pragma unroll
        for (int i = 0; i < 16; i++) acc[i] = 0.f;
        layer_mma_s<8, 1>(smb, smb + SM_W, ER, EA_LO, EW_LO64, lane, mbase, nb16, acc);

        if (DIR == 0) {
            #pragma unroll
            for (int m = 0; m < 2; m++)
                #pragma unroll
                for (int h = 0; h < 2; h++) {
                    const float* d = acc + (m * 2 + h) * 4;
                    int c = nb16 + h * 8 + 2 * (lane & 3);
                    int r = mbase + m * 16 + (lane >> 2);
                    float b0 = bias_s[256 + c], b1v = bias_s[256 + c + 1];
                    float* q0 = nm + (size_t)idx[r] * 64 + c;
                    float* q1 = nm + (size_t)idx[r + 8] * 64 + c;
                    atomicAdd(q0,     d[0] + b0);
                    atomicAdd(q0 + 1, d[1] + b1v);
                    atomicAdd(q1,     d[2] + b0);
                    atomicAdd(q1 + 1, d[3] + b1v);
                }
        } else {
            __syncthreads();                   // done reading A region
            float* st = (float*)sm;
            #pragma unroll
            for (int m = 0; m < 2; m++)
                #pragma unroll
                for (int h = 0; h < 2; h++) {
                    const float* d = acc + (m * 2 + h) * 4;
                    int c = nb16 + h * 8 + 2 * (lane & 3);
                    int r = mbase + m * 16 + (lane >> 2);
                    float b0 = bias_s[256 + c], b1v = bias_s[256 + c + 1];
                    st[r * 68 + c]           = d[0] + b0;
                    st[r * 68 + c + 1]       = d[1] + b1v;
                    st[(r + 8) * 68 + c]     = d[2] + b0;
                    st[(r + 8) * 68 + c + 1] = d[3] + b1v;
                }
            __syncthreads();
            for (int i = tid; i < 2048; i += 256) {
                int r = i >> 6, c = i & 63;
                nm[(size_t)(p0 + r) * 64 + c] = st[(2 * r) * 68 + c] + st[(2 * r + 1) * 68 + c];
            }
        }
        ph ^= 1;
    }
}

// ---------------- HMMA GRU (unchanged) ----------------
#define GSM_W    69632
#define GSM_BIAS 208896
#define GSM_MBW  209920
#define GRU_SMEM_BYTES 209952
__global__ __launch_bounds__(512, 1) void gru_mma_kernel(
    float* __restrict__ h,
    __nv_bfloat16* __restrict__ h_hi, __nv_bfloat16* __restrict__ h_lo,
    float* __restrict__ x,
    const unsigned char* __restrict__ wsrc,
    const float* __restrict__ bih, const float* __restrict__ bhh,
    int nrows)
{
    extern __shared__ __align__(256) unsigned char sm[];
    const uint32_t smb = smem_u32(sm);
    const int tid = threadIdx.x;
    const int r0 = blockIdx.x * 128;

    float* bias_s = (float*)(sm + GSM_BIAS);
    float* gs     = (float*)(sm + GSM_W);
    const uint32_t mbw = smb + GSM_MBW;

    if (tid == 0) MBARRIER_INIT(mbw, 1u);
    __syncthreads();
    if (tid == 0) {
        MBARRIER_EXPECT_TX(mbw, 139264u);
        bulk_copy_g2s(smb + GSM_W, wsrc, 139264u, mbw);
    }
    for (int i = tid; i < 256; i += 512) {
        float v;
        if (i < 128)      v = bih[i] + bhh[i];
        else if (i < 192) v = bih[i];
        else              v = bhh[i - 64];
        bias_s[i] = v;
    }

    for (int i = tid; i < 128 * 32; i += 512) {
        int e = i >> 5, q = i & 31;
        int rr = r0 + e;
        int rc = rr < nrows ? rr : nrows - 1;
        float4 xv;
        if (q < 16) {
            xv = *(const float4*)(x + (size_t)rc * 64 + q * 4);
            if (rr < nrows) *(float4*)(x + (size_t)rc * 64 + q * 4) = make_float4(0.f, 0.f, 0.f, 0.f);
        } else {
            xv = *(const float4*)(h + (size_t)rc * 64 + (q - 16) * 4);
        }
        __nv_bfloat162 h01 = __floats2bfloat162_rn(xv.x, xv.y);
        __nv_bfloat162 h23 = __floats2bfloat162_rn(xv.z, xv.w);
        __nv_bfloat162 l01 = __floats2bfloat162_rn(xv.x - __low2float(h01), xv.y - __high2float(h01));
        __nv_bfloat162 l23 = __floats2bfloat162_rn(xv.z - __low2float(h23), xv.w - __high2float(h23));
        uint32_t off = (uint32_t)e * GR + (uint32_t)q * 8;
        *(uint2*)(sm + off)         = make_uint2(*(uint32_t*)&h01, *(uint32_t*)&h23);
        *(uint2*)(sm + GA_LO + off) = make_uint2(*(uint32_t*)&l01, *(uint32_t*)&l23);
    }
    __syncthreads();

    const int w = tid >> 5, lane = tid & 31;
    const int mbase = (w & 3) * 32;
    const int nbase = (w >> 2) * 64;
    float acc[64];
    #pragma unroll
    for (int i = 0; i < 64; i++) acc[i] = 0.f;

    MBARRIER_WAIT_PARITY(mbw, 0);
    layer_mma_s<8, 4>(smb, smb + GSM_W, GR, GA_LO, GW_LO, lane, mbase, nbase, acc);
    __syncthreads();

    #pragma unroll
    for (int m = 0; m < 2; m++)
        #pragma unroll
        for (int np = 0; np < 4; np++)
            #pragma unroll
            for (int hh = 0; hh < 2; hh++) {
                const float* d = acc + ((m * 4 + np) * 2 + hh) * 4;
                int c = nbase + np * 16 + hh * 8 + 2 * (lane & 3);
                int r = mbase + m * 16 + (lane >> 2);
                gs[r * 256 + c]           = d[0];
                gs[r * 256 + c + 1]       = d[1];
                gs[(r + 8) * 256 + c]     = d[2];
                gs[(r + 8) * 256 + c + 1] = d[3];
            }
    __syncthreads();

    for (int i = tid; i < 128 * 64; i += 512) {
        int e = i >> 6, d = i & 63;
        int r = r0 + e;
        if (r >= nrows) continue;
        const float* g = gs + e * 256;
        float pr = g[d]       + bias_s[d];
        float pz = g[64 + d]  + bias_s[64 + d];
        float in = g[128 + d] + bias_s[128 + d];
        float hn = g[192 + d] + bias_s[192 + d];
        float rr = 1.f / (1.f + expf(-pr));
        float zz = 1.f / (1.f + expf(-pz));
        float nn = tanhf(in + rr * hn);
        float hv = h[(size_t)r * 64 + d];
        float hnew = (1.f - zz) * nn + zz * hv;
        h[(size_t)r * 64 + d] = hnew;
        __nv_bfloat16 hb = __float2bfloat16(hnew);
        h_hi[(size_t)r * 64 + d] = hb;
        h_lo[(size_t)r * 64 + d] = __float2bfloat16(hnew - __bfloat162float(hb));
    }
}

// ---------------- readout (unchanged) ----------------
__global__ __launch_bounds__(256) void readout_kernel(
    const float* __restrict__ h,
    const float* __restrict__ W1, const float* __restrict__ b1,
    const float* __restrict__ W2, const float* __restrict__ b2,
    const float* __restrict__ W3, const float* __restrict__ b3,
    float* __restrict__ out, int nrows)
{
    __shared__ float hs[32 * 68];
    __shared__ float l1s[32 * 132];
    __shared__ float l2s[32 * 132];
    __shared__ float lg[64];

    const int tid = threadIdx.x;
    const int r0  = blockIdx.x * 32;

    for (int i = tid; i < 32 * 64; i += 256) {
        int e = i >> 6, k = i & 63;
        int r = r0 + e;
        hs[e * 68 + k] = (r < nrows) ? h[(size_t)r * 64 + k] : 0.f;
    }
    __syncthreads();

    const int warp = tid >> 5, lane = tid & 31;
    #pragma unroll
    for (int jc = 0; jc < 4; jc++) {
        const int j0 = warp * 16 + jc * 4;
        float a[4] = {0.f, 0.f, 0.f, 0.f};
        #pragma unroll
        for (int k = 0; k < 64; k += 4) {
            float4 xv = *(const float4*)(hs + lane * 68 + k);
            #pragma unroll
            for (int jj = 0; jj < 4; jj++) {
                float4 wv = *(const float4*)(W1 + (size_t)(j0 + jj) * 64 + k);
                a[jj] += wv.x * xv.x + wv.y * xv.y + wv.z * xv.z + wv.w * xv.w;
            }
        }
        #pragma unroll
        for (int jj = 0; jj < 4; jj++)
            l1s[lane * 132 + j0 + jj] = fmaxf(a[jj] + b1[j0 + jj], 0.f);
    }
    __syncthreads();
    #pragma unroll
    for (int jc = 0; jc < 4; jc++) {
        const int j0 = warp * 16 + jc * 4;
        float a[4] = {0.f, 0.f, 0.f, 0.f};
        #pragma unroll 2
        for (int k = 0; k < 128; k += 4) {
            float4 xv = *(const float4*)(l1s + lane * 132 + k);
            #pragma unroll
            for (int jj = 0; jj < 4; jj++) {
                float4 wv = *(const float4*)(W2 + (size_t)(j0 + jj) * 128 + k);
                a[jj] += wv.x * xv.x + wv.y * xv.y + wv.z * xv.z + wv.w * xv.w;
            }
        }
        #pragma unroll
        for (int jj = 0; jj < 4; jj++)
            l2s[lane * 132 + j0 + jj] = fmaxf(a[jj] + b2[j0 + jj], 0.f);
    }
    __syncthreads();
    if (tid < 64) {
        int e = tid >> 1, j = tid & 1;
        float a = 0.f;
        #pragma unroll 4
        for (int k = 0; k < 128; k += 4) {
            float4 xv = *(const float4*)(l2s + e * 132 + k);
            float4 wv = *(const float4*)(W3 + (size_t)j * 128 + k);
            a += wv.x * xv.x + wv.y * xv.y + wv.z * xv.z + wv.w * xv.w;
        }
        lg[e * 2 + j] = a + b3[j];
    }
    __syncthreads();
    if (tid < 64) {
        int e = tid >> 1, j = tid & 1;
        int r = r0 + e;
        if (r < nrows) {
            float self  = lg[e * 2 + j];
            float other = lg[e * 2 + (j ^ 1)];
            out[(size_t)r * 2 + j] = 1.f / (1.f + expf(other - self));
        }
    }
}

extern "C" void kernel_launch(void* const* d_in, const int* in_sizes, int n_in,
                              void* d_out, int out_size)
{
    const int*   f2v_col  = (const int*)d_in[1];
    const int*   v2f_row  = (const int*)d_in[2];
    const float* f2v_feat = (const float*)d_in[4];
    const float* v2f_feat = (const float*)d_in[5];
    const float* f2v_w1 = (const float*)d_in[6];   const float* f2v_b1 = (const float*)d_in[7];
    const float* f2v_w2 = (const float*)d_in[8];   const float* f2v_b2 = (const float*)d_in[9];
    const float* f2v_w3 = (const float*)d_in[10];  const float* f2v_b3 = (const float*)d_in[11];
    const float* v2f_w1 = (const float*)d_in[12];  const float* v2f_b1 = (const float*)d_in[13];
    const float* v2f_w2 = (const float*)d_in[14];  const float* v2f_b2 = (const float*)d_in[15];
    const float* v2f_w3 = (const float*)d_in[16];  const float* v2f_b3 = (const float*)d_in[17];
    const float* gf_wih = (const float*)d_in[18];  const float* gf_whh = (const float*)d_in[19];
    const float* gf_bih = (const float*)d_in[20];  const float* gf_bhh = (const float*)d_in[21];
    const float* gv_wih = (const float*)d_in[22];  const float* gv_whh = (const float*)d_in[23];
    const float* gv_bih = (const float*)d_in[24];  const float* gv_bhh = (const float*)d_in[25];
    const float* ro_w1  = (const float*)d_in[26];  const float* ro_b1  = (const float*)d_in[27];
    const float* ro_w2  = (const float*)d_in[28];  const float* ro_b2  = (const float*)d_in[29];
    const float* ro_w3  = (const float*)d_in[30];  const float* ro_b3  = (const float*)d_in[31];
    float* out = (float*)d_out;

    float *var_h, *fac_h, *nm_var, *nm_fac;
    __nv_bfloat16 *var_hhi, *var_hlo, *fac_hhi, *fac_hlo;
    __nv_bfloat16 *f2v_fhi, *f2v_flo, *v2f_fhi, *v2f_flo;
    unsigned char *wp_f2v, *wp_v2f, *wg_gf, *wg_gv;
    cudaGetSymbolAddress((void**)&var_h,   g_var_h);
    cudaGetSymbolAddress((void**)&fac_h,   g_fac_h);
    cudaGetSymbolAddress((void**)&nm_var,  g_nm_var);
    cudaGetSymbolAddress((void**)&nm_fac,  g_nm_fac);
    cudaGetSymbolAddress((void**)&var_hhi, g_var_hhi);
    cudaGetSymbolAddress((void**)&var_hlo, g_var_hlo);
    cudaGetSymbolAddress((void**)&fac_hhi, g_fac_hhi);
    cudaGetSymbolAddress((void**)&fac_hlo, g_fac_hlo);
    cudaGetSymbolAddress((void**)&f2v_fhi, g_f2v_fhi);
    cudaGetSymbolAddress((void**)&f2v_flo, g_f2v_flo);
    cudaGetSymbolAddress((void**)&v2f_fhi, g_v2f_fhi);
    cudaGetSymbolAddress((void**)&v2f_flo, g_v2f_flo);
    cudaGetSymbolAddress((void**)&wp_f2v,  g_wpack_f2v);
    cudaGetSymbolAddress((void**)&wp_v2f,  g_wpack_v2f);
    cudaGetSymbolAddress((void**)&wg_gf,   g_wgru_gf);
    cudaGetSymbolAddress((void**)&wg_gv,   g_wgru_gv);

    cudaFuncSetAttribute(edge_mma_kernel<0>, cudaFuncAttributeMaxDynamicSharedMemorySize, EDGE_SMEM_BYTES);
    cudaFuncSetAttribute(edge_mma_kernel<1>, cudaFuncAttributeMaxDynamicSharedMemorySize, EDGE_SMEM_BYTES);
    cudaFuncSetAttribute(gru_mma_kernel,     cudaFuncAttributeMaxDynamicSharedMemorySize, GRU_SMEM_BYTES);

    pack_weights_kernel<<<32, 256>>>(wp_f2v,           f2v_w1, 128, 136);
    pack_weights_kernel<<<32, 256>>>(wp_f2v + 69632,   f2v_w2, 128, 128);
    pack_weights_kernel<<<32, 256>>>(wp_f2v + 139264,  f2v_w3,  64, 128);
    pack_weights_kernel<<<32, 256>>>(wp_v2f,           v2f_w1, 128, 136);
    pack_weights_kernel<<<32, 256>>>(wp_v2f + 69632,   v2f_w2, 128, 128);
    pack_weights_kernel<<<32, 256>>>(wp_v2f + 139264,  v2f_w3,  64, 128);
    pack_gru_kernel<<<32, 256>>>(wg_gf, gf_wih, gf_whh);
    pack_gru_kernel<<<32, 256>>>(wg_gv, gv_wih, gv_whh);
    pack_split_kernel<<<64, 256>>>(f2v_fhi, f2v_flo, f2v_feat, NE * 4);
    pack_split_kernel<<<64, 256>>>(v2f_fhi, v2f_flo, v2f_feat, NE * 4);

    zero_kernel<<<256, 256>>>(var_h, NV * 64);
    zero_kernel<<<512, 256>>>(fac_h, NF * 64);
    zero_kernel<<<256, 256>>>(nm_var, NV * 64);
    zero_kernel<<<256, 256>>>((float*)var_hhi, NV * 32);
    zero_kernel<<<256, 256>>>((float*)var_hlo, NV * 32);
    zero_kernel<<<512, 256>>>((float*)fac_hhi, NF * 32);
    zero_kernel<<<512, 256>>>((float*)fac_hlo, NF * 32);

    for (int s = 0; s < 5; s++) {
        edge_mma_kernel<0><<<EGRID, 256, EDGE_SMEM_BYTES>>>(
            fac_hhi, fac_hlo, var_hhi, var_hlo, f2v_col, f2v_fhi, f2v_flo,
            wp_f2v, f2v_b1, f2v_b2, f2v_b3, nm_var);
        gru_mma_kernel<<<(NV + 127) / 128, 512, GRU_SMEM_BYTES>>>(
            var_h, var_hhi, var_hlo, nm_var, wg_gf, gf_bih, gf_bhh, NV);

        edge_mma_kernel<1><<<EGRID, 256, EDGE_SMEM_BYTES>>>(
            var_hhi, var_hlo, fac_hhi, fac_hlo, v2f_row, v2f_fhi, v2f_flo,
            wp_v2f, v2f_b1, v2f_b2, v2f_b3, nm_fac);
        gru_mma_kernel<<<NF / 128, 512, GRU_SMEM_BYTES>>>(
            fac_h, fac_hhi, fac_hlo, nm_fac, wg_gv, gv_bih, gv_bhh, NF);
    }

    readout_kernel<<<(NV + 31) / 32, 256>>>(
        var_h, ro_w1, ro_b1, ro_w2, ro_b2, ro_w3, ro_b3, out, NV);
}

// round 12
// speedup vs baseline: 1.1178x; 1.0582x over previous
#include <cuda_runtime.h>
#include <cuda_bf16.h>
#include <cstdint>
#include <math.h>

#define NV 10000
#define NF 80000
#define NE 160000

#define ER 272
#define EA_LO 17408
#define EW_LO128 34816
#define EW_LO64  17408

#define GR 272
#define GA_LO 34816
#define GW_LO 69632

__device__ float g_var_h[NV * 64];
__device__ float g_fac_h[NF * 64];
__device__ float g_nm_var[NV * 64];
__device__ float g_nm_fac[NF * 64];
__device__ __nv_bfloat16 g_var_hhi[NV * 64];
__device__ __nv_bfloat16 g_var_hlo[NV * 64];
__device__ __nv_bfloat16 g_fac_hhi[NF * 64];
__device__ __nv_bfloat16 g_fac_hlo[NF * 64];
__device__ __nv_bfloat16 g_f2v_fhi[NE * 4];
__device__ __nv_bfloat16 g_f2v_flo[NE * 4];
__device__ __nv_bfloat16 g_v2f_fhi[NE * 4];
__device__ __nv_bfloat16 g_v2f_flo[NE * 4];
__device__ __align__(256) unsigned char g_wpack_f2v[174080];
__device__ __align__(256) unsigned char g_wpack_v2f[174080];
__device__ __align__(256) unsigned char g_wgru_gf[139264];
__device__ __align__(256) unsigned char g_wgru_gv[139264];

__device__ __forceinline__ uint32_t smem_u32(const void* p) {
    uint32_t a;
    asm("{ .reg .u64 t; cvta.to.shared.u64 t, %1; cvt.u32.u64 %0, t; }" : "=r"(a) : "l"(p));
    return a;
}
#define MBARRIER_INIT(mbar, cnt) \
    asm volatile("mbarrier.init.shared.b64 [%0], %1;" :: "r"(mbar), "r"(cnt) : "memory")
#define MBARRIER_EXPECT_TX(mbar, bytes) \
    asm volatile("mbarrier.arrive.expect_tx.shared.b64 _, [%0], %1;" :: "r"(mbar), "r"(bytes) : "memory")
#define MBARRIER_WAIT_PARITY(mbar, ph) do { \
    asm volatile("{\n\t.reg .pred P1;\n\t" \
        "W_%=:\n\tmbarrier.try_wait.parity.acquire.cta.shared::cta.b64 P1, [%0], %1, 0x989680;\n\t" \
        "@P1 bra.uni D_%=;\n\tbra.uni W_%=;\n\tD_%=:\n\t}" \
        :: "r"(mbar), "r"(ph) : "memory"); \
} while (0)

__device__ __forceinline__ void bulk_copy_g2s(uint32_t dst, const void* src,
                                              uint32_t bytes, uint32_t mbar) {
    asm volatile(
        "cp.async.bulk.shared::cluster.global.mbarrier::complete_tx::bytes [%0], [%1], %2, [%3];"
        :: "r"(dst), "l"(src), "r"(bytes), "r"(mbar) : "memory");
}
__device__ __forceinline__ void ldsm4(uint32_t addr, uint32_t* r) {
    asm volatile("ldmatrix.sync.aligned.m8n8.x4.shared.b16 {%0,%1,%2,%3}, [%4];"
        : "=r"(r[0]), "=r"(r[1]), "=r"(r[2]), "=r"(r[3]) : "r"(addr));
}
__device__ __forceinline__ void mma16816(float* d, const uint32_t* a, const uint32_t* b) {
    asm volatile("mma.sync.aligned.m16n8k16.row.col.f32.bf16.bf16.f32 "
        "{%0,%1,%2,%3}, {%4,%5,%6,%7}, {%8,%9}, {%0,%1,%2,%3};"
        : "+f"(d[0]), "+f"(d[1]), "+f"(d[2]), "+f"(d[3])
        : "r"(a[0]), "r"(a[1]), "r"(a[2]), "r"(a[3]), "r"(b[0]), "r"(b[1]));
}
__device__ __forceinline__ void mma16808(float* d, const uint32_t* a, uint32_t b) {
    asm volatile("mma.sync.aligned.m16n8k8.row.col.f32.bf16.bf16.f32 "
        "{%0,%1,%2,%3}, {%4,%5}, {%6}, {%0,%1,%2,%3};"
        : "+f"(d[0]), "+f"(d[1]), "+f"(d[2]), "+f"(d[3])
        : "r"(a[0]), "r"(a[1]), "r"(b));
}

// ---------------- fused setup: all packing + zeroing in ONE kernel ----------
__device__ void dev_pack_w(unsigned char* dst, const float* W, int nrows, int kin,
                           int gt, int gs) {
    const int total = nrows * 136;
    const int plane = nrows * ER;
    for (int i = gt; i < total; i += gs) {
        int n = i / 136, k = i - n * 136;
        float v = (k < kin) ? W[n * kin + k] : 0.0f;
        __nv_bfloat16 hi = __float2bfloat16(v);
        __nv_bfloat16 lo = __float2bfloat16(v - __bfloat162float(hi));
        uint32_t off = (uint32_t)n * ER + (uint32_t)k * 2;
        *(__nv_bfloat16*)(dst + off) = hi;
        *(__nv_bfloat16*)(dst + plane + off) = lo;
    }
}
__device__ void dev_pack_gru(unsigned char* dst, const float* wih, const float* whh,
                             int gt, int gs) {
    const int total = 256 * 136;
    for (int i = gt; i < total; i += gs) {
        int r = i / 136, k = i - r * 136;
        float v = 0.0f;
        if (k < 128) {
            if (r < 128)       v = (k < 64) ? wih[r * 64 + k] : whh[r * 64 + (k - 64)];
            else if (r < 192)  { if (k < 64)  v = wih[r * 64 + k]; }
            else               { if (k >= 64) v = whh[(r - 64) * 64 + (k - 64)]; }
        }
        __nv_bfloat16 hi = __float2bfloat16(v);
        __nv_bfloat16 lo = __float2bfloat16(v - __bfloat162float(hi));
        uint32_t off = (uint32_t)r * GR + (uint32_t)k * 2;
        *(__nv_bfloat16*)(dst + off) = hi;
        *(__nv_bfloat16*)(dst + GW_LO + off) = lo;
    }
}
__device__ void dev_split(__nv_bfloat16* hi_out, __nv_bfloat16* lo_out,
                          const float* src, int n, int gt, int gs) {
    for (int i = gt; i < n; i += gs) {
        float v = src[i];
        __nv_bfloat16 hi = __float2bfloat16(v);
        hi_out[i] = hi;
        lo_out[i] = __float2bfloat16(v - __bfloat162float(hi));
    }
}
__device__ void dev_zero_f(float* p, int n, int gt, int gs) {
    for (int i = gt; i < n; i += gs) p[i] = 0.0f;
}

__global__ __launch_bounds__(256) void setup_kernel(
    const float* __restrict__ f2v_w1, const float* __restrict__ f2v_w2,
    const float* __restrict__ f2v_w3,
    const float* __restrict__ v2f_w1, const float* __restrict__ v2f_w2,
    const float* __restrict__ v2f_w3,
    const float* __restrict__ gf_wih, const float* __restrict__ gf_whh,
    const float* __restrict__ gv_wih, const float* __restrict__ gv_whh,
    const float* __restrict__ f2v_feat, const float* __restrict__ v2f_feat)
{
    const int gt = blockIdx.x * blockDim.x + threadIdx.x;
    const int gs = gridDim.x * blockDim.x;

    dev_pack_w(g_wpack_f2v,          f2v_w1, 128, 136, gt, gs);
    dev_pack_w(g_wpack_f2v + 69632,  f2v_w2, 128, 128, gt, gs);
    dev_pack_w(g_wpack_f2v + 139264, f2v_w3,  64, 128, gt, gs);
    dev_pack_w(g_wpack_v2f,          v2f_w1, 128, 136, gt, gs);
    dev_pack_w(g_wpack_v2f + 69632,  v2f_w2, 128, 128, gt, gs);
    dev_pack_w(g_wpack_v2f + 139264, v2f_w3,  64, 128, gt, gs);
    dev_pack_gru(g_wgru_gf, gf_wih, gf_whh, gt, gs);
    dev_pack_gru(g_wgru_gv, gv_wih, gv_whh, gt, gs);
    dev_split(g_f2v_fhi, g_f2v_flo, f2v_feat, NE * 4, gt, gs);
    dev_split(g_v2f_fhi, g_v2f_flo, v2f_feat, NE * 4, gt, gs);
    dev_zero_f(g_var_h,  NV * 64, gt, gs);
    dev_zero_f(g_fac_h,  NF * 64, gt, gs);
    dev_zero_f(g_nm_var, NV * 64, gt, gs);
    dev_zero_f((float*)g_var_hhi, NV * 32, gt, gs);
    dev_zero_f((float*)g_var_hlo, NV * 32, gt, gs);
    dev_zero_f((float*)g_fac_hhi, NF * 32, gt, gs);
    dev_zero_f((float*)g_fac_hlo, NF * 32, gt, gs);
}

// ---------------- generic HMMA tile ----------------
template<int KCH, int NPAIR>
__device__ __forceinline__ void layer_mma_s(
    uint32_t aA, uint32_t aW, uint32_t rstr, uint32_t aLo, uint32_t wLo,
    int lane, int mbase, int nbase, float* acc)
{
    const uint32_t aRow = aA + (uint32_t)(mbase + (lane & 15)) * rstr + ((lane >> 4) << 4);
    const uint32_t bRow = aW + (uint32_t)(nbase + (lane & 7) + ((lane >> 4) << 3)) * rstr
                        + (((lane >> 3) & 1) << 4);
    #pragma unroll
    for (int kc = 0; kc < KCH; kc++) {
        uint32_t ah[8], al[8];
        ldsm4(aRow + kc * 32, ah);
        ldsm4(aRow + 16 * rstr + kc * 32, ah + 4);
        ldsm4(aRow + aLo + kc * 32, al);
        ldsm4(aRow + aLo + 16 * rstr + kc * 32, al + 4);
        #pragma unroll
        for (int np = 0; np < NPAIR; np++) {
            uint32_t bh[4], bl[4];
            ldsm4(bRow + np * 16 * rstr + kc * 32, bh);
            ldsm4(bRow + wLo + np * 16 * rstr + kc * 32, bl);
            #pragma unroll
            for (int m = 0; m < 2; m++) {
                #pragma unroll
                for (int h = 0; h < 2; h++) {
                    float* d = acc + ((m * NPAIR + np) * 2 + h) * 4;
                    mma16816(d, ah + m * 4, bh + h * 2);
                    mma16816(d, ah + m * 4, bl + h * 2);
                    mma16816(d, al + m * 4, bh + h * 2);
                }
            }
        }
    }
}

__device__ __forceinline__ void layer1_tail(
    uint32_t aA, uint32_t aW, int lane, int mbase, int nbase, float* acc)
{
    const uint32_t aAddr = aA + (uint32_t)(mbase + lane) * ER + 256;
    const uint32_t bAddr = aW + (uint32_t)(nbase + lane) * ER + 256;
    uint32_t ah[4], al[4], bh[4], bl[4];
    ldsm4(aAddr, ah);
    ldsm4(aAddr + EA_LO, al);
    ldsm4(bAddr, bh);
    ldsm4(bAddr + EW_LO128, bl);
    #pragma unroll
    for (int m = 0; m < 2; m++)
        #pragma unroll
        for (int n4 = 0; n4 < 4; n4++) {
            float* d = acc + ((m * 2 + (n4 >> 1)) * 2 + (n4 & 1)) * 4;
            mma16808(d, ah + 2 * m, bh[n4]);
            mma16808(d, ah + 2 * m, bl[n4]);
            mma16808(d, al + 2 * m, bh[n4]);
        }
}

__device__ __forceinline__ void epi12(unsigned char* Ab, const float* bias,
                                      int lane, int mbase, int nbase, const float* acc)
{
    #pragma unroll
    for (int m = 0; m < 2; m++)
        #pragma unroll
        for (int np = 0; np < 2; np++)
            #pragma unroll
            for (int h = 0; h < 2; h++) {
                const float* d = acc + ((m * 2 + np) * 2 + h) * 4;
                int c = nbase + np * 16 + h * 8 + 2 * (lane & 3);
                int r = mbase + m * 16 + (lane >> 2);
                float b0 = bias[c], b1 = bias[c + 1];
                float v0 = fmaxf(d[0] + b0, 0.f), v1 = fmaxf(d[1] + b1, 0.f);
                float v2 = fmaxf(d[2] + b0, 0.f), v3 = fmaxf(d[3] + b1, 0.f);
                __nv_bfloat162 hA = __floats2bfloat162_rn(v0, v1);
                __nv_bfloat162 lA = __floats2bfloat162_rn(v0 - __low2float(hA),
                                                          v1 - __high2float(hA));
                __nv_bfloat162 hB = __floats2bfloat162_rn(v2, v3);
                __nv_bfloat162 lB = __floats2bfloat162_rn(v2 - __low2float(hB),
                                                          v3 - __high2float(hB));
                uint32_t o0 = (uint32_t)r * ER + (uint32_t)c * 2;
                uint32_t o1 = o0 + 8u * ER;
                *(uint32_t*)(Ab + o0)         = *(uint32_t*)&hA;
                *(uint32_t*)(Ab + EA_LO + o0) = *(uint32_t*)&lA;
                *(uint32_t*)(Ab + o1)         = *(uint32_t*)&hB;
                *(uint32_t*)(Ab + EA_LO + o1) = *(uint32_t*)&lB;
            }
}

// ---------------- edge MLP (R9 exact): 64 edges/block, occ=2 ----------------
#define SM_W    34816
#define SM_IDX  104448
#define SM_BIAS 104960
#define SM_MBW  106240
#define EDGE_SMEM_BYTES 106272
template<int DIR>
__global__ __launch_bounds__(256, 2) void edge_mma_kernel(
    const __nv_bfloat16* __restrict__ Ahi, const __nv_bfloat16* __restrict__ Alo,
    const __nv_bfloat16* __restrict__ Bhi, const __nv_bfloat16* __restrict__ Blo,
    const int* __restrict__ idxArr,
    const __nv_bfloat16* __restrict__ fhi, const __nv_bfloat16* __restrict__ flo,
    const unsigned char* __restrict__ wsrc,
    const float* __restrict__ b1, const float* __restrict__ b2,
    const float* __restrict__ b3,
    float* __restrict__ nm)
{
    extern __shared__ __align__(256) unsigned char sm[];
    const uint32_t smb = smem_u32(sm);
    const int tid = threadIdx.x;
    const int e0 = blockIdx.x * 64;
    const int p0 = e0 >> 1;

    int*   idx    = (int*)(sm + SM_IDX);
    float* bias_s = (float*)(sm + SM_BIAS);
    const uint32_t mbw = smb + SM_MBW;

    if (tid == 0) MBARRIER_INIT(mbw, 1u);
    __syncthreads();
    if (tid == 0) {
        MBARRIER_EXPECT_TX(mbw, 69632u);
        bulk_copy_g2s(smb + SM_W, wsrc, 69632u, mbw);
    }
    if (tid < 64) idx[tid] = idxArr[e0 + tid];
    for (int i = tid; i < 320; i += 256)
        bias_s[i] = (i < 128) ? b1[i] : (i < 256 ? b2[i - 128] : b3[i - 256]);
    __syncthreads();

    {
        int r = tid >> 3, q = tid & 7;
        const __nv_bfloat16* srcH = (DIR == 0) ? Ahi : Bhi;
        const __nv_bfloat16* srcL = (DIR == 0) ? Alo : Blo;
        uint4 hv = *(const uint4*)(srcH + (size_t)(p0 + r) * 64 + q * 8);
        uint4 lv = *(const uint4*)(srcL + (size_t)(p0 + r) * 64 + q * 8);
        uint32_t cb = (DIR == 0) ? 0u : 128u;
        uint32_t o0 = (uint32_t)(2 * r)     * ER + cb + q * 16;
        uint32_t o1 = (uint32_t)(2 * r + 1) * ER + cb + q * 16;
        *(uint4*)(sm + o0)         = hv;  *(uint4*)(sm + o1)         = hv;
        *(uint4*)(sm + EA_LO + o0) = lv;  *(uint4*)(sm + EA_LO + o1) = lv;
    }
    for (int i = tid; i < 512; i += 256) {
        int e = i >> 3, q = i & 7;
        int s = idx[e];
        const __nv_bfloat16* srcH = (DIR == 0) ? Bhi : Ahi;
        const __nv_bfloat16* srcL = (DIR == 0) ? Blo : Alo;
        uint4 hv = *(const uint4*)(srcH + (size_t)s * 64 + q * 8);
        uint4 lv = *(const uint4*)(srcL + (size_t)s * 64 + q * 8);
        uint32_t cb = (DIR == 0) ? 128u : 0u;
        uint32_t o = (uint32_t)e * ER + cb + q * 16;
        *(uint4*)(sm + o)         = hv;
        *(uint4*)(sm + EA_LO + o) = lv;
    }
    if (tid < 64) {
        int e = tid;
        int rowIdx = (DIR == 0) ? (p0 + (e >> 1)) : idx[e];
        int colIdx = (DIR == 0) ? idx[e] : (p0 + (e >> 1));
        uint2 rh = *(const uint2*)(fhi + (size_t)rowIdx * 4);
        uint2 ch = *(const uint2*)(fhi + (size_t)colIdx * 4);
        uint2 rl = *(const uint2*)(flo + (size_t)rowIdx * 4);
        uint2 cl = *(const uint2*)(flo + (size_t)colIdx * 4);
        uint32_t o = (uint32_t)e * ER + 256;
        *(uint4*)(sm + o)         = make_uint4(rh.x, rh.y, ch.x, ch.y);
        *(uint4*)(sm + EA_LO + o) = make_uint4(rl.x, rl.y, cl.x, cl.y);
    }
    __syncthreads();

    const int w = tid >> 5, lane = tid & 31;
    const int mbase = (w & 1) * 32;
    const int nb32  = (w >> 1) * 32;
    const int nb16  = (w >> 1) * 16;
    float acc[32];

    // ---- layer 1: K=136, N=128 ----
    MBARRIER_WAIT_PARITY(mbw, 0);
    #pragma unroll
    for (int i = 0; i < 32; i++) acc[i] = 0.f;
    layer_mma_s<8, 2>(smb, smb + SM_W, ER, EA_LO, EW_LO128, lane, mbase, nb32, acc);
    layer1_tail(smb, smb + SM_W, lane, mbase, nb32, acc);
    __syncthreads();
    if (tid == 0) {
        MBARRIER_EXPECT_TX(mbw, 69632u);
        bulk_copy_g2s(smb + SM_W, wsrc + 69632, 69632u, mbw);
    }
    epi12(sm, bias_s, lane, mbase, nb32, acc);
    __syncthreads();

    // ---- layer 2: K=128, N=128 ----
    MBARRIER_WAIT_PARITY(mbw, 1);
    #pragma unroll
    for (int i = 0; i < 32; i++) acc[i] = 0.f;
    layer_mma_s<8, 2>(smb, smb + SM_W, ER, EA_LO, EW_LO128, lane, mbase, nb32, acc);
    __syncthreads();
    if (tid == 0) {
        MBARRIER_EXPECT_TX(mbw, 34816u);
        bulk_copy_g2s(smb + SM_W, wsrc + 139264, 34816u, mbw);
    }
    epi12(sm, bias_s + 128, lane, mbase, nb32, acc);
    __syncthreads();

    // ---- layer 3: K=128, N=64 ----
    MBARRIER_WAIT_PARITY(mbw, 0);
    #pragma unroll
    for (int i = 0; i < 16; i++) acc[i] = 0.f;
    layer_mma_s<8, 1>(smb, smb + SM_W, ER, EA_LO, EW_LO64, lane, mbase, nb16, acc);

    if (DIR == 0) {
        #pragma unroll
        for (int m = 0; m < 2; m++)
            #pragma unroll
            for (int h = 0; h < 2; h++) {
                const float* d = acc + (m * 2 + h) * 4;
                int c = nb16 + h * 8 + 2 * (lane & 3);
                int r = mbase + m * 16 + (lane >> 2);
                float b0 = bias_s[256 + c], b1v = bias_s[256 + c + 1];
                float* q0 = nm + (size_t)idx[r] * 64 + c;
                float* q1 = nm + (size_t)idx[r + 8] * 64 + c;
                atomicAdd(q0,     d[0] + b0);
                atomicAdd(q0 + 1, d[1] + b1v);
                atomicAdd(q1,     d[2] + b0);
                atomicAdd(q1 + 1, d[3] + b1v);
            }
    } else {
        __syncthreads();
        float* st = (float*)sm;
        #pragma unroll
        for (int m = 0; m < 2; m++)
            #pragma unroll
            for (int h = 0; h < 2; h++) {
                const float* d = acc + (m * 2 + h) * 4;
                int c = nb16 + h * 8 + 2 * (lane & 3);
                int r = mbase + m * 16 + (lane >> 2);
                float b0 = bias_s[256 + c], b1v = bias_s[256 + c + 1];
                st[r * 68 + c]           = d[0] + b0;
                st[r * 68 + c + 1]       = d[1] + b1v;
                st[(r + 8) * 68 + c]     = d[2] + b0;
                st[(r + 8) * 68 + c + 1] = d[3] + b1v;
            }
        __syncthreads();
        for (int i = tid; i < 2048; i += 256) {
            int r = i >> 6, c = i & 63;
            nm[(size_t)(p0 + r) * 64 + c] = st[(2 * r) * 68 + c] + st[(2 * r + 1) * 68 + c];
        }
    }
}

// ---------------- HMMA GRU (unchanged) ----------------
#define GSM_W    69632
#define GSM_BIAS 208896
#define GSM_MBW  209920
#define GRU_SMEM_BYTES 209952
__global__ __launch_bounds__(512, 1) void gru_mma_kernel(
    float* __restrict__ h,
    __nv_bfloat16* __restrict__ h_hi, __nv_bfloat16* __restrict__ h_lo,
    float* __restrict__ x,
    const unsigned char* __restrict__ wsrc,
    const float* __restrict__ bih, const float* __restrict__ bhh,
    int nrows)
{
    extern __shared__ __align__(256) unsigned char sm[];
    const uint32_t smb = smem_u32(sm);
    const int tid = threadIdx.x;
    const int r0 = blockIdx.x * 128;

    float* bias_s = (float*)(sm + GSM_BIAS);
    float* gs     = (float*)(sm + GSM_W);
    const uint32_t mbw = smb + GSM_MBW;

    if (tid == 0) MBARRIER_INIT(mbw, 1u);
    __syncthreads();
    if (tid == 0) {
        MBARRIER_EXPECT_TX(mbw, 139264u);
        bulk_copy_g2s(smb + GSM_W, wsrc, 139264u, mbw);
    }
    for (int i = tid; i < 256; i += 512) {
        float v;
        if (i < 128)      v = bih[i] + bhh[i];
        else if (i < 192) v = bih[i];
        else              v = bhh[i - 64];
        bias_s[i] = v;
    }

    for (int i = tid; i < 128 * 32; i += 512) {
        int e = i >> 5, q = i & 31;
        int rr = r0 + e;
        int rc = rr < nrows ? rr : nrows - 1;
        float4 xv;
        if (q < 16) {
            xv = *(const float4*)(x + (size_t)rc * 64 + q * 4);
            if (rr < nrows) *(float4*)(x + (size_t)rc * 64 + q * 4) = make_float4(0.f, 0.f, 0.f, 0.f);
        } else {
            xv = *(const float4*)(h + (size_t)rc * 64 + (q - 16) * 4);
        }
        __nv_bfloat162 h01 = __floats2bfloat162_rn(xv.x, xv.y);
        __nv_bfloat162 h23 = __floats2bfloat162_rn(xv.z, xv.w);
        __nv_bfloat162 l01 = __floats2bfloat162_rn(xv.x - __low2float(h01), xv.y - __high2float(h01));
        __nv_bfloat162 l23 = __floats2bfloat162_rn(xv.z - __low2float(h23), xv.w - __high2float(h23));
        uint32_t off = (uint32_t)e * GR + (uint32_t)q * 8;
        *(uint2*)(sm + off)         = make_uint2(*(uint32_t*)&h01, *(uint32_t*)&h23);
        *(uint2*)(sm + GA_LO + off) = make_uint2(*(uint32_t*)&l01, *(uint32_t*)&l23);
    }
    __syncthreads();

    const int w = tid >> 5, lane = tid & 31;
    const int mbase = (w & 3) * 32;
    const int nbase = (w >> 2) * 64;
    float acc[64];
    #pragma unroll
    for (int i = 0; i < 64; i++) acc[i] = 0.f;

    MBARRIER_WAIT_PARITY(mbw, 0);
    layer_mma_s<8, 4>(smb, smb + GSM_W, GR, GA_LO, GW_LO, lane, mbase, nbase, acc);
    __syncthreads();

    #pragma unroll
    for (int m = 0; m < 2; m++)
        #pragma unroll
        for (int np = 0; np < 4; np++)
            #pragma unroll
            for (int hh = 0; hh < 2; hh++) {
                const float* d = acc + ((m * 4 + np) * 2 + hh) * 4;
                int c = nbase + np * 16 + hh * 8 + 2 * (lane & 3);
                int r = mbase + m * 16 + (lane >> 2);
                gs[r * 256 + c]           = d[0];
                gs[r * 256 + c + 1]       = d[1];
                gs[(r + 8) * 256 + c]     = d[2];
                gs[(r + 8) * 256 + c + 1] = d[3];
            }
    __syncthreads();

    for (int i = tid; i < 128 * 64; i += 512) {
        int e = i >> 6, d = i & 63;
        int r = r0 + e;
        if (r >= nrows) continue;
        const float* g = gs + e * 256;
        float pr = g[d]       + bias_s[d];
        float pz = g[64 + d]  + bias_s[64 + d];
        float in = g[128 + d] + bias_s[128 + d];
        float hn = g[192 + d] + bias_s[192 + d];
        float rr = 1.f / (1.f + expf(-pr));
        float zz = 1.f / (1.f + expf(-pz));
        float nn = tanhf(in + rr * hn);
        float hv = h[(size_t)r * 64 + d];
        float hnew = (1.f - zz) * nn + zz * hv;
        h[(size_t)r * 64 + d] = hnew;
        __nv_bfloat16 hb = __float2bfloat16(hnew);
        h_hi[(size_t)r * 64 + d] = hb;
        h_lo[(size_t)r * 64 + d] = __float2bfloat16(hnew - __bfloat162float(hb));
    }
}

// ---------------- readout (unchanged) ----------------
__global__ __launch_bounds__(256) void readout_kernel(
    const float* __restrict__ h,
    const float* __restrict__ W1, const float* __restrict__ b1,
    const float* __restrict__ W2, const float* __restrict__ b2,
    const float* __restrict__ W3, const float* __restrict__ b3,
    float* __restrict__ out, int nrows)
{
    __shared__ float hs[32 * 68];
    __shared__ float l1s[32 * 132];
    __shared__ float l2s[32 * 132];
    __shared__ float lg[64];

    const int tid = threadIdx.x;
    const int r0  = blockIdx.x * 32;

    for (int i = tid; i < 32 * 64; i += 256) {
        int e = i >> 6, k = i & 63;
        int r = r0 + e;
        hs[e * 68 + k] = (r < nrows) ? h[(size_t)r * 64 + k] : 0.f;
    }
    __syncthreads();

    const int warp = tid >> 5, lane = tid & 31;
    #pragma unroll
    for (int jc = 0; jc < 4; jc++) {
        const int j0 = warp * 16 + jc * 4;
        float a[4] = {0.f, 0.f, 0.f, 0.f};
        #pragma unroll
        for (int k = 0; k < 64; k += 4) {
            float4 xv = *(const float4*)(hs + lane * 68 + k);
            #pragma unroll
            for (int jj = 0; jj < 4; jj++) {
                float4 wv = *(const float4*)(W1 + (size_t)(j0 + jj) * 64 + k);
                a[jj] += wv.x * xv.x + wv.y * xv.y + wv.z * xv.z + wv.w * xv.w;
            }
        }
        #pragma unroll
        for (int jj = 0; jj < 4; jj++)
            l1s[lane * 132 + j0 + jj] = fmaxf(a[jj] + b1[j0 + jj], 0.f);
    }
    __syncthreads();
    #pragma unroll
    for (int jc = 0; jc < 4; jc++) {
        const int j0 = warp * 16 + jc * 4;
        float a[4] = {0.f, 0.f, 0.f, 0.f};
        #pragma unroll 2
        for (int k = 0; k < 128; k += 4) {
            float4 xv = *(const float4*)(l1s + lane * 132 + k);
            #pragma unroll
            for (int jj = 0; jj < 4; jj++) {
                float4 wv = *(const float4*)(W2 + (size_t)(j0 + jj) * 128 + k);
                a[jj] += wv.x * xv.x + wv.y * xv.y + wv.z * xv.z + wv.w * xv.w;
            }
        }
        #pragma unroll
        for (int jj = 0; jj < 4; jj++)
            l2s[lane * 132 + j0 + jj] = fmaxf(a[jj] + b2[j0 + jj], 0.f);
    }
    __syncthreads();
    if (tid < 64) {
        int e = tid >> 1, j = tid & 1;
        float a = 0.f;
        #pragma unroll 4
        for (int k = 0; k < 128; k += 4) {
            float4 xv = *(const float4*)(l2s + e * 132 + k);
            float4 wv = *(const float4*)(W3 + (size_t)j * 128 + k);
            a += wv.x * xv.x + wv.y * xv.y + wv.z * xv.z + wv.w * xv.w;
        }
        lg[e * 2 + j] = a + b3[j];
    }
    __syncthreads();
    if (tid < 64) {
        int e = tid >> 1, j = tid & 1;
        int r = r0 + e;
        if (r < nrows) {
            float self  = lg[e * 2 + j];
            float other = lg[e * 2 + (j ^ 1)];
            out[(size_t)r * 2 + j] = 1.f / (1.f + expf(other - self));
        }
    }
}

extern "C" void kernel_launch(void* const* d_in, const int* in_sizes, int n_in,
                              void* d_out, int out_size)
{
    const int*   f2v_col  = (const int*)d_in[1];
    const int*   v2f_row  = (const int*)d_in[2];
    const float* f2v_feat = (const float*)d_in[4];
    const float* v2f_feat = (const float*)d_in[5];
    const float* f2v_w1 = (const float*)d_in[6];   const float* f2v_b1 = (const float*)d_in[7];
    const float* f2v_w2 = (const float*)d_in[8];   const float* f2v_b2 = (const float*)d_in[9];
    const float* f2v_w3 = (const float*)d_in[10];  const float* f2v_b3 = (const float*)d_in[11];
    const float* v2f_w1 = (const float*)d_in[12];  const float* v2f_b1 = (const float*)d_in[13];
    const float* v2f_w2 = (const float*)d_in[14];  const float* v2f_b2 = (const float*)d_in[15];
    const float* v2f_w3 = (const float*)d_in[16];  const float* v2f_b3 = (const float*)d_in[17];
    const float* gf_wih = (const float*)d_in[18];  const float* gf_whh = (const float*)d_in[19];
    const float* gf_bih = (const float*)d_in[20];  const float* gf_bhh = (const float*)d_in[21];
    const float* gv_wih = (const float*)d_in[22];  const float* gv_whh = (const float*)d_in[23];
    const float* gv_bih = (const float*)d_in[24];  const float* gv_bhh = (const float*)d_in[25];
    const float* ro_w1  = (const float*)d_in[26];  const float* ro_b1  = (const float*)d_in[27];
    const float* ro_w2  = (const float*)d_in[28];  const float* ro_b2  = (const float*)d_in[29];
    const float* ro_w3  = (const float*)d_in[30];  const float* ro_b3  = (const float*)d_in[31];
    float* out = (float*)d_out;

    float *var_h, *fac_h, *nm_var, *nm_fac;
    __nv_bfloat16 *var_hhi, *var_hlo, *fac_hhi, *fac_hlo;
    __nv_bfloat16 *f2v_fhi, *f2v_flo, *v2f_fhi, *v2f_flo;
    unsigned char *wp_f2v, *wp_v2f, *wg_gf, *wg_gv;
    cudaGetSymbolAddress((void**)&var_h,   g_var_h);
    cudaGetSymbolAddress((void**)&fac_h,   g_fac_h);
    cudaGetSymbolAddress((void**)&nm_var,  g_nm_var);
    cudaGetSymbolAddress((void**)&nm_fac,  g_nm_fac);
    cudaGetSymbolAddress((void**)&var_hhi, g_var_hhi);
    cudaGetSymbolAddress((void**)&var_hlo, g_var_hlo);
    cudaGetSymbolAddress((void**)&fac_hhi, g_fac_hhi);
    cudaGetSymbolAddress((void**)&fac_hlo, g_fac_hlo);
    cudaGetSymbolAddress((void**)&f2v_fhi, g_f2v_fhi);
    cudaGetSymbolAddress((void**)&f2v_flo, g_f2v_flo);
    cudaGetSymbolAddress((void**)&v2f_fhi, g_v2f_fhi);
    cudaGetSymbolAddress((void**)&v2f_flo, g_v2f_flo);
    cudaGetSymbolAddress((void**)&wp_f2v,  g_wpack_f2v);
    cudaGetSymbolAddress((void**)&wp_v2f,  g_wpack_v2f);
    cudaGetSymbolAddress((void**)&wg_gf,   g_wgru_gf);
    cudaGetSymbolAddress((void**)&wg_gv,   g_wgru_gv);

    cudaFuncSetAttribute(edge_mma_kernel<0>, cudaFuncAttributeMaxDynamicSharedMemorySize, EDGE_SMEM_BYTES);
    cudaFuncSetAttribute(edge_mma_kernel<1>, cudaFuncAttributeMaxDynamicSharedMemorySize, EDGE_SMEM_BYTES);
    cudaFuncSetAttribute(gru_mma_kernel,     cudaFuncAttributeMaxDynamicSharedMemorySize, GRU_SMEM_BYTES);

    setup_kernel<<<296, 256>>>(
        f2v_w1, f2v_w2, f2v_w3, v2f_w1, v2f_w2, v2f_w3,
        gf_wih, gf_whh, gv_wih, gv_whh, f2v_feat, v2f_feat);

    for (int s = 0; s < 5; s++) {
        edge_mma_kernel<0><<<NE / 64, 256, EDGE_SMEM_BYTES>>>(
            fac_hhi, fac_hlo, var_hhi, var_hlo, f2v_col, f2v_fhi, f2v_flo,
            wp_f2v, f2v_b1, f2v_b2, f2v_b3, nm_var);
        gru_mma_kernel<<<(NV + 127) / 128, 512, GRU_SMEM_BYTES>>>(
            var_h, var_hhi, var_hlo, nm_var, wg_gf, gf_bih, gf_bhh, NV);

        edge_mma_kernel<1><<<NE / 64, 256, EDGE_SMEM_BYTES>>>(
            var_hhi, var_hlo, fac_hhi, fac_hlo, v2f_row, v2f_fhi, v2f_flo,
            wp_v2f, v2f_b1, v2f_b2, v2f_b3, nm_fac);
        gru_mma_kernel<<<NF / 128, 512, GRU_SMEM_BYTES>>>(
            fac_h, fac_hhi, fac_hlo, nm_fac, wg_gv, gv_bih, gv_bhh, NF);
    }

    readout_kernel<<<(NV + 31) / 32, 256>>>(
        var_h, ro_w1, ro_b1, ro_w2, ro_b2, ro_w3, ro_b3, out, NV);
}

// round 13
// speedup vs baseline: 1.1672x; 1.0442x over previous
#include <cuda_runtime.h>
#include <cuda_bf16.h>
#include <cstdint>
#include <math.h>

#define NV 10000
#define NF 80000
#define NE 160000

#define ER 272
#define EA_LO 17408
#define EW_LO128 34816
#define EW_LO64  17408

__device__ float g_var_h[NV * 64];
__device__ float g_fac_h[NF * 64];
__device__ float g_nm_var[NV * 64];
__device__ float g_nm_fac[NF * 64];
__device__ __nv_bfloat16 g_var_hhi[NV * 64];
__device__ __nv_bfloat16 g_var_hlo[NV * 64];
__device__ __nv_bfloat16 g_fac_hhi[NF * 64];
__device__ __nv_bfloat16 g_fac_hlo[NF * 64];
__device__ __nv_bfloat16 g_f2v_fhi[NE * 4];
__device__ __nv_bfloat16 g_f2v_flo[NE * 4];
__device__ __nv_bfloat16 g_v2f_fhi[NE * 4];
__device__ __nv_bfloat16 g_v2f_flo[NE * 4];
__device__ __align__(256) unsigned char g_wpack_f2v[174080];
__device__ __align__(256) unsigned char g_wpack_v2f[174080];
// GRU pack: [Wrz hi 34816][Wrz lo 34816][Wn hi 18432][Wn lo 18432] = 106496
__device__ __align__(256) unsigned char g_wgru_gf[106496];
__device__ __align__(256) unsigned char g_wgru_gv[106496];

__device__ __forceinline__ uint32_t smem_u32(const void* p) {
    uint32_t a;
    asm("{ .reg .u64 t; cvta.to.shared.u64 t, %1; cvt.u32.u64 %0, t; }" : "=r"(a) : "l"(p));
    return a;
}
#define MBARRIER_INIT(mbar, cnt) \
    asm volatile("mbarrier.init.shared.b64 [%0], %1;" :: "r"(mbar), "r"(cnt) : "memory")
#define MBARRIER_EXPECT_TX(mbar, bytes) \
    asm volatile("mbarrier.arrive.expect_tx.shared.b64 _, [%0], %1;" :: "r"(mbar), "r"(bytes) : "memory")
#define MBARRIER_WAIT_PARITY(mbar, ph) do { \
    asm volatile("{\n\t.reg .pred P1;\n\t" \
        "W_%=:\n\tmbarrier.try_wait.parity.acquire.cta.shared::cta.b64 P1, [%0], %1, 0x989680;\n\t" \
        "@P1 bra.uni D_%=;\n\tbra.uni W_%=;\n\tD_%=:\n\t}" \
        :: "r"(mbar), "r"(ph) : "memory"); \
} while (0)

__device__ __forceinline__ void bulk_copy_g2s(uint32_t dst, const void* src,
                                              uint32_t bytes, uint32_t mbar) {
    asm volatile(
        "cp.async.bulk.shared::cluster.global.mbarrier::complete_tx::bytes [%0], [%1], %2, [%3];"
        :: "r"(dst), "l"(src), "r"(bytes), "r"(mbar) : "memory");
}
__device__ __forceinline__ void ldsm4(uint32_t addr, uint32_t* r) {
    asm volatile("ldmatrix.sync.aligned.m8n8.x4.shared.b16 {%0,%1,%2,%3}, [%4];"
        : "=r"(r[0]), "=r"(r[1]), "=r"(r[2]), "=r"(r[3]) : "r"(addr));
}
__device__ __forceinline__ void mma16816(float* d, const uint32_t* a, const uint32_t* b) {
    asm volatile("mma.sync.aligned.m16n8k16.row.col.f32.bf16.bf16.f32 "
        "{%0,%1,%2,%3}, {%4,%5,%6,%7}, {%8,%9}, {%0,%1,%2,%3};"
        : "+f"(d[0]), "+f"(d[1]), "+f"(d[2]), "+f"(d[3])
        : "r"(a[0]), "r"(a[1]), "r"(a[2]), "r"(a[3]), "r"(b[0]), "r"(b[1]));
}
__device__ __forceinline__ void mma16808(float* d, const uint32_t* a, uint32_t b) {
    asm volatile("mma.sync.aligned.m16n8k8.row.col.f32.bf16.bf16.f32 "
        "{%0,%1,%2,%3}, {%4,%5}, {%6}, {%0,%1,%2,%3};"
        : "+f"(d[0]), "+f"(d[1]), "+f"(d[2]), "+f"(d[3])
        : "r"(a[0]), "r"(a[1]), "r"(b));
}

// ---------------- fused setup ----------------
__device__ void dev_pack_w(unsigned char* dst, const float* W, int nrows, int kin,
                           int gt, int gs) {
    const int total = nrows * 136;
    const int plane = nrows * ER;
    for (int i = gt; i < total; i += gs) {
        int n = i / 136, k = i - n * 136;
        float v = (k < kin) ? W[n * kin + k] : 0.0f;
        __nv_bfloat16 hi = __float2bfloat16(v);
        __nv_bfloat16 lo = __float2bfloat16(v - __bfloat162float(hi));
        uint32_t off = (uint32_t)n * ER + (uint32_t)k * 2;
        *(__nv_bfloat16*)(dst + off) = hi;
        *(__nv_bfloat16*)(dst + plane + off) = lo;
    }
}
// GRU: Wrz [128 x 136 pad] stride 272 (cols0-63=wih_r/z, 64-127=whh_r/z)
//      Wn  [128 x 72 pad]  stride 144 (rows0-63=wih_n, rows64-127=whh_n)
__device__ void dev_pack_gru(unsigned char* dst, const float* wih, const float* whh,
                             int gt, int gs) {
    for (int i = gt; i < 128 * 136; i += gs) {
        int r = i / 136, k = i - r * 136;
        float v = 0.0f;
        if (k < 64)       v = wih[r * 64 + k];
        else if (k < 128) v = whh[r * 64 + (k - 64)];
        __nv_bfloat16 hi = __float2bfloat16(v);
        __nv_bfloat16 lo = __float2bfloat16(v - __bfloat162float(hi));
        uint32_t off = (uint32_t)r * 272 + (uint32_t)k * 2;
        *(__nv_bfloat16*)(dst + off) = hi;
        *(__nv_bfloat16*)(dst + 34816 + off) = lo;
    }
    for (int i = gt; i < 128 * 72; i += gs) {
        int r = i / 72, k = i - r * 72;
        float v = 0.0f;
        if (k < 64)
            v = (r < 64) ? wih[(128 + r) * 64 + k] : whh[(64 + r) * 64 + k];
        __nv_bfloat16 hi = __float2bfloat16(v);
        __nv_bfloat16 lo = __float2bfloat16(v - __bfloat162float(hi));
        uint32_t off = (uint32_t)r * 144 + (uint32_t)k * 2;
        *(__nv_bfloat16*)(dst + 69632 + off) = hi;
        *(__nv_bfloat16*)(dst + 69632 + 18432 + off) = lo;
    }
}
__device__ void dev_split(__nv_bfloat16* hi_out, __nv_bfloat16* lo_out,
                          const float* src, int n, int gt, int gs) {
    for (int i = gt; i < n; i += gs) {
        float v = src[i];
        __nv_bfloat16 hi = __float2bfloat16(v);
        hi_out[i] = hi;
        lo_out[i] = __float2bfloat16(v - __bfloat162float(hi));
    }
}
__device__ void dev_zero_f(float* p, int n, int gt, int gs) {
    for (int i = gt; i < n; i += gs) p[i] = 0.0f;
}

__global__ __launch_bounds__(256) void setup_kernel(
    const float* __restrict__ f2v_w1, const float* __restrict__ f2v_w2,
    const float* __restrict__ f2v_w3,
    const float* __restrict__ v2f_w1, const float* __restrict__ v2f_w2,
    const float* __restrict__ v2f_w3,
    const float* __restrict__ gf_wih, const float* __restrict__ gf_whh,
    const float* __restrict__ gv_wih, const float* __restrict__ gv_whh,
    const float* __restrict__ f2v_feat, const float* __restrict__ v2f_feat)
{
    const int gt = blockIdx.x * blockDim.x + threadIdx.x;
    const int gs = gridDim.x * blockDim.x;

    dev_pack_w(g_wpack_f2v,          f2v_w1, 128, 136, gt, gs);
    dev_pack_w(g_wpack_f2v + 69632,  f2v_w2, 128, 128, gt, gs);
    dev_pack_w(g_wpack_f2v + 139264, f2v_w3,  64, 128, gt, gs);
    dev_pack_w(g_wpack_v2f,          v2f_w1, 128, 136, gt, gs);
    dev_pack_w(g_wpack_v2f + 69632,  v2f_w2, 128, 128, gt, gs);
    dev_pack_w(g_wpack_v2f + 139264, v2f_w3,  64, 128, gt, gs);
    dev_pack_gru(g_wgru_gf, gf_wih, gf_whh, gt, gs);
    dev_pack_gru(g_wgru_gv, gv_wih, gv_whh, gt, gs);
    dev_split(g_f2v_fhi, g_f2v_flo, f2v_feat, NE * 4, gt, gs);
    dev_split(g_v2f_fhi, g_v2f_flo, v2f_feat, NE * 4, gt, gs);
    dev_zero_f(g_var_h,  NV * 64, gt, gs);
    dev_zero_f(g_fac_h,  NF * 64, gt, gs);
    dev_zero_f(g_nm_var, NV * 64, gt, gs);
    dev_zero_f((float*)g_var_hhi, NV * 32, gt, gs);
    dev_zero_f((float*)g_var_hlo, NV * 32, gt, gs);
    dev_zero_f((float*)g_fac_hhi, NF * 32, gt, gs);
    dev_zero_f((float*)g_fac_hlo, NF * 32, gt, gs);
}

// ---------------- HMMA tile, single stride (edge kernel, proven) -----------
template<int KCH, int NPAIR>
__device__ __forceinline__ void layer_mma_s(
    uint32_t aA, uint32_t aW, uint32_t rstr, uint32_t aLo, uint32_t wLo,
    int lane, int mbase, int nbase, float* acc)
{
    const uint32_t aRow = aA + (uint32_t)(mbase + (lane & 15)) * rstr + ((lane >> 4) << 4);
    const uint32_t bRow = aW + (uint32_t)(nbase + (lane & 7) + ((lane >> 4) << 3)) * rstr
                        + (((lane >> 3) & 1) << 4);
    #pragma unroll
    for (int kc = 0; kc < KCH; kc++) {
        uint32_t ah[8], al[8];
        ldsm4(aRow + kc * 32, ah);
        ldsm4(aRow + 16 * rstr + kc * 32, ah + 4);
        ldsm4(aRow + aLo + kc * 32, al);
        ldsm4(aRow + aLo + 16 * rstr + kc * 32, al + 4);
        #pragma unroll
        for (int np = 0; np < NPAIR; np++) {
            uint32_t bh[4], bl[4];
            ldsm4(bRow + np * 16 * rstr + kc * 32, bh);
            ldsm4(bRow + wLo + np * 16 * rstr + kc * 32, bl);
            #pragma unroll
            for (int m = 0; m < 2; m++) {
                #pragma unroll
                for (int h = 0; h < 2; h++) {
                    float* d = acc + ((m * NPAIR + np) * 2 + h) * 4;
                    mma16816(d, ah + m * 4, bh + h * 2);
                    mma16816(d, ah + m * 4, bl + h * 2);
                    mma16816(d, al + m * 4, bh + h * 2);
                }
            }
        }
    }
}

// ---------------- HMMA tile, separate A/W strides (GRU) --------------------
template<int KCH, int NPAIR>
__device__ __forceinline__ void layer_mma_2s(
    uint32_t aA, uint32_t aStr, uint32_t aLo,
    uint32_t aW, uint32_t wStr, uint32_t wLo,
    int lane, int mbase, int nbase, float* acc)
{
    const uint32_t aRow = aA + (uint32_t)(mbase + (lane & 15)) * aStr + ((lane >> 4) << 4);
    const uint32_t bRow = aW + (uint32_t)(nbase + (lane & 7) + ((lane >> 4) << 3)) * wStr
                        + (((lane >> 3) & 1) << 4);
    #pragma unroll
    for (int kc = 0; kc < KCH; kc++) {
        uint32_t ah[8], al[8];
        ldsm4(aRow + kc * 32, ah);
        ldsm4(aRow + 16 * aStr + kc * 32, ah + 4);
        ldsm4(aRow + aLo + kc * 32, al);
        ldsm4(aRow + aLo + 16 * aStr + kc * 32, al + 4);
        #pragma unroll
        for (int np = 0; np < NPAIR; np++) {
            uint32_t bh[4], bl[4];
            ldsm4(bRow + np * 16 * wStr + kc * 32, bh);
            ldsm4(bRow + wLo + np * 16 * wStr + kc * 32, bl);
            #pragma unroll
            for (int m = 0; m < 2; m++) {
                #pragma unroll
                for (int h = 0; h < 2; h++) {
                    float* d = acc + ((m * NPAIR + np) * 2 + h) * 4;
                    mma16816(d, ah + m * 4, bh + h * 2);
                    mma16816(d, ah + m * 4, bl + h * 2);
                    mma16816(d, al + m * 4, bh + h * 2);
                }
            }
        }
    }
}

__device__ __forceinline__ void layer1_tail(
    uint32_t aA, uint32_t aW, int lane, int mbase, int nbase, float* acc)
{
    const uint32_t aAddr = aA + (uint32_t)(mbase + lane) * ER + 256;
    const uint32_t bAddr = aW + (uint32_t)(nbase + lane) * ER + 256;
    uint32_t ah[4], al[4], bh[4], bl[4];
    ldsm4(aAddr, ah);
    ldsm4(aAddr + EA_LO, al);
    ldsm4(bAddr, bh);
    ldsm4(bAddr + EW_LO128, bl);
    #pragma unroll
    for (int m = 0; m < 2; m++)
        #pragma unroll
        for (int n4 = 0; n4 < 4; n4++) {
            float* d = acc + ((m * 2 + (n4 >> 1)) * 2 + (n4 & 1)) * 4;
            mma16808(d, ah + 2 * m, bh[n4]);
            mma16808(d, ah + 2 * m, bl[n4]);
            mma16808(d, al + 2 * m, bh[n4]);
        }
}

__device__ __forceinline__ void epi12(unsigned char* Ab, const float* bias,
                                      int lane, int mbase, int nbase, const float* acc)
{
    #pragma unroll
    for (int m = 0; m < 2; m++)
        #pragma unroll
        for (int np = 0; np < 2; np++)
            #pragma unroll
            for (int h = 0; h < 2; h++) {
                const float* d = acc + ((m * 2 + np) * 2 + h) * 4;
                int c = nbase + np * 16 + h * 8 + 2 * (lane & 3);
                int r = mbase + m * 16 + (lane >> 2);
                float b0 = bias[c], b1 = bias[c + 1];
                float v0 = fmaxf(d[0] + b0, 0.f), v1 = fmaxf(d[1] + b1, 0.f);
                float v2 = fmaxf(d[2] + b0, 0.f), v3 = fmaxf(d[3] + b1, 0.f);
                __nv_bfloat162 hA = __floats2bfloat162_rn(v0, v1);
                __nv_bfloat162 lA = __floats2bfloat162_rn(v0 - __low2float(hA),
                                                          v1 - __high2float(hA));
                __nv_bfloat162 hB = __floats2bfloat162_rn(v2, v3);
                __nv_bfloat162 lB = __floats2bfloat162_rn(v2 - __low2float(hB),
                                                          v3 - __high2float(hB));
                uint32_t o0 = (uint32_t)r * ER + (uint32_t)c * 2;
                uint32_t o1 = o0 + 8u * ER;
                *(uint32_t*)(Ab + o0)         = *(uint32_t*)&hA;
                *(uint32_t*)(Ab + EA_LO + o0) = *(uint32_t*)&lA;
                *(uint32_t*)(Ab + o1)         = *(uint32_t*)&hB;
                *(uint32_t*)(Ab + EA_LO + o1) = *(uint32_t*)&lB;
            }
}

// ---------------- edge MLP (R12 exact, untouched) ----------------
#define SM_W    34816
#define SM_IDX  104448
#define SM_BIAS 104960
#define SM_MBW  106240
#define EDGE_SMEM_BYTES 106272
template<int DIR>
__global__ __launch_bounds__(256, 2) void edge_mma_kernel(
    const __nv_bfloat16* __restrict__ Ahi, const __nv_bfloat16* __restrict__ Alo,
    const __nv_bfloat16* __restrict__ Bhi, const __nv_bfloat16* __restrict__ Blo,
    const int* __restrict__ idxArr,
    const __nv_bfloat16* __restrict__ fhi, const __nv_bfloat16* __restrict__ flo,
    const unsigned char* __restrict__ wsrc,
    const float* __restrict__ b1, const float* __restrict__ b2,
    const float* __restrict__ b3,
    float* __restrict__ nm)
{
    extern __shared__ __align__(256) unsigned char sm[];
    const uint32_t smb = smem_u32(sm);
    const int tid = threadIdx.x;
    const int e0 = blockIdx.x * 64;
    const int p0 = e0 >> 1;

    int*   idx    = (int*)(sm + SM_IDX);
    float* bias_s = (float*)(sm + SM_BIAS);
    const uint32_t mbw = smb + SM_MBW;

    if (tid == 0) MBARRIER_INIT(mbw, 1u);
    __syncthreads();
    if (tid == 0) {
        MBARRIER_EXPECT_TX(mbw, 69632u);
        bulk_copy_g2s(smb + SM_W, wsrc, 69632u, mbw);
    }
    if (tid < 64) idx[tid] = idxArr[e0 + tid];
    for (int i = tid; i < 320; i += 256)
        bias_s[i] = (i < 128) ? b1[i] : (i < 256 ? b2[i - 128] : b3[i - 256]);
    __syncthreads();

    {
        int r = tid >> 3, q = tid & 7;
        const __nv_bfloat16* srcH = (DIR == 0) ? Ahi : Bhi;
        const __nv_bfloat16* srcL = (DIR == 0) ? Alo : Blo;
        uint4 hv = *(const uint4*)(srcH + (size_t)(p0 + r) * 64 + q * 8);
        uint4 lv = *(const uint4*)(srcL + (size_t)(p0 + r) * 64 + q * 8);
        uint32_t cb = (DIR == 0) ? 0u : 128u;
        uint32_t o0 = (uint32_t)(2 * r)     * ER + cb + q * 16;
        uint32_t o1 = (uint32_t)(2 * r + 1) * ER + cb + q * 16;
        *(uint4*)(sm + o0)         = hv;  *(uint4*)(sm + o1)         = hv;
        *(uint4*)(sm + EA_LO + o0) = lv;  *(uint4*)(sm + EA_LO + o1) = lv;
    }
    for (int i = tid; i < 512; i += 256) {
        int e = i >> 3, q = i & 7;
        int s = idx[e];
        const __nv_bfloat16* srcH = (DIR == 0) ? Bhi : Ahi;
        const __nv_bfloat16* srcL = (DIR == 0) ? Blo : Alo;
        uint4 hv = *(const uint4*)(srcH + (size_t)s * 64 + q * 8);
        uint4 lv = *(const uint4*)(srcL + (size_t)s * 64 + q * 8);
        uint32_t cb = (DIR == 0) ? 128u : 0u;
        uint32_t o = (uint32_t)e * ER + cb + q * 16;
        *(uint4*)(sm + o)         = hv;
        *(uint4*)(sm + EA_LO + o) = lv;
    }
    if (tid < 64) {
        int e = tid;
        int rowIdx = (DIR == 0) ? (p0 + (e >> 1)) : idx[e];
        int colIdx = (DIR == 0) ? idx[e] : (p0 + (e >> 1));
        uint2 rh = *(const uint2*)(fhi + (size_t)rowIdx * 4);
        uint2 ch = *(const uint2*)(fhi + (size_t)colIdx * 4);
        uint2 rl = *(const uint2*)(flo + (size_t)rowIdx * 4);
        uint2 cl = *(const uint2*)(flo + (size_t)colIdx * 4);
        uint32_t o = (uint32_t)e * ER + 256;
        *(uint4*)(sm + o)         = make_uint4(rh.x, rh.y, ch.x, ch.y);
        *(uint4*)(sm + EA_LO + o) = make_uint4(rl.x, rl.y, cl.x, cl.y);
    }
    __syncthreads();

    const int w = tid >> 5, lane = tid & 31;
    const int mbase = (w & 1) * 32;
    const int nb32  = (w >> 1) * 32;
    const int nb16  = (w >> 1) * 16;
    float acc[32];

    MBARRIER_WAIT_PARITY(mbw, 0);
    #pragma unroll
    for (int i = 0; i < 32; i++) acc[i] = 0.f;
    layer_mma_s<8, 2>(smb, smb + SM_W, ER, EA_LO, EW_LO128, lane, mbase, nb32, acc);
    layer1_tail(smb, smb + SM_W, lane, mbase, nb32, acc);
    __syncthreads();
    if (tid == 0) {
        MBARRIER_EXPECT_TX(mbw, 69632u);
        bulk_copy_g2s(smb + SM_W, wsrc + 69632, 69632u, mbw);
    }
    epi12(sm, bias_s, lane, mbase, nb32, acc);
    __syncthreads();

    MBARRIER_WAIT_PARITY(mbw, 1);
    #pragma unroll
    for (int i = 0; i < 32; i++) acc[i] = 0.f;
    layer_mma_s<8, 2>(smb, smb + SM_W, ER, EA_LO, EW_LO128, lane, mbase, nb32, acc);
    __syncthreads();
    if (tid == 0) {
        MBARRIER_EXPECT_TX(mbw, 34816u);
        bulk_copy_g2s(smb + SM_W, wsrc + 139264, 34816u, mbw);
    }
    epi12(sm, bias_s + 128, lane, mbase, nb32, acc);
    __syncthreads();

    MBARRIER_WAIT_PARITY(mbw, 0);
    #pragma unroll
    for (int i = 0; i < 16; i++) acc[i] = 0.f;
    layer_mma_s<8, 1>(smb, smb + SM_W, ER, EA_LO, EW_LO64, lane, mbase, nb16, acc);

    if (DIR == 0) {
        #pragma unroll
        for (int m = 0; m < 2; m++)
            #pragma unroll
            for (int h = 0; h < 2; h++) {
                const float* d = acc + (m * 2 + h) * 4;
                int c = nb16 + h * 8 + 2 * (lane & 3);
                int r = mbase + m * 16 + (lane >> 2);
                float b0 = bias_s[256 + c], b1v = bias_s[256 + c + 1];
                float* q0 = nm + (size_t)idx[r] * 64 + c;
                float* q1 = nm + (size_t)idx[r + 8] * 64 + c;
                atomicAdd(q0,     d[0] + b0);
                atomicAdd(q0 + 1, d[1] + b1v);
                atomicAdd(q1,     d[2] + b0);
                atomicAdd(q1 + 1, d[3] + b1v);
            }
    } else {
        __syncthreads();
        float* st = (float*)sm;
        #pragma unroll
        for (int m = 0; m < 2; m++)
            #pragma unroll
            for (int h = 0; h < 2; h++) {
                const float* d = acc + (m * 2 + h) * 4;
                int c = nb16 + h * 8 + 2 * (lane & 3);
                int r = mbase + m * 16 + (lane >> 2);
                float b0 = bias_s[256 + c], b1v = bias_s[256 + c + 1];
                st[r * 68 + c]           = d[0] + b0;
                st[r * 68 + c + 1]       = d[1] + b1v;
                st[(r + 8) * 68 + c]     = d[2] + b0;
                st[(r + 8) * 68 + c + 1] = d[3] + b1v;
            }
        __syncthreads();
        for (int i = tid; i < 2048; i += 256) {
            int r = i >> 6, c = i & 63;
            nm[(size_t)(p0 + r) * 64 + c] = st[(2 * r) * 68 + c] + st[(2 * r + 1) * 68 + c];
        }
    }
}

// ---------------- GRU-64: 64 rows/block, occ=2, zero-blocks removed ---------
// smem: A hi+lo [34816] | W buf [69632] | bias[1024] | mbar
// pass1: [x|h](K=128) @ Wrz(N=128).  pass2: x@wn (N 0-63), h@hn (N 64-127).
// gs overlay on A∪W after all MMA: 64 rows x 256 f32 = 65536 bytes.
#define G64_W    34816
#define G64_BIAS 104448
#define G64_MBW  105472
#define G64_SMEM_BYTES 105504
__global__ __launch_bounds__(256, 2) void gru64_kernel(
    float* __restrict__ h,
    __nv_bfloat16* __restrict__ h_hi, __nv_bfloat16* __restrict__ h_lo,
    float* __restrict__ x,
    const unsigned char* __restrict__ wsrc,
    const float* __restrict__ bih, const float* __restrict__ bhh,
    int nrows)
{
    extern __shared__ __align__(256) unsigned char sm[];
    const uint32_t smb = smem_u32(sm);
    const int tid = threadIdx.x;
    const int r0 = blockIdx.x * 64;

    float* bias_s = (float*)(sm + G64_BIAS);
    const uint32_t mbw = smb + G64_MBW;

    if (tid == 0) MBARRIER_INIT(mbw, 1u);
    __syncthreads();
    if (tid == 0) {
        MBARRIER_EXPECT_TX(mbw, 69632u);
        bulk_copy_g2s(smb + G64_W, wsrc, 69632u, mbw);   // Wrz hi+lo
    }
    {
        int i = tid;
        float v;
        if (i < 128)      v = bih[i] + bhh[i];
        else if (i < 192) v = bih[i];
        else              v = bhh[i - 64];
        bias_s[i & 255] = v;   // 256 threads -> one each
    }

    // gather A = [x | h], hi/lo split; zero x after read
    for (int i = tid; i < 64 * 32; i += 256) {
        int e = i >> 5, q = i & 31;
        int rr = r0 + e;
        int rc = rr < nrows ? rr : nrows - 1;
        float4 xv;
        if (q < 16) {
            xv = *(const float4*)(x + (size_t)rc * 64 + q * 4);
            if (rr < nrows) *(float4*)(x + (size_t)rc * 64 + q * 4) = make_float4(0.f, 0.f, 0.f, 0.f);
        } else {
            xv = *(const float4*)(h + (size_t)rc * 64 + (q - 16) * 4);
        }
        __nv_bfloat162 h01 = __floats2bfloat162_rn(xv.x, xv.y);
        __nv_bfloat162 h23 = __floats2bfloat162_rn(xv.z, xv.w);
        __nv_bfloat162 l01 = __floats2bfloat162_rn(xv.x - __low2float(h01), xv.y - __high2float(h01));
        __nv_bfloat162 l23 = __floats2bfloat162_rn(xv.z - __low2float(h23), xv.w - __high2float(h23));
        uint32_t off = (uint32_t)e * ER + (uint32_t)q * 8;
        *(uint2*)(sm + off)         = make_uint2(*(uint32_t*)&h01, *(uint32_t*)&h23);
        *(uint2*)(sm + EA_LO + off) = make_uint2(*(uint32_t*)&l01, *(uint32_t*)&l23);
    }
    __syncthreads();

    const int w = tid >> 5, lane = tid & 31;
    const int mbase = (w & 1) * 32;
    const int nb32  = (w >> 1) * 32;
    float acc1[32], acc2[32];
    #pragma unroll
    for (int i = 0; i < 32; i++) { acc1[i] = 0.f; acc2[i] = 0.f; }

    // pass 1: rz, K=128 (8 ch)
    MBARRIER_WAIT_PARITY(mbw, 0);
    layer_mma_2s<8, 2>(smb, ER, EA_LO, smb + G64_W, ER, 34816, lane, mbase, nb32, acc1);
    __syncthreads();   // Wrz reads done -> Wn may overwrite
    if (tid == 0) {
        MBARRIER_EXPECT_TX(mbw, 36864u);
        bulk_copy_g2s(smb + G64_W, wsrc + 69632, 36864u, mbw);   // Wn hi+lo
    }
    // pass 2: n-gates, K=64 (4 ch). nb32<64 -> x@wn; else h@hn.
    MBARRIER_WAIT_PARITY(mbw, 1);
    {
        uint32_t aOff = (nb32 >= 64) ? 128u : 0u;        // x cols / h cols
        int nbW = nb32 & 63;                              // wn rows 0-63, hn rows 64-127
        int wBase = (nb32 >= 64) ? 64 : 0;
        layer_mma_2s<4, 2>(smb + aOff, ER, EA_LO,
                           smb + G64_W, 144, 18432, lane, mbase, wBase + nbW, acc2);
    }
    __syncthreads();   // all MMA + A reads done -> gs overlay safe

    float* gs = (float*)sm;   // 64 x 256 f32 overlay on A∪W
    #pragma unroll
    for (int m = 0; m < 2; m++)
        #pragma unroll
        for (int np = 0; np < 2; np++)
            #pragma unroll
            for (int hh = 0; hh < 2; hh++) {
                int c = nb32 + np * 16 + hh * 8 + 2 * (lane & 3);
                int r = mbase + m * 16 + (lane >> 2);
                const float* d1 = acc1 + ((m * 2 + np) * 2 + hh) * 4;
                const float* d2 = acc2 + ((m * 2 + np) * 2 + hh) * 4;
                gs[r * 256 + c]                 = d1[0];
                gs[r * 256 + c + 1]             = d1[1];
                gs[(r + 8) * 256 + c]           = d1[2];
                gs[(r + 8) * 256 + c + 1]       = d1[3];
                gs[r * 256 + 128 + c]           = d2[0];
                gs[r * 256 + 128 + c + 1]       = d2[1];
                gs[(r + 8) * 256 + 128 + c]     = d2[2];
                gs[(r + 8) * 256 + 128 + c + 1] = d2[3];
            }
    __syncthreads();

    for (int i = tid; i < 64 * 64; i += 256) {
        int e = i >> 6, d = i & 63;
        int r = r0 + e;
        if (r >= nrows) continue;
        const float* g = gs + e * 256;
        float pr = g[d]       + bias_s[d];
        float pz = g[64 + d]  + bias_s[64 + d];
        float in = g[128 + d] + bias_s[128 + d];
        float hn = g[192 + d] + bias_s[192 + d];
        float rr = 1.f / (1.f + expf(-pr));
        float zz = 1.f / (1.f + expf(-pz));
        float nn = tanhf(in + rr * hn);
        float hv = h[(size_t)r * 64 + d];
        float hnew = (1.f - zz) * nn + zz * hv;
        h[(size_t)r * 64 + d] = hnew;
        __nv_bfloat16 hb = __float2bfloat16(hnew);
        h_hi[(size_t)r * 64 + d] = hb;
        h_lo[(size_t)r * 64 + d] = __float2bfloat16(hnew - __bfloat162float(hb));
    }
}

// ---------------- readout (unchanged) ----------------
__global__ __launch_bounds__(256) void readout_kernel(
    const float* __restrict__ h,
    const float* __restrict__ W1, const float* __restrict__ b1,
    const float* __restrict__ W2, const float* __restrict__ b2,
    const float* __restrict__ W3, const float* __restrict__ b3,
    float* __restrict__ out, int nrows)
{
    __shared__ float hs[32 * 68];
    __shared__ float l1s[32 * 132];
    __shared__ float l2s[32 * 132];
    __shared__ float lg[64];

    const int tid = threadIdx.x;
    const int r0  = blockIdx.x * 32;

    for (int i = tid; i < 32 * 64; i += 256) {
        int e = i >> 6, k = i & 63;
        int r = r0 + e;
        hs[e * 68 + k] = (r < nrows) ? h[(size_t)r * 64 + k] : 0.f;
    }
    __syncthreads();

    const int warp = tid >> 5, lane = tid & 31;
    #pragma unroll
    for (int jc = 0; jc < 4; jc++) {
        const int j0 = warp * 16 + jc * 4;
        float a[4] = {0.f, 0.f, 0.f, 0.f};
        #pragma unroll
        for (int k = 0; k < 64; k += 4) {
            float4 xv = *(const float4*)(hs + lane * 68 + k);
            #pragma unroll
            for (int jj = 0; jj < 4; jj++) {
                float4 wv = *(const float4*)(W1 + (size_t)(j0 + jj) * 64 + k);
                a[jj] += wv.x * xv.x + wv.y * xv.y + wv.z * xv.z + wv.w * xv.w;
            }
        }
        #pragma unroll
        for (int jj = 0; jj < 4; jj++)
            l1s[lane * 132 + j0 + jj] = fmaxf(a[jj] + b1[j0 + jj], 0.f);
    }
    __syncthreads();
    #pragma unroll
    for (int jc = 0; jc < 4; jc++) {
        const int j0 = warp * 16 + jc * 4;
        float a[4] = {0.f, 0.f, 0.f, 0.f};
        #pragma unroll 2
        for (int k = 0; k < 128; k += 4) {
            float4 xv = *(const float4*)(l1s + lane * 132 + k);
            #pragma unroll
            for (int jj = 0; jj < 4; jj++) {
                float4 wv = *(const float4*)(W2 + (size_t)(j0 + jj) * 128 + k);
                a[jj] += wv.x * xv.x + wv.y * xv.y + wv.z * xv.z + wv.w * xv.w;
            }
        }
        #pragma unroll
        for (int jj = 0; jj < 4; jj++)
            l2s[lane * 132 + j0 + jj] = fmaxf(a[jj] + b2[j0 + jj], 0.f);
    }
    __syncthreads();
    if (tid < 64) {
        int e = tid >> 1, j = tid & 1;
        float a = 0.f;
        #pragma unroll 4
        for (int k = 0; k < 128; k += 4) {
            float4 xv = *(const float4*)(l2s + e * 132 + k);
            float4 wv = *(const float4*)(W3 + (size_t)j * 128 + k);
            a += wv.x * xv.x + wv.y * xv.y + wv.z * xv.z + wv.w * xv.w;
        }
        lg[e * 2 + j] = a + b3[j];
    }
    __syncthreads();
    if (tid < 64) {
        int e = tid >> 1, j = tid & 1;
        int r = r0 + e;
        if (r < nrows) {
            float self  = lg[e * 2 + j];
            float other = lg[e * 2 + (j ^ 1)];
            out[(size_t)r * 2 + j] = 1.f / (1.f + expf(other - self));
        }
    }
}

extern "C" void kernel_launch(void* const* d_in, const int* in_sizes, int n_in,
                              void* d_out, int out_size)
{
    const int*   f2v_col  = (const int*)d_in[1];
    const int*   v2f_row  = (const int*)d_in[2];
    const float* f2v_feat = (const float*)d_in[4];
    const float* v2f_feat = (const float*)d_in[5];
    const float* f2v_w1 = (const float*)d_in[6];   const float* f2v_b1 = (const float*)d_in[7];
    const float* f2v_w2 = (const float*)d_in[8];   const float* f2v_b2 = (const float*)d_in[9];
    const float* f2v_w3 = (const float*)d_in[10];  const float* f2v_b3 = (const float*)d_in[11];
    const float* v2f_w1 = (const float*)d_in[12];  const float* v2f_b1 = (const float*)d_in[13];
    const float* v2f_w2 = (const float*)d_in[14];  const float* v2f_b2 = (const float*)d_in[15];
    const float* v2f_w3 = (const float*)d_in[16];  const float* v2f_b3 = (const float*)d_in[17];
    const float* gf_wih = (const float*)d_in[18];  const float* gf_whh = (const float*)d_in[19];
    const float* gf_bih = (const float*)d_in[20];  const float* gf_bhh = (const float*)d_in[21];
    const float* gv_wih = (const float*)d_in[22];  const float* gv_whh = (const float*)d_in[23];
    const float* gv_bih = (const float*)d_in[24];  const float* gv_bhh = (const float*)d_in[25];
    const float* ro_w1  = (const float*)d_in[26];  const float* ro_b1  = (const float*)d_in[27];
    const float* ro_w2  = (const float*)d_in[28];  const float* ro_b2  = (const float*)d_in[29];
    const float* ro_w3  = (const float*)d_in[30];  const float* ro_b3  = (const float*)d_in[31];
    float* out = (float*)d_out;

    float *var_h, *fac_h, *nm_var, *nm_fac;
    __nv_bfloat16 *var_hhi, *var_hlo, *fac_hhi, *fac_hlo;
    __nv_bfloat16 *f2v_fhi, *f2v_flo, *v2f_fhi, *v2f_flo;
    unsigned char *wp_f2v, *wp_v2f, *wg_gf, *wg_gv;
    cudaGetSymbolAddress((void**)&var_h,   g_var_h);
    cudaGetSymbolAddress((void**)&fac_h,   g_fac_h);
    cudaGetSymbolAddress((void**)&nm_var,  g_nm_var);
    cudaGetSymbolAddress((void**)&nm_fac,  g_nm_fac);
    cudaGetSymbolAddress((void**)&var_hhi, g_var_hhi);
    cudaGetSymbolAddress((void**)&var_hlo, g_var_hlo);
    cudaGetSymbolAddress((void**)&fac_hhi, g_fac_hhi);
    cudaGetSymbolAddress((void**)&fac_hlo, g_fac_hlo);
    cudaGetSymbolAddress((void**)&f2v_fhi, g_f2v_fhi);
    cudaGetSymbolAddress((void**)&f2v_flo, g_f2v_flo);
    cudaGetSymbolAddress((void**)&v2f_fhi, g_v2f_fhi);
    cudaGetSymbolAddress((void**)&v2f_flo, g_v2f_flo);
    cudaGetSymbolAddress((void**)&wp_f2v,  g_wpack_f2v);
    cudaGetSymbolAddress((void**)&wp_v2f,  g_wpack_v2f);
    cudaGetSymbolAddress((void**)&wg_gf,   g_wgru_gf);
    cudaGetSymbolAddress((void**)&wg_gv,   g_wgru_gv);

    cudaFuncSetAttribute(edge_mma_kernel<0>, cudaFuncAttributeMaxDynamicSharedMemorySize, EDGE_SMEM_BYTES);
    cudaFuncSetAttribute(edge_mma_kernel<1>, cudaFuncAttributeMaxDynamicSharedMemorySize, EDGE_SMEM_BYTES);
    cudaFuncSetAttribute(gru64_kernel,       cudaFuncAttributeMaxDynamicSharedMemorySize, G64_SMEM_BYTES);

    setup_kernel<<<296, 256>>>(
        f2v_w1, f2v_w2, f2v_w3, v2f_w1, v2f_w2, v2f_w3,
        gf_wih, gf_whh, gv_wih, gv_whh, f2v_feat, v2f_feat);

    for (int s = 0; s < 5; s++) {
        edge_mma_kernel<0><<<NE / 64, 256, EDGE_SMEM_BYTES>>>(
            fac_hhi, fac_hlo, var_hhi, var_hlo, f2v_col, f2v_fhi, f2v_flo,
            wp_f2v, f2v_b1, f2v_b2, f2v_b3, nm_var);
        gru64_kernel<<<(NV + 63) / 64, 256, G64_SMEM_BYTES>>>(
            var_h, var_hhi, var_hlo, nm_var, wg_gf, gf_bih, gf_bhh, NV);

        edge_mma_kernel<1><<<NE / 64, 256, EDGE_SMEM_BYTES>>>(
            var_hhi, var_hlo, fac_hhi, fac_hlo, v2f_row, v2f_fhi, v2f_flo,
            wp_v2f, v2f_b1, v2f_b2, v2f_b3, nm_fac);
        gru64_kernel<<<NF / 64, 256, G64_SMEM_BYTES>>>(
            fac_h, fac_hhi, fac_hlo, nm_fac, wg_gv, gv_bih, gv_bhh, NF);
    }

    readout_kernel<<<(NV + 31) / 32, 256>>>(
        var_h, ro_w1, ro_b1, ro_w2, ro_b2, ro_w3, ro_b3, out, NV);
}

// round 14
// speedup vs baseline: 1.3223x; 1.1329x over previous
#include <cuda_runtime.h>
#include <cuda_bf16.h>
#include <cstdint>
#include <math.h>

#define NV 10000
#define NF 80000
#define NE 160000

#define ER 272
#define EA_LO 17408
#define EW_LO128 34816
#define EW_LO64  17408

__device__ float g_var_h[NV * 64];
__device__ float g_fac_h[NF * 64];
__device__ float g_nm_var[NV * 64];
__device__ float g_nm_fac[NF * 64];
__device__ __nv_bfloat16 g_var_hhi[NV * 64];
__device__ __nv_bfloat16 g_var_hlo[NV * 64];
__device__ __nv_bfloat16 g_fac_hhi[NF * 64];
__device__ __nv_bfloat16 g_fac_hlo[NF * 64];
__device__ __nv_bfloat16 g_f2v_fhi[NE * 4];
__device__ __nv_bfloat16 g_f2v_flo[NE * 4];
__device__ __nv_bfloat16 g_v2f_fhi[NE * 4];
__device__ __nv_bfloat16 g_v2f_flo[NE * 4];
__device__ __align__(256) unsigned char g_wpack_f2v[174080];
__device__ __align__(256) unsigned char g_wpack_v2f[174080];
// GRU pack: [Wrz hi 34816][Wrz lo 34816][Wn hi 18432][Wn lo 18432] = 106496
__device__ __align__(256) unsigned char g_wgru_gf[106496];
__device__ __align__(256) unsigned char g_wgru_gv[106496];

__device__ __forceinline__ uint32_t smem_u32(const void* p) {
    uint32_t a;
    asm("{ .reg .u64 t; cvta.to.shared.u64 t, %1; cvt.u32.u64 %0, t; }" : "=r"(a) : "l"(p));
    return a;
}
#define MBARRIER_INIT(mbar, cnt) \
    asm volatile("mbarrier.init.shared.b64 [%0], %1;" :: "r"(mbar), "r"(cnt) : "memory")
#define MBARRIER_EXPECT_TX(mbar, bytes) \
    asm volatile("mbarrier.arrive.expect_tx.shared.b64 _, [%0], %1;" :: "r"(mbar), "r"(bytes) : "memory")
#define MBARRIER_WAIT_PARITY(mbar, ph) do { \
    asm volatile("{\n\t.reg .pred P1;\n\t" \
        "W_%=:\n\tmbarrier.try_wait.parity.acquire.cta.shared::cta.b64 P1, [%0], %1, 0x989680;\n\t" \
        "@P1 bra.uni D_%=;\n\tbra.uni W_%=;\n\tD_%=:\n\t}" \
        :: "r"(mbar), "r"(ph) : "memory"); \
} while (0)

__device__ __forceinline__ void bulk_copy_g2s(uint32_t dst, const void* src,
                                              uint32_t bytes, uint32_t mbar) {
    asm volatile(
        "cp.async.bulk.shared::cluster.global.mbarrier::complete_tx::bytes [%0], [%1], %2, [%3];"
        :: "r"(dst), "l"(src), "r"(bytes), "r"(mbar) : "memory");
}
__device__ __forceinline__ void ldsm4(uint32_t addr, uint32_t* r) {
    asm volatile("ldmatrix.sync.aligned.m8n8.x4.shared.b16 {%0,%1,%2,%3}, [%4];"
        : "=r"(r[0]), "=r"(r[1]), "=r"(r[2]), "=r"(r[3]) : "r"(addr));
}
__device__ __forceinline__ void mma16816(float* d, const uint32_t* a, const uint32_t* b) {
    asm volatile("mma.sync.aligned.m16n8k16.row.col.f32.bf16.bf16.f32 "
        "{%0,%1,%2,%3}, {%4,%5,%6,%7}, {%8,%9}, {%0,%1,%2,%3};"
        : "+f"(d[0]), "+f"(d[1]), "+f"(d[2]), "+f"(d[3])
        : "r"(a[0]), "r"(a[1]), "r"(a[2]), "r"(a[3]), "r"(b[0]), "r"(b[1]));
}
__device__ __forceinline__ void mma16808(float* d, const uint32_t* a, uint32_t b) {
    asm volatile("mma.sync.aligned.m16n8k8.row.col.f32.bf16.bf16.f32 "
        "{%0,%1,%2,%3}, {%4,%5}, {%6}, {%0,%1,%2,%3};"
        : "+f"(d[0]), "+f"(d[1]), "+f"(d[2]), "+f"(d[3])
        : "r"(a[0]), "r"(a[1]), "r"(b));
}

// ---------------- fused setup ----------------
__device__ void dev_pack_w(unsigned char* dst, const float* W, int nrows, int kin,
                           int gt, int gs) {
    const int total = nrows * 136;
    const int plane = nrows * ER;
    for (int i = gt; i < total; i += gs) {
        int n = i / 136, k = i - n * 136;
        float v = (k < kin) ? W[n * kin + k] : 0.0f;
        __nv_bfloat16 hi = __float2bfloat16(v);
        __nv_bfloat16 lo = __float2bfloat16(v - __bfloat162float(hi));
        uint32_t off = (uint32_t)n * ER + (uint32_t)k * 2;
        *(__nv_bfloat16*)(dst + off) = hi;
        *(__nv_bfloat16*)(dst + plane + off) = lo;
    }
}
__device__ void dev_pack_gru(unsigned char* dst, const float* wih, const float* whh,
                             int gt, int gs) {
    for (int i = gt; i < 128 * 136; i += gs) {
        int r = i / 136, k = i - r * 136;
        float v = 0.0f;
        if (k < 64)       v = wih[r * 64 + k];
        else if (k < 128) v = whh[r * 64 + (k - 64)];
        __nv_bfloat16 hi = __float2bfloat16(v);
        __nv_bfloat16 lo = __float2bfloat16(v - __bfloat162float(hi));
        uint32_t off = (uint32_t)r * 272 + (uint32_t)k * 2;
        *(__nv_bfloat16*)(dst + off) = hi;
        *(__nv_bfloat16*)(dst + 34816 + off) = lo;
    }
    for (int i = gt; i < 128 * 72; i += gs) {
        int r = i / 72, k = i - r * 72;
        float v = 0.0f;
        if (k < 64)
            v = (r < 64) ? wih[(128 + r) * 64 + k] : whh[(64 + r) * 64 + k];
        __nv_bfloat16 hi = __float2bfloat16(v);
        __nv_bfloat16 lo = __float2bfloat16(v - __bfloat162float(hi));
        uint32_t off = (uint32_t)r * 144 + (uint32_t)k * 2;
        *(__nv_bfloat16*)(dst + 69632 + off) = hi;
        *(__nv_bfloat16*)(dst + 69632 + 18432 + off) = lo;
    }
}
__device__ void dev_split(__nv_bfloat16* hi_out, __nv_bfloat16* lo_out,
                          const float* src, int n, int gt, int gs) {
    for (int i = gt; i < n; i += gs) {
        float v = src[i];
        __nv_bfloat16 hi = __float2bfloat16(v);
        hi_out[i] = hi;
        lo_out[i] = __float2bfloat16(v - __bfloat162float(hi));
    }
}
__device__ void dev_zero_f(float* p, int n, int gt, int gs) {
    for (int i = gt; i < n; i += gs) p[i] = 0.0f;
}

__global__ __launch_bounds__(256) void setup_kernel(
    const float* __restrict__ f2v_w1, const float* __restrict__ f2v_w2,
    const float* __restrict__ f2v_w3,
    const float* __restrict__ v2f_w1, const float* __restrict__ v2f_w2,
    const float* __restrict__ v2f_w3,
    const float* __restrict__ gf_wih, const float* __restrict__ gf_whh,
    const float* __restrict__ gv_wih, const float* __restrict__ gv_whh,
    const float* __restrict__ f2v_feat, const float* __restrict__ v2f_feat)
{
    const int gt = blockIdx.x * blockDim.x + threadIdx.x;
    const int gs = gridDim.x * blockDim.x;

    dev_pack_w(g_wpack_f2v,          f2v_w1, 128, 136, gt, gs);
    dev_pack_w(g_wpack_f2v + 69632,  f2v_w2, 128, 128, gt, gs);
    dev_pack_w(g_wpack_f2v + 139264, f2v_w3,  64, 128, gt, gs);
    dev_pack_w(g_wpack_v2f,          v2f_w1, 128, 136, gt, gs);
    dev_pack_w(g_wpack_v2f + 69632,  v2f_w2, 128, 128, gt, gs);
    dev_pack_w(g_wpack_v2f + 139264, v2f_w3,  64, 128, gt, gs);
    dev_pack_gru(g_wgru_gf, gf_wih, gf_whh, gt, gs);
    dev_pack_gru(g_wgru_gv, gv_wih, gv_whh, gt, gs);
    dev_split(g_f2v_fhi, g_f2v_flo, f2v_feat, NE * 4, gt, gs);
    dev_split(g_v2f_fhi, g_v2f_flo, v2f_feat, NE * 4, gt, gs);
    dev_zero_f(g_var_h,  NV * 64, gt, gs);
    dev_zero_f(g_fac_h,  NF * 64, gt, gs);
    dev_zero_f(g_nm_var, NV * 64, gt, gs);
    dev_zero_f((float*)g_var_hhi, NV * 32, gt, gs);
    dev_zero_f((float*)g_var_hlo, NV * 32, gt, gs);
    dev_zero_f((float*)g_fac_hhi, NF * 32, gt, gs);
    dev_zero_f((float*)g_fac_hlo, NF * 32, gt, gs);
}

// ---------------- HMMA tile, single stride ----------------
template<int KCH, int NPAIR>
__device__ __forceinline__ void layer_mma_s(
    uint32_t aA, uint32_t aW, uint32_t rstr, uint32_t aLo, uint32_t wLo,
    int lane, int mbase, int nbase, float* acc)
{
    const uint32_t aRow = aA + (uint32_t)(mbase + (lane & 15)) * rstr + ((lane >> 4) << 4);
    const uint32_t bRow = aW + (uint32_t)(nbase + (lane & 7) + ((lane >> 4) << 3)) * rstr
                        + (((lane >> 3) & 1) << 4);
    #pragma unroll
    for (int kc = 0; kc < KCH; kc++) {
        uint32_t ah[8], al[8];
        ldsm4(aRow + kc * 32, ah);
        ldsm4(aRow + 16 * rstr + kc * 32, ah + 4);
        ldsm4(aRow + aLo + kc * 32, al);
        ldsm4(aRow + aLo + 16 * rstr + kc * 32, al + 4);
        #pragma unroll
        for (int np = 0; np < NPAIR; np++) {
            uint32_t bh[4], bl[4];
            ldsm4(bRow + np * 16 * rstr + kc * 32, bh);
            ldsm4(bRow + wLo + np * 16 * rstr + kc * 32, bl);
            #pragma unroll
            for (int m = 0; m < 2; m++) {
                #pragma unroll
                for (int h = 0; h < 2; h++) {
                    float* d = acc + ((m * NPAIR + np) * 2 + h) * 4;
                    mma16816(d, ah + m * 4, bh + h * 2);
                    mma16816(d, ah + m * 4, bl + h * 2);
                    mma16816(d, al + m * 4, bh + h * 2);
                }
            }
        }
    }
}

// ---------------- HMMA tile, separate A/W strides (GRU) --------------------
template<int KCH, int NPAIR>
__device__ __forceinline__ void layer_mma_2s(
    uint32_t aA, uint32_t aStr, uint32_t aLo,
    uint32_t aW, uint32_t wStr, uint32_t wLo,
    int lane, int mbase, int nbase, float* acc)
{
    const uint32_t aRow = aA + (uint32_t)(mbase + (lane & 15)) * aStr + ((lane >> 4) << 4);
    const uint32_t bRow = aW + (uint32_t)(nbase + (lane & 7) + ((lane >> 4) << 3)) * wStr
                        + (((lane >> 3) & 1) << 4);
    #pragma unroll
    for (int kc = 0; kc < KCH; kc++) {
        uint32_t ah[8], al[8];
        ldsm4(aRow + kc * 32, ah);
        ldsm4(aRow + 16 * aStr + kc * 32, ah + 4);
        ldsm4(aRow + aLo + kc * 32, al);
        ldsm4(aRow + aLo + 16 * aStr + kc * 32, al + 4);
        #pragma unroll
        for (int np = 0; np < NPAIR; np++) {
            uint32_t bh[4], bl[4];
            ldsm4(bRow + np * 16 * wStr + kc * 32, bh);
            ldsm4(bRow + wLo + np * 16 * wStr + kc * 32, bl);
            #pragma unroll
            for (int m = 0; m < 2; m++) {
                #pragma unroll
                for (int h = 0; h < 2; h++) {
                    float* d = acc + ((m * NPAIR + np) * 2 + h) * 4;
                    mma16816(d, ah + m * 4, bh + h * 2);
                    mma16816(d, ah + m * 4, bl + h * 2);
                    mma16816(d, al + m * 4, bh + h * 2);
                }
            }
        }
    }
}

__device__ __forceinline__ void layer1_tail(
    uint32_t aA, uint32_t aW, int lane, int mbase, int nbase, float* acc)
{
    const uint32_t aAddr = aA + (uint32_t)(mbase + lane) * ER + 256;
    const uint32_t bAddr = aW + (uint32_t)(nbase + lane) * ER + 256;
    uint32_t ah[4], al[4], bh[4], bl[4];
    ldsm4(aAddr, ah);
    ldsm4(aAddr + EA_LO, al);
    ldsm4(bAddr, bh);
    ldsm4(bAddr + EW_LO128, bl);
    #pragma unroll
    for (int m = 0; m < 2; m++)
        #pragma unroll
        for (int n4 = 0; n4 < 4; n4++) {
            float* d = acc + ((m * 2 + (n4 >> 1)) * 2 + (n4 & 1)) * 4;
            mma16808(d, ah + 2 * m, bh[n4]);
            mma16808(d, ah + 2 * m, bl[n4]);
            mma16808(d, al + 2 * m, bh[n4]);
        }
}

__device__ __forceinline__ void epi12(unsigned char* Ab, const float* bias,
                                      int lane, int mbase, int nbase, const float* acc)
{
    #pragma unroll
    for (int m = 0; m < 2; m++)
        #pragma unroll
        for (int np = 0; np < 2; np++)
            #pragma unroll
            for (int h = 0; h < 2; h++) {
                const float* d = acc + ((m * 2 + np) * 2 + h) * 4;
                int c = nbase + np * 16 + h * 8 + 2 * (lane & 3);
                int r = mbase + m * 16 + (lane >> 2);
                float b0 = bias[c], b1 = bias[c + 1];
                float v0 = fmaxf(d[0] + b0, 0.f), v1 = fmaxf(d[1] + b1, 0.f);
                float v2 = fmaxf(d[2] + b0, 0.f), v3 = fmaxf(d[3] + b1, 0.f);
                __nv_bfloat162 hA = __floats2bfloat162_rn(v0, v1);
                __nv_bfloat162 lA = __floats2bfloat162_rn(v0 - __low2float(hA),
                                                          v1 - __high2float(hA));
                __nv_bfloat162 hB = __floats2bfloat162_rn(v2, v3);
                __nv_bfloat162 lB = __floats2bfloat162_rn(v2 - __low2float(hB),
                                                          v3 - __high2float(hB));
                uint32_t o0 = (uint32_t)r * ER + (uint32_t)c * 2;
                uint32_t o1 = o0 + 8u * ER;
                *(uint32_t*)(Ab + o0)         = *(uint32_t*)&hA;
                *(uint32_t*)(Ab + EA_LO + o0) = *(uint32_t*)&lA;
                *(uint32_t*)(Ab + o1)         = *(uint32_t*)&hB;
                *(uint32_t*)(Ab + EA_LO + o1) = *(uint32_t*)&lB;
            }
}

// ---------------- edge MLP (unchanged) ----------------
#define SM_W    34816
#define SM_IDX  104448
#define SM_BIAS 104960
#define SM_MBW  106240
#define EDGE_SMEM_BYTES 106272
template<int DIR>
__global__ __launch_bounds__(256, 2) void edge_mma_kernel(
    const __nv_bfloat16* __restrict__ Ahi, const __nv_bfloat16* __restrict__ Alo,
    const __nv_bfloat16* __restrict__ Bhi, const __nv_bfloat16* __restrict__ Blo,
    const int* __restrict__ idxArr,
    const __nv_bfloat16* __restrict__ fhi, const __nv_bfloat16* __restrict__ flo,
    const unsigned char* __restrict__ wsrc,
    const float* __restrict__ b1, const float* __restrict__ b2,
    const float* __restrict__ b3,
    float* __restrict__ nm)
{
    extern __shared__ __align__(256) unsigned char sm[];
    const uint32_t smb = smem_u32(sm);
    const int tid = threadIdx.x;
    const int e0 = blockIdx.x * 64;
    const int p0 = e0 >> 1;

    int*   idx    = (int*)(sm + SM_IDX);
    float* bias_s = (float*)(sm + SM_BIAS);
    const uint32_t mbw = smb + SM_MBW;

    if (tid == 0) MBARRIER_INIT(mbw, 1u);
    __syncthreads();
    if (tid == 0) {
        MBARRIER_EXPECT_TX(mbw, 69632u);
        bulk_copy_g2s(smb + SM_W, wsrc, 69632u, mbw);
    }
    if (tid < 64) idx[tid] = idxArr[e0 + tid];
    for (int i = tid; i < 320; i += 256)
        bias_s[i] = (i < 128) ? b1[i] : (i < 256 ? b2[i - 128] : b3[i - 256]);
    __syncthreads();

    {
        int r = tid >> 3, q = tid & 7;
        const __nv_bfloat16* srcH = (DIR == 0) ? Ahi : Bhi;
        const __nv_bfloat16* srcL = (DIR == 0) ? Alo : Blo;
        uint4 hv = *(const uint4*)(srcH + (size_t)(p0 + r) * 64 + q * 8);
        uint4 lv = *(const uint4*)(srcL + (size_t)(p0 + r) * 64 + q * 8);
        uint32_t cb = (DIR == 0) ? 0u : 128u;
        uint32_t o0 = (uint32_t)(2 * r)     * ER + cb + q * 16;
        uint32_t o1 = (uint32_t)(2 * r + 1) * ER + cb + q * 16;
        *(uint4*)(sm + o0)         = hv;  *(uint4*)(sm + o1)         = hv;
        *(uint4*)(sm + EA_LO + o0) = lv;  *(uint4*)(sm + EA_LO + o1) = lv;
    }
    for (int i = tid; i < 512; i += 256) {
        int e = i >> 3, q = i & 7;
        int s = idx[e];
        const __nv_bfloat16* srcH = (DIR == 0) ? Bhi : Ahi;
        const __nv_bfloat16* srcL = (DIR == 0) ? Blo : Alo;
        uint4 hv = *(const uint4*)(srcH + (size_t)s * 64 + q * 8);
        uint4 lv = *(const uint4*)(srcL + (size_t)s * 64 + q * 8);
        uint32_t cb = (DIR == 0) ? 128u : 0u;
        uint32_t o = (uint32_t)e * ER + cb + q * 16;
        *(uint4*)(sm + o)         = hv;
        *(uint4*)(sm + EA_LO + o) = lv;
    }
    if (tid < 64) {
        int e = tid;
        int rowIdx = (DIR == 0) ? (p0 + (e >> 1)) : idx[e];
        int colIdx = (DIR == 0) ? idx[e] : (p0 + (e >> 1));
        uint2 rh = *(const uint2*)(fhi + (size_t)rowIdx * 4);
        uint2 ch = *(const uint2*)(fhi + (size_t)colIdx * 4);
        uint2 rl = *(const uint2*)(flo + (size_t)rowIdx * 4);
        uint2 cl = *(const uint2*)(flo + (size_t)colIdx * 4);
        uint32_t o = (uint32_t)e * ER + 256;
        *(uint4*)(sm + o)         = make_uint4(rh.x, rh.y, ch.x, ch.y);
        *(uint4*)(sm + EA_LO + o) = make_uint4(rl.x, rl.y, cl.x, cl.y);
    }
    __syncthreads();

    const int w = tid >> 5, lane = tid & 31;
    const int mbase = (w & 1) * 32;
    const int nb32  = (w >> 1) * 32;
    const int nb16  = (w >> 1) * 16;
    float acc[32];

    MBARRIER_WAIT_PARITY(mbw, 0);
    #pragma unroll
    for (int i = 0; i < 32; i++) acc[i] = 0.f;
    layer_mma_s<8, 2>(smb, smb + SM_W, ER, EA_LO, EW_LO128, lane, mbase, nb32, acc);
    layer1_tail(smb, smb + SM_W, lane, mbase, nb32, acc);
    __syncthreads();
    if (tid == 0) {
        MBARRIER_EXPECT_TX(mbw, 69632u);
        bulk_copy_g2s(smb + SM_W, wsrc + 69632, 69632u, mbw);
    }
    epi12(sm, bias_s, lane, mbase, nb32, acc);
    __syncthreads();

    MBARRIER_WAIT_PARITY(mbw, 1);
    #pragma unroll
    for (int i = 0; i < 32; i++) acc[i] = 0.f;
    layer_mma_s<8, 2>(smb, smb + SM_W, ER, EA_LO, EW_LO128, lane, mbase, nb32, acc);
    __syncthreads();
    if (tid == 0) {
        MBARRIER_EXPECT_TX(mbw, 34816u);
        bulk_copy_g2s(smb + SM_W, wsrc + 139264, 34816u, mbw);
    }
    epi12(sm, bias_s + 128, lane, mbase, nb32, acc);
    __syncthreads();

    MBARRIER_WAIT_PARITY(mbw, 0);
    #pragma unroll
    for (int i = 0; i < 16; i++) acc[i] = 0.f;
    layer_mma_s<8, 1>(smb, smb + SM_W, ER, EA_LO, EW_LO64, lane, mbase, nb16, acc);

    if (DIR == 0) {
        #pragma unroll
        for (int m = 0; m < 2; m++)
            #pragma unroll
            for (int h = 0; h < 2; h++) {
                const float* d = acc + (m * 2 + h) * 4;
                int c = nb16 + h * 8 + 2 * (lane & 3);
                int r = mbase + m * 16 + (lane >> 2);
                float b0 = bias_s[256 + c], b1v = bias_s[256 + c + 1];
                float* q0 = nm + (size_t)idx[r] * 64 + c;
                float* q1 = nm + (size_t)idx[r + 8] * 64 + c;
                atomicAdd(q0,     d[0] + b0);
                atomicAdd(q0 + 1, d[1] + b1v);
                atomicAdd(q1,     d[2] + b0);
                atomicAdd(q1 + 1, d[3] + b1v);
            }
    } else {
        __syncthreads();
        float* st = (float*)sm;
        #pragma unroll
        for (int m = 0; m < 2; m++)
            #pragma unroll
            for (int h = 0; h < 2; h++) {
                const float* d = acc + (m * 2 + h) * 4;
                int c = nb16 + h * 8 + 2 * (lane & 3);
                int r = mbase + m * 16 + (lane >> 2);
                float b0 = bias_s[256 + c], b1v = bias_s[256 + c + 1];
                st[r * 68 + c]           = d[0] + b0;
                st[r * 68 + c + 1]       = d[1] + b1v;
                st[(r + 8) * 68 + c]     = d[2] + b0;
                st[(r + 8) * 68 + c + 1] = d[3] + b1v;
            }
        __syncthreads();
        for (int i = tid; i < 2048; i += 256) {
            int r = i >> 6, c = i & 63;
            nm[(size_t)(p0 + r) * 64 + c] = st[(2 * r) * 68 + c] + st[(2 * r + 1) * 68 + c];
        }
    }
}

// ---------------- GRU-64 (unchanged) ----------------
#define G64_W    34816
#define G64_BIAS 104448
#define G64_MBW  105472
#define G64_SMEM_BYTES 105504
__global__ __launch_bounds__(256, 2) void gru64_kernel(
    float* __restrict__ h,
    __nv_bfloat16* __restrict__ h_hi, __nv_bfloat16* __restrict__ h_lo,
    float* __restrict__ x,
    const unsigned char* __restrict__ wsrc,
    const float* __restrict__ bih, const float* __restrict__ bhh,
    int nrows)
{
    extern __shared__ __align__(256) unsigned char sm[];
    const uint32_t smb = smem_u32(sm);
    const int tid = threadIdx.x;
    const int r0 = blockIdx.x * 64;

    float* bias_s = (float*)(sm + G64_BIAS);
    const uint32_t mbw = smb + G64_MBW;

    if (tid == 0) MBARRIER_INIT(mbw, 1u);
    __syncthreads();
    if (tid == 0) {
        MBARRIER_EXPECT_TX(mbw, 69632u);
        bulk_copy_g2s(smb + G64_W, wsrc, 69632u, mbw);
    }
    {
        int i = tid;
        float v;
        if (i < 128)      v = bih[i] + bhh[i];
        else if (i < 192) v = bih[i];
        else              v = bhh[i - 64];
        bias_s[i & 255] = v;
    }

    for (int i = tid; i < 64 * 32; i += 256) {
        int e = i >> 5, q = i & 31;
        int rr = r0 + e;
        int rc = rr < nrows ? rr : nrows - 1;
        float4 xv;
        if (q < 16) {
            xv = *(const float4*)(x + (size_t)rc * 64 + q * 4);
            if (rr < nrows) *(float4*)(x + (size_t)rc * 64 + q * 4) = make_float4(0.f, 0.f, 0.f, 0.f);
        } else {
            xv = *(const float4*)(h + (size_t)rc * 64 + (q - 16) * 4);
        }
        __nv_bfloat162 h01 = __floats2bfloat162_rn(xv.x, xv.y);
        __nv_bfloat162 h23 = __floats2bfloat162_rn(xv.z, xv.w);
        __nv_bfloat162 l01 = __floats2bfloat162_rn(xv.x - __low2float(h01), xv.y - __high2float(h01));
        __nv_bfloat162 l23 = __floats2bfloat162_rn(xv.z - __low2float(h23), xv.w - __high2float(h23));
        uint32_t off = (uint32_t)e * ER + (uint32_t)q * 8;
        *(uint2*)(sm + off)         = make_uint2(*(uint32_t*)&h01, *(uint32_t*)&h23);
        *(uint2*)(sm + EA_LO + off) = make_uint2(*(uint32_t*)&l01, *(uint32_t*)&l23);
    }
    __syncthreads();

    const int w = tid >> 5, lane = tid & 31;
    const int mbase = (w & 1) * 32;
    const int nb32  = (w >> 1) * 32;
    float acc1[32], acc2[32];
    #pragma unroll
    for (int i = 0; i < 32; i++) { acc1[i] = 0.f; acc2[i] = 0.f; }

    MBARRIER_WAIT_PARITY(mbw, 0);
    layer_mma_2s<8, 2>(smb, ER, EA_LO, smb + G64_W, ER, 34816, lane, mbase, nb32, acc1);
    __syncthreads();
    if (tid == 0) {
        MBARRIER_EXPECT_TX(mbw, 36864u);
        bulk_copy_g2s(smb + G64_W, wsrc + 69632, 36864u, mbw);
    }
    MBARRIER_WAIT_PARITY(mbw, 1);
    {
        uint32_t aOff = (nb32 >= 64) ? 128u : 0u;
        int nbW = nb32 & 63;
        int wBase = (nb32 >= 64) ? 64 : 0;
        layer_mma_2s<4, 2>(smb + aOff, ER, EA_LO,
                           smb + G64_W, 144, 18432, lane, mbase, wBase + nbW, acc2);
    }
    __syncthreads();

    float* gs = (float*)sm;
    #pragma unroll
    for (int m = 0; m < 2; m++)
        #pragma unroll
        for (int np = 0; np < 2; np++)
            #pragma unroll
            for (int hh = 0; hh < 2; hh++) {
                int c = nb32 + np * 16 + hh * 8 + 2 * (lane & 3);
                int r = mbase + m * 16 + (lane >> 2);
                const float* d1 = acc1 + ((m * 2 + np) * 2 + hh) * 4;
                const float* d2 = acc2 + ((m * 2 + np) * 2 + hh) * 4;
                gs[r * 256 + c]                 = d1[0];
                gs[r * 256 + c + 1]             = d1[1];
                gs[(r + 8) * 256 + c]           = d1[2];
                gs[(r + 8) * 256 + c + 1]       = d1[3];
                gs[r * 256 + 128 + c]           = d2[0];
                gs[r * 256 + 128 + c + 1]       = d2[1];
                gs[(r + 8) * 256 + 128 + c]     = d2[2];
                gs[(r + 8) * 256 + 128 + c + 1] = d2[3];
            }
    __syncthreads();

    for (int i = tid; i < 64 * 64; i += 256) {
        int e = i >> 6, d = i & 63;
        int r = r0 + e;
        if (r >= nrows) continue;
        const float* g = gs + e * 256;
        float pr = g[d]       + bias_s[d];
        float pz = g[64 + d]  + bias_s[64 + d];
        float in = g[128 + d] + bias_s[128 + d];
        float hn = g[192 + d] + bias_s[192 + d];
        float rr = 1.f / (1.f + expf(-pr));
        float zz = 1.f / (1.f + expf(-pz));
        float nn = tanhf(in + rr * hn);
        float hv = h[(size_t)r * 64 + d];
        float hnew = (1.f - zz) * nn + zz * hv;
        h[(size_t)r * 64 + d] = hnew;
        __nv_bfloat16 hb = __float2bfloat16(hnew);
        h_hi[(size_t)r * 64 + d] = hb;
        h_lo[(size_t)r * 64 + d] = __float2bfloat16(hnew - __bfloat162float(hb));
    }
}

// ---------------- readout (unchanged) ----------------
__global__ __launch_bounds__(256) void readout_kernel(
    const float* __restrict__ h,
    const float* __restrict__ W1, const float* __restrict__ b1,
    const float* __restrict__ W2, const float* __restrict__ b2,
    const float* __restrict__ W3, const float* __restrict__ b3,
    float* __restrict__ out, int nrows)
{
    __shared__ float hs[32 * 68];
    __shared__ float l1s[32 * 132];
    __shared__ float l2s[32 * 132];
    __shared__ float lg[64];

    const int tid = threadIdx.x;
    const int r0  = blockIdx.x * 32;

    for (int i = tid; i < 32 * 64; i += 256) {
        int e = i >> 6, k = i & 63;
        int r = r0 + e;
        hs[e * 68 + k] = (r < nrows) ? h[(size_t)r * 64 + k] : 0.f;
    }
    __syncthreads();

    const int warp = tid >> 5, lane = tid & 31;
    #pragma unroll
    for (int jc = 0; jc < 4; jc++) {
        const int j0 = warp * 16 + jc * 4;
        float a[4] = {0.f, 0.f, 0.f, 0.f};
        #pragma unroll
        for (int k = 0; k < 64; k += 4) {
            float4 xv = *(const float4*)(hs + lane * 68 + k);
            #pragma unroll
            for (int jj = 0; jj < 4; jj++) {
                float4 wv = *(const float4*)(W1 + (size_t)(j0 + jj) * 64 + k);
                a[jj] += wv.x * xv.x + wv.y * xv.y + wv.z * xv.z + wv.w * xv.w;
            }
        }
        #pragma unroll
        for (int jj = 0; jj < 4; jj++)
            l1s[lane * 132 + j0 + jj] = fmaxf(a[jj] + b1[j0 + jj], 0.f);
    }
    __syncthreads();
    #pragma unroll
    for (int jc = 0; jc < 4; jc++) {
        const int j0 = warp * 16 + jc * 4;
        float a[4] = {0.f, 0.f, 0.f, 0.f};
        #pragma unroll 2
        for (int k = 0; k < 128; k += 4) {
            float4 xv = *(const float4*)(l1s + lane * 132 + k);
            #pragma unroll
            for (int jj = 0; jj < 4; jj++) {
                float4 wv = *(const float4*)(W2 + (size_t)(j0 + jj) * 128 + k);
                a[jj] += wv.x * xv.x + wv.y * xv.y + wv.z * xv.z + wv.w * xv.w;
            }
        }
        #pragma unroll
        for (int jj = 0; jj < 4; jj++)
            l2s[lane * 132 + j0 + jj] = fmaxf(a[jj] + b2[j0 + jj], 0.f);
    }
    __syncthreads();
    if (tid < 64) {
        int e = tid >> 1, j = tid & 1;
        float a = 0.f;
        #pragma unroll 4
        for (int k = 0; k < 128; k += 4) {
            float4 xv = *(const float4*)(l2s + e * 132 + k);
            float4 wv = *(const float4*)(W3 + (size_t)j * 128 + k);
            a += wv.x * xv.x + wv.y * xv.y + wv.z * xv.z + wv.w * xv.w;
        }
        lg[e * 2 + j] = a + b3[j];
    }
    __syncthreads();
    if (tid < 64) {
        int e = tid >> 1, j = tid & 1;
        int r = r0 + e;
        if (r < nrows) {
            float self  = lg[e * 2 + j];
            float other = lg[e * 2 + (j ^ 1)];
            out[(size_t)r * 2 + j] = 1.f / (1.f + expf(other - self));
        }
    }
}

extern "C" void kernel_launch(void* const* d_in, const int* in_sizes, int n_in,
                              void* d_out, int out_size)
{
    const int*   f2v_col  = (const int*)d_in[1];
    const int*   v2f_row  = (const int*)d_in[2];
    const float* f2v_feat = (const float*)d_in[4];
    const float* v2f_feat = (const float*)d_in[5];
    const float* f2v_w1 = (const float*)d_in[6];   const float* f2v_b1 = (const float*)d_in[7];
    const float* f2v_w2 = (const float*)d_in[8];   const float* f2v_b2 = (const float*)d_in[9];
    const float* f2v_w3 = (const float*)d_in[10];  const float* f2v_b3 = (const float*)d_in[11];
    const float* v2f_w1 = (const float*)d_in[12];  const float* v2f_b1 = (const float*)d_in[13];
    const float* v2f_w2 = (const float*)d_in[14];  const float* v2f_b2 = (const float*)d_in[15];
    const float* v2f_w3 = (const float*)d_in[16];  const float* v2f_b3 = (const float*)d_in[17];
    const float* gf_wih = (const float*)d_in[18];  const float* gf_whh = (const float*)d_in[19];
    const float* gf_bih = (const float*)d_in[20];  const float* gf_bhh = (const float*)d_in[21];
    const float* gv_wih = (const float*)d_in[22];  const float* gv_whh = (const float*)d_in[23];
    const float* gv_bih = (const float*)d_in[24];  const float* gv_bhh = (const float*)d_in[25];
    const float* ro_w1  = (const float*)d_in[26];  const float* ro_b1  = (const float*)d_in[27];
    const float* ro_w2  = (const float*)d_in[28];  const float* ro_b2  = (const float*)d_in[29];
    const float* ro_w3  = (const float*)d_in[30];  const float* ro_b3  = (const float*)d_in[31];
    float* out = (float*)d_out;

    float *var_h, *fac_h, *nm_var, *nm_fac;
    __nv_bfloat16 *var_hhi, *var_hlo, *fac_hhi, *fac_hlo;
    __nv_bfloat16 *f2v_fhi, *f2v_flo, *v2f_fhi, *v2f_flo;
    unsigned char *wp_f2v, *wp_v2f, *wg_gf, *wg_gv;
    cudaGetSymbolAddress((void**)&var_h,   g_var_h);
    cudaGetSymbolAddress((void**)&fac_h,   g_fac_h);
    cudaGetSymbolAddress((void**)&nm_var,  g_nm_var);
    cudaGetSymbolAddress((void**)&nm_fac,  g_nm_fac);
    cudaGetSymbolAddress((void**)&var_hhi, g_var_hhi);
    cudaGetSymbolAddress((void**)&var_hlo, g_var_hlo);
    cudaGetSymbolAddress((void**)&fac_hhi, g_fac_hhi);
    cudaGetSymbolAddress((void**)&fac_hlo, g_fac_hlo);
    cudaGetSymbolAddress((void**)&f2v_fhi, g_f2v_fhi);
    cudaGetSymbolAddress((void**)&f2v_flo, g_f2v_flo);
    cudaGetSymbolAddress((void**)&v2f_fhi, g_v2f_fhi);
    cudaGetSymbolAddress((void**)&v2f_flo, g_v2f_flo);
    cudaGetSymbolAddress((void**)&wp_f2v,  g_wpack_f2v);
    cudaGetSymbolAddress((void**)&wp_v2f,  g_wpack_v2f);
    cudaGetSymbolAddress((void**)&wg_gf,   g_wgru_gf);
    cudaGetSymbolAddress((void**)&wg_gv,   g_wgru_gv);

    cudaFuncSetAttribute(edge_mma_kernel<0>, cudaFuncAttributeMaxDynamicSharedMemorySize, EDGE_SMEM_BYTES);
    cudaFuncSetAttribute(edge_mma_kernel<1>, cudaFuncAttributeMaxDynamicSharedMemorySize, EDGE_SMEM_BYTES);
    cudaFuncSetAttribute(gru64_kernel,       cudaFuncAttributeMaxDynamicSharedMemorySize, G64_SMEM_BYTES);

    setup_kernel<<<296, 256>>>(
        f2v_w1, f2v_w2, f2v_w3, v2f_w1, v2f_w2, v2f_w3,
        gf_wih, gf_whh, gv_wih, gv_whh, f2v_feat, v2f_feat);

    // 5 full var updates; fac updated only 4 times (step-5 fac result is dead:
    // the readout consumes var_h only).
    for (int s = 0; s < 5; s++) {
        edge_mma_kernel<0><<<NE / 64, 256, EDGE_SMEM_BYTES>>>(
            fac_hhi, fac_hlo, var_hhi, var_hlo, f2v_col, f2v_fhi, f2v_flo,
            wp_f2v, f2v_b1, f2v_b2, f2v_b3, nm_var);
        gru64_kernel<<<(NV + 63) / 64, 256, G64_SMEM_BYTES>>>(
            var_h, var_hhi, var_hlo, nm_var, wg_gf, gf_bih, gf_bhh, NV);

        if (s < 4) {
            edge_mma_kernel<1><<<NE / 64, 256, EDGE_SMEM_BYTES>>>(
                var_hhi, var_hlo, fac_hhi, fac_hlo, v2f_row, v2f_fhi, v2f_flo,
                wp_v2f, v2f_b1, v2f_b2, v2f_b3, nm_fac);
            gru64_kernel<<<NF / 64, 256, G64_SMEM_BYTES>>>(
                fac_h, fac_hhi, fac_hlo, nm_fac, wg_gv, gv_bih, gv_bhh, NF);
        }
    }

    readout_kernel<<<(NV + 31) / 32, 256>>>(
        var_h, ro_w1, ro_b1, ro_w2, ro_b2, ro_w3, ro_b3, out, NV);
}

// round 15
// speedup vs baseline: 1.4369x; 1.0867x over previous
#include <cuda_runtime.h>
#include <cuda_bf16.h>
#include <cstdint>
#include <math.h>

#define NV 10000
#define NF 80000
#define NE 160000

#define ER 272
#define EA_LO 17408
#define EW_LO128 34816
#define EW_LO64  17408

__device__ float g_var_h[NV * 64];
__device__ float g_fac_h[NF * 64];
__device__ float g_nm_var[NV * 64];
__device__ __nv_bfloat16 g_var_hhi[NV * 64];
__device__ __nv_bfloat16 g_var_hlo[NV * 64];
__device__ __nv_bfloat16 g_fac_hhi[NF * 64];
__device__ __nv_bfloat16 g_fac_hlo[NF * 64];
__device__ __nv_bfloat16 g_f2v_fhi[NE * 4];
__device__ __nv_bfloat16 g_f2v_flo[NE * 4];
__device__ __nv_bfloat16 g_v2f_fhi[NE * 4];
__device__ __nv_bfloat16 g_v2f_flo[NE * 4];
__device__ __align__(256) unsigned char g_wpack_f2v[174080];
__device__ __align__(256) unsigned char g_wpack_v2f[174080];
// GRU pack: [Wrz hi 34816][Wrz lo 34816][Wn hi 18432][Wn lo 18432] = 106496
__device__ __align__(256) unsigned char g_wgru_gf[106496];
__device__ __align__(256) unsigned char g_wgru_gv[106496];

__device__ __forceinline__ uint32_t smem_u32(const void* p) {
    uint32_t a;
    asm("{ .reg .u64 t; cvta.to.shared.u64 t, %1; cvt.u32.u64 %0, t; }" : "=r"(a) : "l"(p));
    return a;
}
#define MBARRIER_INIT(mbar, cnt) \
    asm volatile("mbarrier.init.shared.b64 [%0], %1;" :: "r"(mbar), "r"(cnt) : "memory")
#define MBARRIER_EXPECT_TX(mbar, bytes) \
    asm volatile("mbarrier.arrive.expect_tx.shared.b64 _, [%0], %1;" :: "r"(mbar), "r"(bytes) : "memory")
#define MBARRIER_WAIT_PARITY(mbar, ph) do { \
    asm volatile("{\n\t.reg .pred P1;\n\t" \
        "W_%=:\n\tmbarrier.try_wait.parity.acquire.cta.shared::cta.b64 P1, [%0], %1, 0x989680;\n\t" \
        "@P1 bra.uni D_%=;\n\tbra.uni W_%=;\n\tD_%=:\n\t}" \
        :: "r"(mbar), "r"(ph) : "memory"); \
} while (0)

__device__ __forceinline__ void bulk_copy_g2s(uint32_t dst, const void* src,
                                              uint32_t bytes, uint32_t mbar) {
    asm volatile(
        "cp.async.bulk.shared::cluster.global.mbarrier::complete_tx::bytes [%0], [%1], %2, [%3];"
        :: "r"(dst), "l"(src), "r"(bytes), "r"(mbar) : "memory");
}
__device__ __forceinline__ void ldsm4(uint32_t addr, uint32_t* r) {
    asm volatile("ldmatrix.sync.aligned.m8n8.x4.shared.b16 {%0,%1,%2,%3}, [%4];"
        : "=r"(r[0]), "=r"(r[1]), "=r"(r[2]), "=r"(r[3]) : "r"(addr));
}
__device__ __forceinline__ void mma16816(float* d, const uint32_t* a, const uint32_t* b) {
    asm volatile("mma.sync.aligned.m16n8k16.row.col.f32.bf16.bf16.f32 "
        "{%0,%1,%2,%3}, {%4,%5,%6,%7}, {%8,%9}, {%0,%1,%2,%3};"
        : "+f"(d[0]), "+f"(d[1]), "+f"(d[2]), "+f"(d[3])
        : "r"(a[0]), "r"(a[1]), "r"(a[2]), "r"(a[3]), "r"(b[0]), "r"(b[1]));
}
__device__ __forceinline__ void mma16808(float* d, const uint32_t* a, uint32_t b) {
    asm volatile("mma.sync.aligned.m16n8k8.row.col.f32.bf16.bf16.f32 "
        "{%0,%1,%2,%3}, {%4,%5}, {%6}, {%0,%1,%2,%3};"
        : "+f"(d[0]), "+f"(d[1]), "+f"(d[2]), "+f"(d[3])
        : "r"(a[0]), "r"(a[1]), "r"(b));
}

// ---------------- fused setup ----------------
__device__ void dev_pack_w(unsigned char* dst, const float* W, int nrows, int kin,
                           int gt, int gs) {
    const int total = nrows * 136;
    const int plane = nrows * ER;
    for (int i = gt; i < total; i += gs) {
        int n = i / 136, k = i - n * 136;
        float v = (k < kin) ? W[n * kin + k] : 0.0f;
        __nv_bfloat16 hi = __float2bfloat16(v);
        __nv_bfloat16 lo = __float2bfloat16(v - __bfloat162float(hi));
        uint32_t off = (uint32_t)n * ER + (uint32_t)k * 2;
        *(__nv_bfloat16*)(dst + off) = hi;
        *(__nv_bfloat16*)(dst + plane + off) = lo;
    }
}
__device__ void dev_pack_gru(unsigned char* dst, const float* wih, const float* whh,
                             int gt, int gs) {
    for (int i = gt; i < 128 * 136; i += gs) {
        int r = i / 136, k = i - r * 136;
        float v = 0.0f;
        if (k < 64)       v = wih[r * 64 + k];
        else if (k < 128) v = whh[r * 64 + (k - 64)];
        __nv_bfloat16 hi = __float2bfloat16(v);
        __nv_bfloat16 lo = __float2bfloat16(v - __bfloat162float(hi));
        uint32_t off = (uint32_t)r * 272 + (uint32_t)k * 2;
        *(__nv_bfloat16*)(dst + off) = hi;
        *(__nv_bfloat16*)(dst + 34816 + off) = lo;
    }
    for (int i = gt; i < 128 * 72; i += gs) {
        int r = i / 72, k = i - r * 72;
        float v = 0.0f;
        if (k < 64)
            v = (r < 64) ? wih[(128 + r) * 64 + k] : whh[(64 + r) * 64 + k];
        __nv_bfloat16 hi = __float2bfloat16(v);
        __nv_bfloat16 lo = __float2bfloat16(v - __bfloat162float(hi));
        uint32_t off = (uint32_t)r * 144 + (uint32_t)k * 2;
        *(__nv_bfloat16*)(dst + 69632 + off) = hi;
        *(__nv_bfloat16*)(dst + 69632 + 18432 + off) = lo;
    }
}
__device__ void dev_split(__nv_bfloat16* hi_out, __nv_bfloat16* lo_out,
                          const float* src, int n, int gt, int gs) {
    for (int i = gt; i < n; i += gs) {
        float v = src[i];
        __nv_bfloat16 hi = __float2bfloat16(v);
        hi_out[i] = hi;
        lo_out[i] = __float2bfloat16(v - __bfloat162float(hi));
    }
}
__device__ void dev_zero_f(float* p, int n, int gt, int gs) {
    for (int i = gt; i < n; i += gs) p[i] = 0.0f;
}

__global__ __launch_bounds__(256) void setup_kernel(
    const float* __restrict__ f2v_w1, const float* __restrict__ f2v_w2,
    const float* __restrict__ f2v_w3,
    const float* __restrict__ v2f_w1, const float* __restrict__ v2f_w2,
    const float* __restrict__ v2f_w3,
    const float* __restrict__ gf_wih, const float* __restrict__ gf_whh,
    const float* __restrict__ gv_wih, const float* __restrict__ gv_whh,
    const float* __restrict__ f2v_feat, const float* __restrict__ v2f_feat)
{
    const int gt = blockIdx.x * blockDim.x + threadIdx.x;
    const int gs = gridDim.x * blockDim.x;

    dev_pack_w(g_wpack_f2v,          f2v_w1, 128, 136, gt, gs);
    dev_pack_w(g_wpack_f2v + 69632,  f2v_w2, 128, 128, gt, gs);
    dev_pack_w(g_wpack_f2v + 139264, f2v_w3,  64, 128, gt, gs);
    dev_pack_w(g_wpack_v2f,          v2f_w1, 128, 136, gt, gs);
    dev_pack_w(g_wpack_v2f + 69632,  v2f_w2, 128, 128, gt, gs);
    dev_pack_w(g_wpack_v2f + 139264, v2f_w3,  64, 128, gt, gs);
    dev_pack_gru(g_wgru_gf, gf_wih, gf_whh, gt, gs);
    dev_pack_gru(g_wgru_gv, gv_wih, gv_whh, gt, gs);
    dev_split(g_f2v_fhi, g_f2v_flo, f2v_feat, NE * 4, gt, gs);
    dev_split(g_v2f_fhi, g_v2f_flo, v2f_feat, NE * 4, gt, gs);
    dev_zero_f(g_var_h,  NV * 64, gt, gs);
    dev_zero_f(g_fac_h,  NF * 64, gt, gs);
    dev_zero_f(g_nm_var, NV * 64, gt, gs);
    dev_zero_f((float*)g_var_hhi, NV * 32, gt, gs);
    dev_zero_f((float*)g_var_hlo, NV * 32, gt, gs);
    dev_zero_f((float*)g_fac_hhi, NF * 32, gt, gs);
    dev_zero_f((float*)g_fac_hlo, NF * 32, gt, gs);
}

// ---------------- HMMA tiles ----------------
template<int KCH, int NPAIR>
__device__ __forceinline__ void layer_mma_s(
    uint32_t aA, uint32_t aW, uint32_t rstr, uint32_t aLo, uint32_t wLo,
    int lane, int mbase, int nbase, float* acc)
{
    const uint32_t aRow = aA + (uint32_t)(mbase + (lane & 15)) * rstr + ((lane >> 4) << 4);
    const uint32_t bRow = aW + (uint32_t)(nbase + (lane & 7) + ((lane >> 4) << 3)) * rstr
                        + (((lane >> 3) & 1) << 4);
    #pragma unroll
    for (int kc = 0; kc < KCH; kc++) {
        uint32_t ah[8], al[8];
        ldsm4(aRow + kc * 32, ah);
        ldsm4(aRow + 16 * rstr + kc * 32, ah + 4);
        ldsm4(aRow + aLo + kc * 32, al);
        ldsm4(aRow + aLo + 16 * rstr + kc * 32, al + 4);
        #pragma unroll
        for (int np = 0; np < NPAIR; np++) {
            uint32_t bh[4], bl[4];
            ldsm4(bRow + np * 16 * rstr + kc * 32, bh);
            ldsm4(bRow + wLo + np * 16 * rstr + kc * 32, bl);
            #pragma unroll
            for (int m = 0; m < 2; m++) {
                #pragma unroll
                for (int h = 0; h < 2; h++) {
                    float* d = acc + ((m * NPAIR + np) * 2 + h) * 4;
                    mma16816(d, ah + m * 4, bh + h * 2);
                    mma16816(d, ah + m * 4, bl + h * 2);
                    mma16816(d, al + m * 4, bh + h * 2);
                }
            }
        }
    }
}

template<int KCH, int NPAIR>
__device__ __forceinline__ void layer_mma_2s(
    uint32_t aA, uint32_t aStr, uint32_t aLo,
    uint32_t aW, uint32_t wStr, uint32_t wLo,
    int lane, int mbase, int nbase, float* acc)
{
    const uint32_t aRow = aA + (uint32_t)(mbase + (lane & 15)) * aStr + ((lane >> 4) << 4);
    const uint32_t bRow = aW + (uint32_t)(nbase + (lane & 7) + ((lane >> 4) << 3)) * wStr
                        + (((lane >> 3) & 1) << 4);
    #pragma unroll
    for (int kc = 0; kc < KCH; kc++) {
        uint32_t ah[8], al[8];
        ldsm4(aRow + kc * 32, ah);
        ldsm4(aRow + 16 * aStr + kc * 32, ah + 4);
        ldsm4(aRow + aLo + kc * 32, al);
        ldsm4(aRow + aLo + 16 * aStr + kc * 32, al + 4);
        #pragma unroll
        for (int np = 0; np < NPAIR; np++) {
            uint32_t bh[4], bl[4];
            ldsm4(bRow + np * 16 * wStr + kc * 32, bh);
            ldsm4(bRow + wLo + np * 16 * wStr + kc * 32, bl);
            #pragma unroll
            for (int m = 0; m < 2; m++) {
                #pragma unroll
                for (int h = 0; h < 2; h++) {
                    float* d = acc + ((m * NPAIR + np) * 2 + h) * 4;
                    mma16816(d, ah + m * 4, bh + h * 2);
                    mma16816(d, ah + m * 4, bl + h * 2);
                    mma16816(d, al + m * 4, bh + h * 2);
                }
            }
        }
    }
}

__device__ __forceinline__ void layer1_tail(
    uint32_t aA, uint32_t aW, int lane, int mbase, int nbase, float* acc)
{
    const uint32_t aAddr = aA + (uint32_t)(mbase + lane) * ER + 256;
    const uint32_t bAddr = aW + (uint32_t)(nbase + lane) * ER + 256;
    uint32_t ah[4], al[4], bh[4], bl[4];
    ldsm4(aAddr, ah);
    ldsm4(aAddr + EA_LO, al);
    ldsm4(bAddr, bh);
    ldsm4(bAddr + EW_LO128, bl);
    #pragma unroll
    for (int m = 0; m < 2; m++)
        #pragma unroll
        for (int n4 = 0; n4 < 4; n4++) {
            float* d = acc + ((m * 2 + (n4 >> 1)) * 2 + (n4 & 1)) * 4;
            mma16808(d, ah + 2 * m, bh[n4]);
            mma16808(d, ah + 2 * m, bl[n4]);
            mma16808(d, al + 2 * m, bh[n4]);
        }
}

__device__ __forceinline__ void epi12(unsigned char* Ab, const float* bias,
                                      int lane, int mbase, int nbase, const float* acc)
{
    #pragma unroll
    for (int m = 0; m < 2; m++)
        #pragma unroll
        for (int np = 0; np < 2; np++)
            #pragma unroll
            for (int h = 0; h < 2; h++) {
                const float* d = acc + ((m * 2 + np) * 2 + h) * 4;
                int c = nbase + np * 16 + h * 8 + 2 * (lane & 3);
                int r = mbase + m * 16 + (lane >> 2);
                float b0 = bias[c], b1 = bias[c + 1];
                float v0 = fmaxf(d[0] + b0, 0.f), v1 = fmaxf(d[1] + b1, 0.f);
                float v2 = fmaxf(d[2] + b0, 0.f), v3 = fmaxf(d[3] + b1, 0.f);
                __nv_bfloat162 hA = __floats2bfloat162_rn(v0, v1);
                __nv_bfloat162 lA = __floats2bfloat162_rn(v0 - __low2float(hA),
                                                          v1 - __high2float(hA));
                __nv_bfloat162 hB = __floats2bfloat162_rn(v2, v3);
                __nv_bfloat162 lB = __floats2bfloat162_rn(v2 - __low2float(hB),
                                                          v3 - __high2float(hB));
                uint32_t o0 = (uint32_t)r * ER + (uint32_t)c * 2;
                uint32_t o1 = o0 + 8u * ER;
                *(uint32_t*)(Ab + o0)         = *(uint32_t*)&hA;
                *(uint32_t*)(Ab + EA_LO + o0) = *(uint32_t*)&lA;
                *(uint32_t*)(Ab + o1)         = *(uint32_t*)&hB;
                *(uint32_t*)(Ab + EA_LO + o1) = *(uint32_t*)&lB;
            }
}

// ---------------- edge MLP; DIR=1 fuses the factor GRU ----------------
// smem: A[0,34816) | W[34816,104448) | idx[104448] | bias[104704: 576 f32]
//       | mbar[107008]
// DIR=1 tail regions: st[69632,87040) A2hi[87040,95744) A2lo[95744,104448)
//   Wrz->[0,69632)  Wn->[0,36864)  gs->[36864,69632)
#define SM_W    34816
#define SM_IDX  104448
#define SM_BIAS 104704
#define SM_MBW  107008
#define EDGE_SMEM_BYTES 107040
template<int DIR>
__global__ __launch_bounds__(256, 2) void edge_mma_kernel(
    const __nv_bfloat16* __restrict__ Ahi, const __nv_bfloat16* __restrict__ Alo,
    const __nv_bfloat16* __restrict__ Bhi, const __nv_bfloat16* __restrict__ Blo,
    const int* __restrict__ idxArr,
    const __nv_bfloat16* __restrict__ fhi, const __nv_bfloat16* __restrict__ flo,
    const unsigned char* __restrict__ wsrc,
    const float* __restrict__ b1, const float* __restrict__ b2,
    const float* __restrict__ b3,
    float* __restrict__ nm,
    const unsigned char* __restrict__ gw,
    const float* __restrict__ gbih, const float* __restrict__ gbhh,
    float* __restrict__ gh,
    __nv_bfloat16* __restrict__ gh_hi, __nv_bfloat16* __restrict__ gh_lo)
{
    extern __shared__ __align__(256) unsigned char sm[];
    const uint32_t smb = smem_u32(sm);
    const int tid = threadIdx.x;
    const int e0 = blockIdx.x * 64;
    const int p0 = e0 >> 1;

    int*   idx    = (int*)(sm + SM_IDX);
    float* bias_s = (float*)(sm + SM_BIAS);
    const uint32_t mbw = smb + SM_MBW;

    if (tid == 0) MBARRIER_INIT(mbw, 1u);
    __syncthreads();
    if (tid == 0) {
        MBARRIER_EXPECT_TX(mbw, 69632u);
        bulk_copy_g2s(smb + SM_W, wsrc, 69632u, mbw);
    }
    if (tid < 64) idx[tid] = idxArr[e0 + tid];
    for (int i = tid; i < (DIR ? 576 : 320); i += 256) {
        float v;
        if (i < 128)      v = b1[i];
        else if (i < 256) v = b2[i - 128];
        else if (i < 320) v = b3[i - 256];
        else {
            int g = i - 320;
            if (g < 128)      v = gbih[g] + gbhh[g];
            else if (g < 192) v = gbih[g];
            else              v = gbhh[g - 64];
        }
        bias_s[i] = v;
    }
    __syncthreads();

    {
        int r = tid >> 3, q = tid & 7;
        const __nv_bfloat16* srcH = (DIR == 0) ? Ahi : Bhi;
        const __nv_bfloat16* srcL = (DIR == 0) ? Alo : Blo;
        uint4 hv = *(const uint4*)(srcH + (size_t)(p0 + r) * 64 + q * 8);
        uint4 lv = *(const uint4*)(srcL + (size_t)(p0 + r) * 64 + q * 8);
        uint32_t cb = (DIR == 0) ? 0u : 128u;
        uint32_t o0 = (uint32_t)(2 * r)     * ER + cb + q * 16;
        uint32_t o1 = (uint32_t)(2 * r + 1) * ER + cb + q * 16;
        *(uint4*)(sm + o0)         = hv;  *(uint4*)(sm + o1)         = hv;
        *(uint4*)(sm + EA_LO + o0) = lv;  *(uint4*)(sm + EA_LO + o1) = lv;
    }
    for (int i = tid; i < 512; i += 256) {
        int e = i >> 3, q = i & 7;
        int s = idx[e];
        const __nv_bfloat16* srcH = (DIR == 0) ? Bhi : Ahi;
        const __nv_bfloat16* srcL = (DIR == 0) ? Blo : Alo;
        uint4 hv = *(const uint4*)(srcH + (size_t)s * 64 + q * 8);
        uint4 lv = *(const uint4*)(srcL + (size_t)s * 64 + q * 8);
        uint32_t cb = (DIR == 0) ? 128u : 0u;
        uint32_t o = (uint32_t)e * ER + cb + q * 16;
        *(uint4*)(sm + o)         = hv;
        *(uint4*)(sm + EA_LO + o) = lv;
    }
    if (tid < 64) {
        int e = tid;
        int rowIdx = (DIR == 0) ? (p0 + (e >> 1)) : idx[e];
        int colIdx = (DIR == 0) ? idx[e] : (p0 + (e >> 1));
        uint2 rh = *(const uint2*)(fhi + (size_t)rowIdx * 4);
        uint2 ch = *(const uint2*)(fhi + (size_t)colIdx * 4);
        uint2 rl = *(const uint2*)(flo + (size_t)rowIdx * 4);
        uint2 cl = *(const uint2*)(flo + (size_t)colIdx * 4);
        uint32_t o = (uint32_t)e * ER + 256;
        *(uint4*)(sm + o)         = make_uint4(rh.x, rh.y, ch.x, ch.y);
        *(uint4*)(sm + EA_LO + o) = make_uint4(rl.x, rl.y, cl.x, cl.y);
    }
    __syncthreads();

    const int w = tid >> 5, lane = tid & 31;
    const int mbase = (w & 1) * 32;
    const int nb32  = (w >> 1) * 32;
    const int nb16  = (w >> 1) * 16;
    float acc[32];

    // ---- layer 1 ----
    MBARRIER_WAIT_PARITY(mbw, 0);
    #pragma unroll
    for (int i = 0; i < 32; i++) acc[i] = 0.f;
    layer_mma_s<8, 2>(smb, smb + SM_W, ER, EA_LO, EW_LO128, lane, mbase, nb32, acc);
    layer1_tail(smb, smb + SM_W, lane, mbase, nb32, acc);
    __syncthreads();
    if (tid == 0) {
        MBARRIER_EXPECT_TX(mbw, 69632u);
        bulk_copy_g2s(smb + SM_W, wsrc + 69632, 69632u, mbw);
    }
    epi12(sm, bias_s, lane, mbase, nb32, acc);
    __syncthreads();

    // ---- layer 2 ----
    MBARRIER_WAIT_PARITY(mbw, 1);
    #pragma unroll
    for (int i = 0; i < 32; i++) acc[i] = 0.f;
    layer_mma_s<8, 2>(smb, smb + SM_W, ER, EA_LO, EW_LO128, lane, mbase, nb32, acc);
    __syncthreads();
    if (tid == 0) {
        MBARRIER_EXPECT_TX(mbw, 34816u);
        bulk_copy_g2s(smb + SM_W, wsrc + 139264, 34816u, mbw);
    }
    epi12(sm, bias_s + 128, lane, mbase, nb32, acc);
    __syncthreads();

    // ---- layer 3 ----
    MBARRIER_WAIT_PARITY(mbw, 0);
    #pragma unroll
    for (int i = 0; i < 16; i++) acc[i] = 0.f;
    layer_mma_s<8, 1>(smb, smb + SM_W, ER, EA_LO, EW_LO64, lane, mbase, nb16, acc);

    if (DIR == 0) {
        #pragma unroll
        for (int m = 0; m < 2; m++)
            #pragma unroll
            for (int h = 0; h < 2; h++) {
                const float* d = acc + (m * 2 + h) * 4;
                int c = nb16 + h * 8 + 2 * (lane & 3);
                int r = mbase + m * 16 + (lane >> 2);
                float b0 = bias_s[256 + c], b1v = bias_s[256 + c + 1];
                float* q0 = nm + (size_t)idx[r] * 64 + c;
                float* q1 = nm + (size_t)idx[r + 8] * 64 + c;
                atomicAdd(q0,     d[0] + b0);
                atomicAdd(q0 + 1, d[1] + b1v);
                atomicAdd(q1,     d[2] + b0);
                atomicAdd(q1 + 1, d[3] + b1v);
            }
    } else {
        // ================= fused factor GRU (32 factors p0..p0+31) =========
        __syncthreads();     // all L3 MMA + A/W reads done
        if (tid == 0) {      // Wrz -> [0, 69632)
            MBARRIER_EXPECT_TX(mbw, 69632u);
            bulk_copy_g2s(smb, gw, 69632u, mbw);
        }
        // stage layer-3 messages: st[64][68] f32 at [69632, 87040)
        float* st = (float*)(sm + 69632);
        #pragma unroll
        for (int m = 0; m < 2; m++)
            #pragma unroll
            for (int h = 0; h < 2; h++) {
                const float* d = acc + (m * 2 + h) * 4;
                int c = nb16 + h * 8 + 2 * (lane & 3);
                int r = mbase + m * 16 + (lane >> 2);
                float b0 = bias_s[256 + c], b1v = bias_s[256 + c + 1];
                st[r * 68 + c]           = d[0] + b0;
                st[r * 68 + c + 1]       = d[1] + b1v;
                st[(r + 8) * 68 + c]     = d[2] + b0;
                st[(r + 8) * 68 + c + 1] = d[3] + b1v;
            }
        // A2 h-part from global (fac state), rows p: cols 16-31 (bytes 128-255)
        unsigned char* A2h = sm + 87040;
        unsigned char* A2l = sm + 95744;
        {
            int p = tid >> 3, q = tid & 7;
            uint4 hv = *(const uint4*)(Bhi + (size_t)(p0 + p) * 64 + q * 8);
            uint4 lv = *(const uint4*)(Blo + (size_t)(p0 + p) * 64 + q * 8);
            uint32_t o = (uint32_t)p * ER + 128 + q * 16;
            *(uint4*)(A2h + o) = hv;
            *(uint4*)(A2l + o) = lv;
        }
        __syncthreads();   // st complete
        // A2 x-part = pair-sum of st, hi/lo split (32 x 64)
        for (int i = tid; i < 2048; i += 256) {
            int p = i >> 6, c = i & 63;
            float v = st[(2 * p) * 68 + c] + st[(2 * p + 1) * 68 + c];
            __nv_bfloat16 hb = __float2bfloat16(v);
            __nv_bfloat16 lb = __float2bfloat16(v - __bfloat162float(hb));
            uint32_t o = (uint32_t)p * ER + (uint32_t)c * 2;
            *(__nv_bfloat16*)(A2h + o) = hb;
            *(__nv_bfloat16*)(A2l + o) = lb;
        }
        __syncthreads();

        // rz pass: A2[x|h] (K=128) @ Wrz (N=128); warp tile 32m x 16n
        float* acc1 = acc;          // reuse regs [0..15]
        float* acc2 = acc + 16;
        #pragma unroll
        for (int i = 0; i < 32; i++) acc[i] = 0.f;
        const int gnb = w * 16;
        MBARRIER_WAIT_PARITY(mbw, 1);
        layer_mma_2s<8, 1>(smb + 87040, ER, 8704, smb, ER, 34816,
                           lane, 0, gnb, acc1);
        __syncthreads();   // Wrz reads done
        if (tid == 0) {    // Wn -> [0, 36864)
            MBARRIER_EXPECT_TX(mbw, 36864u);
            bulk_copy_g2s(smb, gw + 69632, 36864u, mbw);
        }
        MBARRIER_WAIT_PARITY(mbw, 0);
        {
            uint32_t aOff = (gnb >= 64) ? 128u : 0u;
            layer_mma_2s<4, 1>(smb + 87040 + aOff, ER, 8704, smb, 144, 18432,
                               lane, 0, gnb, acc2);
        }
        __syncthreads();   // all MMA done; gs overlay safe

        float* gs = (float*)(sm + 36864);   // 32 x 256 f32
        #pragma unroll
        for (int m = 0; m < 2; m++)
            #pragma unroll
            for (int hh = 0; hh < 2; hh++) {
                int c = gnb + hh * 8 + 2 * (lane & 3);
                int r = m * 16 + (lane >> 2);
                const float* d1 = acc1 + (m * 2 + hh) * 4;
                const float* d2 = acc2 + (m * 2 + hh) * 4;
                gs[r * 256 + c]                 = d1[0];
                gs[r * 256 + c + 1]             = d1[1];
                gs[(r + 8) * 256 + c]           = d1[2];
                gs[(r + 8) * 256 + c + 1]       = d1[3];
                gs[r * 256 + 128 + c]           = d2[0];
                gs[r * 256 + 128 + c + 1]       = d2[1];
                gs[(r + 8) * 256 + 128 + c]     = d2[2];
                gs[(r + 8) * 256 + 128 + c + 1] = d2[3];
            }
        __syncthreads();

        const float* gb = bias_s + 320;
        for (int i = tid; i < 2048; i += 256) {
            int p = i >> 6, d = i & 63;
            int f = p0 + p;
            const float* g = gs + p * 256;
            float pr = g[d]       + gb[d];
            float pz = g[64 + d]  + gb[64 + d];
            float in = g[128 + d] + gb[128 + d];
            float hn = g[192 + d] + gb[192 + d];
            float rr = 1.f / (1.f + expf(-pr));
            float zz = 1.f / (1.f + expf(-pz));
            float nn = tanhf(in + rr * hn);
            float hv = gh[(size_t)f * 64 + d];
            float hnew = (1.f - zz) * nn + zz * hv;
            gh[(size_t)f * 64 + d] = hnew;
            __nv_bfloat16 hb = __float2bfloat16(hnew);
            gh_hi[(size_t)f * 64 + d] = hb;
            gh_lo[(size_t)f * 64 + d] = __float2bfloat16(hnew - __bfloat162float(hb));
        }
    }
}

// ---------------- GRU-64 for var (unchanged from R13) ----------------
#define G64_W    34816
#define G64_BIAS 104448
#define G64_MBW  105472
#define G64_SMEM_BYTES 105504
__global__ __launch_bounds__(256, 2) void gru64_kernel(
    float* __restrict__ h,
    __nv_bfloat16* __restrict__ h_hi, __nv_bfloat16* __restrict__ h_lo,
    float* __restrict__ x,
    const unsigned char* __restrict__ wsrc,
    const float* __restrict__ bih, const float* __restrict__ bhh,
    int nrows)
{
    extern __shared__ __align__(256) unsigned char sm[];
    const uint32_t smb = smem_u32(sm);
    const int tid = threadIdx.x;
    const int r0 = blockIdx.x * 64;

    float* bias_s = (float*)(sm + G64_BIAS);
    const uint32_t mbw = smb + G64_MBW;

    if (tid == 0) MBARRIER_INIT(mbw, 1u);
    __syncthreads();
    if (tid == 0) {
        MBARRIER_EXPECT_TX(mbw, 69632u);
        bulk_copy_g2s(smb + G64_W, wsrc, 69632u, mbw);
    }
    {
        int i = tid;
        float v;
        if (i < 128)      v = bih[i] + bhh[i];
        else if (i < 192) v = bih[i];
        else              v = bhh[i - 64];
        bias_s[i & 255] = v;
    }

    for (int i = tid; i < 64 * 32; i += 256) {
        int e = i >> 5, q = i & 31;
        int rr = r0 + e;
        int rc = rr < nrows ? rr : nrows - 1;
        float4 xv;
        if (q < 16) {
            xv = *(const float4*)(x + (size_t)rc * 64 + q * 4);
            if (rr < nrows) *(float4*)(x + (size_t)rc * 64 + q * 4) = make_float4(0.f, 0.f, 0.f, 0.f);
        } else {
            xv = *(const float4*)(h + (size_t)rc * 64 + (q - 16) * 4);
        }
        __nv_bfloat162 h01 = __floats2bfloat162_rn(xv.x, xv.y);
        __nv_bfloat162 h23 = __floats2bfloat162_rn(xv.z, xv.w);
        __nv_bfloat162 l01 = __floats2bfloat162_rn(xv.x - __low2float(h01), xv.y - __high2float(h01));
        __nv_bfloat162 l23 = __floats2bfloat162_rn(xv.z - __low2float(h23), xv.w - __high2float(h23));
        uint32_t off = (uint32_t)e * ER + (uint32_t)q * 8;
        *(uint2*)(sm + off)         = make_uint2(*(uint32_t*)&h01, *(uint32_t*)&h23);
        *(uint2*)(sm + EA_LO + off) = make_uint2(*(uint32_t*)&l01, *(uint32_t*)&l23);
    }
    __syncthreads();

    const int w = tid >> 5, lane = tid & 31;
    const int mbase = (w & 1) * 32;
    const int nb32  = (w >> 1) * 32;
    float acc1[32], acc2[32];
    #pragma unroll
    for (int i = 0; i < 32; i++) { acc1[i] = 0.f; acc2[i] = 0.f; }

    MBARRIER_WAIT_PARITY(mbw, 0);
    layer_mma_2s<8, 2>(smb, ER, EA_LO, smb + G64_W, ER, 34816, lane, mbase, nb32, acc1);
    __syncthreads();
    if (tid == 0) {
        MBARRIER_EXPECT_TX(mbw, 36864u);
        bulk_copy_g2s(smb + G64_W, wsrc + 69632, 36864u, mbw);
    }
    MBARRIER_WAIT_PARITY(mbw, 1);
    {
        uint32_t aOff = (nb32 >= 64) ? 128u : 0u;
        int nbW = nb32 & 63;
        int wBase = (nb32 >= 64) ? 64 : 0;
        layer_mma_2s<4, 2>(smb + aOff, ER, EA_LO,
                           smb + G64_W, 144, 18432, lane, mbase, wBase + nbW, acc2);
    }
    __syncthreads();

    float* gs = (float*)sm;
    #pragma unroll
    for (int m = 0; m < 2; m++)
        #pragma unroll
        for (int np = 0; np < 2; np++)
            #pragma unroll
            for (int hh = 0; hh < 2; hh++) {
                int c = nb32 + np * 16 + hh * 8 + 2 * (lane & 3);
                int r = mbase + m * 16 + (lane >> 2);
                const float* d1 = acc1 + ((m * 2 + np) * 2 + hh) * 4;
                const float* d2 = acc2 + ((m * 2 + np) * 2 + hh) * 4;
                gs[r * 256 + c]                 = d1[0];
                gs[r * 256 + c + 1]             = d1[1];
                gs[(r + 8) * 256 + c]           = d1[2];
                gs[(r + 8) * 256 + c + 1]       = d1[3];
                gs[r * 256 + 128 + c]           = d2[0];
                gs[r * 256 + 128 + c + 1]       = d2[1];
                gs[(r + 8) * 256 + 128 + c]     = d2[2];
                gs[(r + 8) * 256 + 128 + c + 1] = d2[3];
            }
    __syncthreads();

    for (int i = tid; i < 64 * 64; i += 256) {
        int e = i >> 6, d = i & 63;
        int r = r0 + e;
        if (r >= nrows) continue;
        const float* g = gs + e * 256;
        float pr = g[d]       + bias_s[d];
        float pz = g[64 + d]  + bias_s[64 + d];
        float in = g[128 + d] + bias_s[128 + d];
        float hn = g[192 + d] + bias_s[192 + d];
        float rr = 1.f / (1.f + expf(-pr));
        float zz = 1.f / (1.f + expf(-pz));
        float nn = tanhf(in + rr * hn);
        float hv = h[(size_t)r * 64 + d];
        float hnew = (1.f - zz) * nn + zz * hv;
        h[(size_t)r * 64 + d] = hnew;
        __nv_bfloat16 hb = __float2bfloat16(hnew);
        h_hi[(size_t)r * 64 + d] = hb;
        h_lo[(size_t)r * 64 + d] = __float2bfloat16(hnew - __bfloat162float(hb));
    }
}

// ---------------- readout (unchanged) ----------------
__global__ __launch_bounds__(256) void readout_kernel(
    const float* __restrict__ h,
    const float* __restrict__ W1, const float* __restrict__ b1,
    const float* __restrict__ W2, const float* __restrict__ b2,
    const float* __restrict__ W3, const float* __restrict__ b3,
    float* __restrict__ out, int nrows)
{
    __shared__ float hs[32 * 68];
    __shared__ float l1s[32 * 132];
    __shared__ float l2s[32 * 132];
    __shared__ float lg[64];

    const int tid = threadIdx.x;
    const int r0  = blockIdx.x * 32;

    for (int i = tid; i < 32 * 64; i += 256) {
        int e = i >> 6, k = i & 63;
        int r = r0 + e;
        hs[e * 68 + k] = (r < nrows) ? h[(size_t)r * 64 + k] : 0.f;
    }
    __syncthreads();

    const int warp = tid >> 5, lane = tid & 31;
    #pragma unroll
    for (int jc = 0; jc < 4; jc++) {
        const int j0 = warp * 16 + jc * 4;
        float a[4] = {0.f, 0.f, 0.f, 0.f};
        #pragma unroll
        for (int k = 0; k < 64; k += 4) {
            float4 xv = *(const float4*)(hs + lane * 68 + k);
            #pragma unroll
            for (int jj = 0; jj < 4; jj++) {
                float4 wv = *(const float4*)(W1 + (size_t)(j0 + jj) * 64 + k);
                a[jj] += wv.x * xv.x + wv.y * xv.y + wv.z * xv.z + wv.w * xv.w;
            }
        }
        #pragma unroll
        for (int jj = 0; jj < 4; jj++)
            l1s[lane * 132 + j0 + jj] = fmaxf(a[jj] + b1[j0 + jj], 0.f);
    }
    __syncthreads();
    #pragma unroll
    for (int jc = 0; jc < 4; jc++) {
        const int j0 = warp * 16 + jc * 4;
        float a[4] = {0.f, 0.f, 0.f, 0.f};
        #pragma unroll 2
        for (int k = 0; k < 128; k += 4) {
            float4 xv = *(const float4*)(l1s + lane * 132 + k);
            #pragma unroll
            for (int jj = 0; jj < 4; jj++) {
                float4 wv = *(const float4*)(W2 + (size_t)(j0 + jj) * 128 + k);
                a[jj] += wv.x * xv.x + wv.y * xv.y + wv.z * xv.z + wv.w * xv.w;
            }
        }
        #pragma unroll
        for (int jj = 0; jj < 4; jj++)
            l2s[lane * 132 + j0 + jj] = fmaxf(a[jj] + b2[j0 + jj], 0.f);
    }
    __syncthreads();
    if (tid < 64) {
        int e = tid >> 1, j = tid & 1;
        float a = 0.f;
        #pragma unroll 4
        for (int k = 0; k < 128; k += 4) {
            float4 xv = *(const float4*)(l2s + e * 132 + k);
            float4 wv = *(const float4*)(W3 + (size_t)j * 128 + k);
            a += wv.x * xv.x + wv.y * xv.y + wv.z * xv.z + wv.w * xv.w;
        }
        lg[e * 2 + j] = a + b3[j];
    }
    __syncthreads();
    if (tid < 64) {
        int e = tid >> 1, j = tid & 1;
        int r = r0 + e;
        if (r < nrows) {
            float self  = lg[e * 2 + j];
            float other = lg[e * 2 + (j ^ 1)];
            out[(size_t)r * 2 + j] = 1.f / (1.f + expf(other - self));
        }
    }
}

extern "C" void kernel_launch(void* const* d_in, const int* in_sizes, int n_in,
                              void* d_out, int out_size)
{
    const int*   f2v_col  = (const int*)d_in[1];
    const int*   v2f_row  = (const int*)d_in[2];
    const float* f2v_feat = (const float*)d_in[4];
    const float* v2f_feat = (const float*)d_in[5];
    const float* f2v_w1 = (const float*)d_in[6];   const float* f2v_b1 = (const float*)d_in[7];
    const float* f2v_w2 = (const float*)d_in[8];   const float* f2v_b2 = (const float*)d_in[9];
    const float* f2v_w3 = (const float*)d_in[10];  const float* f2v_b3 = (const float*)d_in[11];
    const float* v2f_w1 = (const float*)d_in[12];  const float* v2f_b1 = (const float*)d_in[13];
    const float* v2f_w2 = (const float*)d_in[14];  const float* v2f_b2 = (const float*)d_in[15];
    const float* v2f_w3 = (const float*)d_in[16];  const float* v2f_b3 = (const float*)d_in[17];
    const float* gf_wih = (const float*)d_in[18];  const float* gf_whh = (const float*)d_in[19];
    const float* gf_bih = (const float*)d_in[20];  const float* gf_bhh = (const float*)d_in[21];
    const float* gv_wih = (const float*)d_in[22];  const float* gv_whh = (const float*)d_in[23];
    const float* gv_bih = (const float*)d_in[24];  const float* gv_bhh = (const float*)d_in[25];
    const float* ro_w1  = (const float*)d_in[26];  const float* ro_b1  = (const float*)d_in[27];
    const float* ro_w2  = (const float*)d_in[28];  const float* ro_b2  = (const float*)d_in[29];
    const float* ro_w3  = (const float*)d_in[30];  const float* ro_b3  = (const float*)d_in[31];
    float* out = (float*)d_out;

    float *var_h, *fac_h, *nm_var;
    __nv_bfloat16 *var_hhi, *var_hlo, *fac_hhi, *fac_hlo;
    __nv_bfloat16 *f2v_fhi, *f2v_flo, *v2f_fhi, *v2f_flo;
    unsigned char *wp_f2v, *wp_v2f, *wg_gf, *wg_gv;
    cudaGetSymbolAddress((void**)&var_h,   g_var_h);
    cudaGetSymbolAddress((void**)&fac_h,   g_fac_h);
    cudaGetSymbolAddress((void**)&nm_var,  g_nm_var);
    cudaGetSymbolAddress((void**)&var_hhi, g_var_hhi);
    cudaGetSymbolAddress((void**)&var_hlo, g_var_hlo);
    cudaGetSymbolAddress((void**)&fac_hhi, g_fac_hhi);
    cudaGetSymbolAddress((void**)&fac_hlo, g_fac_hlo);
    cudaGetSymbolAddress((void**)&f2v_fhi, g_f2v_fhi);
    cudaGetSymbolAddress((void**)&f2v_flo, g_f2v_flo);
    cudaGetSymbolAddress((void**)&v2f_fhi, g_v2f_fhi);
    cudaGetSymbolAddress((void**)&v2f_flo, g_v2f_flo);
    cudaGetSymbolAddress((void**)&wp_f2v,  g_wpack_f2v);
    cudaGetSymbolAddress((void**)&wp_v2f,  g_wpack_v2f);
    cudaGetSymbolAddress((void**)&wg_gf,   g_wgru_gf);
    cudaGetSymbolAddress((void**)&wg_gv,   g_wgru_gv);

    cudaFuncSetAttribute(edge_mma_kernel<0>, cudaFuncAttributeMaxDynamicSharedMemorySize, EDGE_SMEM_BYTES);
    cudaFuncSetAttribute(edge_mma_kernel<1>, cudaFuncAttributeMaxDynamicSharedMemorySize, EDGE_SMEM_BYTES);
    cudaFuncSetAttribute(gru64_kernel,       cudaFuncAttributeMaxDynamicSharedMemorySize, G64_SMEM_BYTES);

    setup_kernel<<<296, 256>>>(
        f2v_w1, f2v_w2, f2v_w3, v2f_w1, v2f_w2, v2f_w3,
        gf_wih, gf_whh, gv_wih, gv_whh, f2v_feat, v2f_feat);

    for (int s = 0; s < 5; s++) {
        edge_mma_kernel<0><<<NE / 64, 256, EDGE_SMEM_BYTES>>>(
            fac_hhi, fac_hlo, var_hhi, var_hlo, f2v_col, f2v_fhi, f2v_flo,
            wp_f2v, f2v_b1, f2v_b2, f2v_b3, nm_var,
            wg_gf, gf_bih, gf_bhh, var_h, var_hhi, var_hlo);
        gru64_kernel<<<(NV + 63) / 64, 256, G64_SMEM_BYTES>>>(
            var_h, var_hhi, var_hlo, nm_var, wg_gf, gf_bih, gf_bhh, NV);

        if (s < 4) {
            // fused: edge message pass + factor GRU (per-block factor ownership)
            edge_mma_kernel<1><<<NE / 64, 256, EDGE_SMEM_BYTES>>>(
                var_hhi, var_hlo, fac_hhi, fac_hlo, v2f_row, v2f_fhi, v2f_flo,
                wp_v2f, v2f_b1, v2f_b2, v2f_b3, nm_var /*unused*/,
                wg_gv, gv_bih, gv_bhh, fac_h, fac_hhi, fac_hlo);
        }
    }

    readout_kernel<<<(NV + 31) / 32, 256>>>(
        var_h, ro_w1, ro_b1, ro_w2, ro_b2, ro_w3, ro_b3, out, NV);
}

// round 16
// speedup vs baseline: 1.5031x; 1.0461x over previous
#include <cuda_runtime.h>
#include <cuda_bf16.h>
#include <cstdint>
#include <math.h>

#define NV 10000
#define NF 80000
#define NE 160000

#define ER 272
#define EA_LO 17408
#define EW_LO128 34816
#define EW_LO64  17408

__device__ float g_var_h[NV * 64];
__device__ float g_fac_h[NF * 64];
__device__ float g_nm_var[NV * 64];
__device__ __nv_bfloat16 g_var_hhi[NV * 64];
__device__ __nv_bfloat16 g_var_hlo[NV * 64];
__device__ __nv_bfloat16 g_fac_hhi[NF * 64];
__device__ __nv_bfloat16 g_fac_hlo[NF * 64];
__device__ __nv_bfloat16 g_f2v_fhi[NE * 4];
__device__ __nv_bfloat16 g_f2v_flo[NE * 4];
__device__ __nv_bfloat16 g_v2f_fhi[NE * 4];
__device__ __nv_bfloat16 g_v2f_flo[NE * 4];
__device__ __align__(256) unsigned char g_wpack_f2v[174080];
__device__ __align__(256) unsigned char g_wpack_v2f[174080];
// GRU pack: [Wrz hi 34816][Wrz lo 34816][Wn hi 18432][Wn lo 18432] = 106496
__device__ __align__(256) unsigned char g_wgru_gf[106496];
__device__ __align__(256) unsigned char g_wgru_gv[106496];

__device__ __forceinline__ uint32_t smem_u32(const void* p) {
    uint32_t a;
    asm("{ .reg .u64 t; cvta.to.shared.u64 t, %1; cvt.u32.u64 %0, t; }" : "=r"(a) : "l"(p));
    return a;
}
#define MBARRIER_INIT(mbar, cnt) \
    asm volatile("mbarrier.init.shared.b64 [%0], %1;" :: "r"(mbar), "r"(cnt) : "memory")
#define MBARRIER_EXPECT_TX(mbar, bytes) \
    asm volatile("mbarrier.arrive.expect_tx.shared.b64 _, [%0], %1;" :: "r"(mbar), "r"(bytes) : "memory")
#define MBARRIER_WAIT_PARITY(mbar, ph) do { \
    asm volatile("{\n\t.reg .pred P1;\n\t" \
        "W_%=:\n\tmbarrier.try_wait.parity.acquire.cta.shared::cta.b64 P1, [%0], %1, 0x989680;\n\t" \
        "@P1 bra.uni D_%=;\n\tbra.uni W_%=;\n\tD_%=:\n\t}" \
        :: "r"(mbar), "r"(ph) : "memory"); \
} while (0)

__device__ __forceinline__ void bulk_copy_g2s(uint32_t dst, const void* src,
                                              uint32_t bytes, uint32_t mbar) {
    asm volatile(
        "cp.async.bulk.shared::cluster.global.mbarrier::complete_tx::bytes [%0], [%1], %2, [%3];"
        :: "r"(dst), "l"(src), "r"(bytes), "r"(mbar) : "memory");
}
__device__ __forceinline__ void ldsm4(uint32_t addr, uint32_t* r) {
    asm volatile("ldmatrix.sync.aligned.m8n8.x4.shared.b16 {%0,%1,%2,%3}, [%4];"
        : "=r"(r[0]), "=r"(r[1]), "=r"(r[2]), "=r"(r[3]) : "r"(addr));
}
__device__ __forceinline__ void mma16816(float* d, const uint32_t* a, const uint32_t* b) {
    asm volatile("mma.sync.aligned.m16n8k16.row.col.f32.bf16.bf16.f32 "
        "{%0,%1,%2,%3}, {%4,%5,%6,%7}, {%8,%9}, {%0,%1,%2,%3};"
        : "+f"(d[0]), "+f"(d[1]), "+f"(d[2]), "+f"(d[3])
        : "r"(a[0]), "r"(a[1]), "r"(a[2]), "r"(a[3]), "r"(b[0]), "r"(b[1]));
}
__device__ __forceinline__ void mma16808(float* d, const uint32_t* a, uint32_t b) {
    asm volatile("mma.sync.aligned.m16n8k8.row.col.f32.bf16.bf16.f32 "
        "{%0,%1,%2,%3}, {%4,%5}, {%6}, {%0,%1,%2,%3};"
        : "+f"(d[0]), "+f"(d[1]), "+f"(d[2]), "+f"(d[3])
        : "r"(a[0]), "r"(a[1]), "r"(b));
}

// ---------------- fused setup ----------------
__device__ void dev_pack_w(unsigned char* dst, const float* W, int nrows, int kin,
                           int gt, int gs) {
    const int total = nrows * 136;
    const int plane = nrows * ER;
    for (int i = gt; i < total; i += gs) {
        int n = i / 136, k = i - n * 136;
        float v = (k < kin) ? W[n * kin + k] : 0.0f;
        __nv_bfloat16 hi = __float2bfloat16(v);
        __nv_bfloat16 lo = __float2bfloat16(v - __bfloat162float(hi));
        uint32_t off = (uint32_t)n * ER + (uint32_t)k * 2;
        *(__nv_bfloat16*)(dst + off) = hi;
        *(__nv_bfloat16*)(dst + plane + off) = lo;
    }
}
__device__ void dev_pack_gru(unsigned char* dst, const float* wih, const float* whh,
                             int gt, int gs) {
    for (int i = gt; i < 128 * 136; i += gs) {
        int r = i / 136, k = i - r * 136;
        float v = 0.0f;
        if (k < 64)       v = wih[r * 64 + k];
        else if (k < 128) v = whh[r * 64 + (k - 64)];
        __nv_bfloat16 hi = __float2bfloat16(v);
        __nv_bfloat16 lo = __float2bfloat16(v - __bfloat162float(hi));
        uint32_t off = (uint32_t)r * 272 + (uint32_t)k * 2;
        *(__nv_bfloat16*)(dst + off) = hi;
        *(__nv_bfloat16*)(dst + 34816 + off) = lo;
    }
    for (int i = gt; i < 128 * 72; i += gs) {
        int r = i / 72, k = i - r * 72;
        float v = 0.0f;
        if (k < 64)
            v = (r < 64) ? wih[(128 + r) * 64 + k] : whh[(64 + r) * 64 + k];
        __nv_bfloat16 hi = __float2bfloat16(v);
        __nv_bfloat16 lo = __float2bfloat16(v - __bfloat162float(hi));
        uint32_t off = (uint32_t)r * 144 + (uint32_t)k * 2;
        *(__nv_bfloat16*)(dst + 69632 + off) = hi;
        *(__nv_bfloat16*)(dst + 69632 + 18432 + off) = lo;
    }
}
__device__ void dev_split(__nv_bfloat16* hi_out, __nv_bfloat16* lo_out,
                          const float* src, int n, int gt, int gs) {
    for (int i = gt; i < n; i += gs) {
        float v = src[i];
        __nv_bfloat16 hi = __float2bfloat16(v);
        hi_out[i] = hi;
        lo_out[i] = __float2bfloat16(v - __bfloat162float(hi));
    }
}
__device__ void dev_zero_f(float* p, int n, int gt, int gs) {
    for (int i = gt; i < n; i += gs) p[i] = 0.0f;
}

__global__ __launch_bounds__(256) void setup_kernel(
    const float* __restrict__ f2v_w1, const float* __restrict__ f2v_w2,
    const float* __restrict__ f2v_w3,
    const float* __restrict__ v2f_w1, const float* __restrict__ v2f_w2,
    const float* __restrict__ v2f_w3,
    const float* __restrict__ gf_wih, const float* __restrict__ gf_whh,
    const float* __restrict__ gv_wih, const float* __restrict__ gv_whh,
    const float* __restrict__ f2v_feat, const float* __restrict__ v2f_feat)
{
    const int gt = blockIdx.x * blockDim.x + threadIdx.x;
    const int gs = gridDim.x * blockDim.x;

    dev_pack_w(g_wpack_f2v,          f2v_w1, 128, 136, gt, gs);
    dev_pack_w(g_wpack_f2v + 69632,  f2v_w2, 128, 128, gt, gs);
    dev_pack_w(g_wpack_f2v + 139264, f2v_w3,  64, 128, gt, gs);
    dev_pack_w(g_wpack_v2f,          v2f_w1, 128, 136, gt, gs);
    dev_pack_w(g_wpack_v2f + 69632,  v2f_w2, 128, 128, gt, gs);
    dev_pack_w(g_wpack_v2f + 139264, v2f_w3,  64, 128, gt, gs);
    dev_pack_gru(g_wgru_gf, gf_wih, gf_whh, gt, gs);
    dev_pack_gru(g_wgru_gv, gv_wih, gv_whh, gt, gs);
    dev_split(g_f2v_fhi, g_f2v_flo, f2v_feat, NE * 4, gt, gs);
    dev_split(g_v2f_fhi, g_v2f_flo, v2f_feat, NE * 4, gt, gs);
    dev_zero_f(g_var_h,  NV * 64, gt, gs);
    dev_zero_f(g_fac_h,  NF * 64, gt, gs);
    dev_zero_f(g_nm_var, NV * 64, gt, gs);
    dev_zero_f((float*)g_var_hhi, NV * 32, gt, gs);
    dev_zero_f((float*)g_var_hlo, NV * 32, gt, gs);
    dev_zero_f((float*)g_fac_hhi, NF * 32, gt, gs);
    dev_zero_f((float*)g_fac_hlo, NF * 32, gt, gs);
}

// ---------------- HMMA tiles ----------------
template<int KCH, int NPAIR>
__device__ __forceinline__ void layer_mma_s(
    uint32_t aA, uint32_t aW, uint32_t rstr, uint32_t aLo, uint32_t wLo,
    int lane, int mbase, int nbase, float* acc)
{
    const uint32_t aRow = aA + (uint32_t)(mbase + (lane & 15)) * rstr + ((lane >> 4) << 4);
    const uint32_t bRow = aW + (uint32_t)(nbase + (lane & 7) + ((lane >> 4) << 3)) * rstr
                        + (((lane >> 3) & 1) << 4);
    #pragma unroll
    for (int kc = 0; kc < KCH; kc++) {
        uint32_t ah[8], al[8];
        ldsm4(aRow + kc * 32, ah);
        ldsm4(aRow + 16 * rstr + kc * 32, ah + 4);
        ldsm4(aRow + aLo + kc * 32, al);
        ldsm4(aRow + aLo + 16 * rstr + kc * 32, al + 4);
        #pragma unroll
        for (int np = 0; np < NPAIR; np++) {
            uint32_t bh[4], bl[4];
            ldsm4(bRow + np * 16 * rstr + kc * 32, bh);
            ldsm4(bRow + wLo + np * 16 * rstr + kc * 32, bl);
            #pragma unroll
            for (int m = 0; m < 2; m++) {
                #pragma unroll
                for (int h = 0; h < 2; h++) {
                    float* d = acc + ((m * NPAIR + np) * 2 + h) * 4;
                    mma16816(d, ah + m * 4, bh + h * 2);
                    mma16816(d, ah + m * 4, bl + h * 2);
                    mma16816(d, al + m * 4, bh + h * 2);
                }
            }
        }
    }
}

template<int KCH, int NPAIR>
__device__ __forceinline__ void layer_mma_2s(
    uint32_t aA, uint32_t aStr, uint32_t aLo,
    uint32_t aW, uint32_t wStr, uint32_t wLo,
    int lane, int mbase, int nbase, float* acc)
{
    const uint32_t aRow = aA + (uint32_t)(mbase + (lane & 15)) * aStr + ((lane >> 4) << 4);
    const uint32_t bRow = aW + (uint32_t)(nbase + (lane & 7) + ((lane >> 4) << 3)) * wStr
                        + (((lane >> 3) & 1) << 4);
    #pragma unroll
    for (int kc = 0; kc < KCH; kc++) {
        uint32_t ah[8], al[8];
        ldsm4(aRow + kc * 32, ah);
        ldsm4(aRow + 16 * aStr + kc * 32, ah + 4);
        ldsm4(aRow + aLo + kc * 32, al);
        ldsm4(aRow + aLo + 16 * aStr + kc * 32, al + 4);
        #pragma unroll
        for (int np = 0; np < NPAIR; np++) {
            uint32_t bh[4], bl[4];
            ldsm4(bRow + np * 16 * wStr + kc * 32, bh);
            ldsm4(bRow + wLo + np * 16 * wStr + kc * 32, bl);
            #pragma unroll
            for (int m = 0; m < 2; m++) {
                #pragma unroll
                for (int h = 0; h < 2; h++) {
                    float* d = acc + ((m * NPAIR + np) * 2 + h) * 4;
                    mma16816(d, ah + m * 4, bh + h * 2);
                    mma16816(d, ah + m * 4, bl + h * 2);
                    mma16816(d, al + m * 4, bh + h * 2);
                }
            }
        }
    }
}

__device__ __forceinline__ void layer1_tail(
    uint32_t aA, uint32_t aW, int lane, int mbase, int nbase, float* acc)
{
    const uint32_t aAddr = aA + (uint32_t)(mbase + lane) * ER + 256;
    const uint32_t bAddr = aW + (uint32_t)(nbase + lane) * ER + 256;
    uint32_t ah[4], al[4], bh[4], bl[4];
    ldsm4(aAddr, ah);
    ldsm4(aAddr + EA_LO, al);
    ldsm4(bAddr, bh);
    ldsm4(bAddr + EW_LO128, bl);
    #pragma unroll
    for (int m = 0; m < 2; m++)
        #pragma unroll
        for (int n4 = 0; n4 < 4; n4++) {
            float* d = acc + ((m * 2 + (n4 >> 1)) * 2 + (n4 & 1)) * 4;
            mma16808(d, ah + 2 * m, bh[n4]);
            mma16808(d, ah + 2 * m, bl[n4]);
            mma16808(d, al + 2 * m, bh[n4]);
        }
}

__device__ __forceinline__ void epi12(unsigned char* Ab, const float* bias,
                                      int lane, int mbase, int nbase, const float* acc)
{
    #pragma unroll
    for (int m = 0; m < 2; m++)
        #pragma unroll
        for (int np = 0; np < 2; np++)
            #pragma unroll
            for (int h = 0; h < 2; h++) {
                const float* d = acc + ((m * 2 + np) * 2 + h) * 4;
                int c = nbase + np * 16 + h * 8 + 2 * (lane & 3);
                int r = mbase + m * 16 + (lane >> 2);
                float b0 = bias[c], b1 = bias[c + 1];
                float v0 = fmaxf(d[0] + b0, 0.f), v1 = fmaxf(d[1] + b1, 0.f);
                float v2 = fmaxf(d[2] + b0, 0.f), v3 = fmaxf(d[3] + b1, 0.f);
                __nv_bfloat162 hA = __floats2bfloat162_rn(v0, v1);
                __nv_bfloat162 lA = __floats2bfloat162_rn(v0 - __low2float(hA),
                                                          v1 - __high2float(hA));
                __nv_bfloat162 hB = __floats2bfloat162_rn(v2, v3);
                __nv_bfloat162 lB = __floats2bfloat162_rn(v2 - __low2float(hB),
                                                          v3 - __high2float(hB));
                uint32_t o0 = (uint32_t)r * ER + (uint32_t)c * 2;
                uint32_t o1 = o0 + 8u * ER;
                *(uint32_t*)(Ab + o0)         = *(uint32_t*)&hA;
                *(uint32_t*)(Ab + EA_LO + o0) = *(uint32_t*)&lA;
                *(uint32_t*)(Ab + o1)         = *(uint32_t*)&hB;
                *(uint32_t*)(Ab + EA_LO + o1) = *(uint32_t*)&lB;
            }
}

// ---------------- edge MLP; DIR=1 fuses the factor GRU; FIRST=step0 ---------
#define SM_W    34816
#define SM_IDX  104448
#define SM_BIAS 104704
#define SM_MBW  107008
#define EDGE_SMEM_BYTES 107040
template<int DIR, int FIRST>
__global__ __launch_bounds__(256, 2) void edge_mma_kernel(
    const __nv_bfloat16* __restrict__ Ahi, const __nv_bfloat16* __restrict__ Alo,
    const __nv_bfloat16* __restrict__ Bhi, const __nv_bfloat16* __restrict__ Blo,
    const int* __restrict__ idxArr,
    const __nv_bfloat16* __restrict__ fhi, const __nv_bfloat16* __restrict__ flo,
    const unsigned char* __restrict__ wsrc,
    const float* __restrict__ b1, const float* __restrict__ b2,
    const float* __restrict__ b3,
    float* __restrict__ nm,
    const unsigned char* __restrict__ gw,
    const float* __restrict__ gbih, const float* __restrict__ gbhh,
    float* __restrict__ gh,
    __nv_bfloat16* __restrict__ gh_hi, __nv_bfloat16* __restrict__ gh_lo)
{
    extern __shared__ __align__(256) unsigned char sm[];
    const uint32_t smb = smem_u32(sm);
    const int tid = threadIdx.x;
    const int e0 = blockIdx.x * 64;
    const int p0 = e0 >> 1;

    int*   idx    = (int*)(sm + SM_IDX);
    float* bias_s = (float*)(sm + SM_BIAS);
    const uint32_t mbw = smb + SM_MBW;

    if (tid == 0) MBARRIER_INIT(mbw, 1u);
    __syncthreads();
    if (tid == 0) {
        MBARRIER_EXPECT_TX(mbw, 69632u);
        bulk_copy_g2s(smb + SM_W, wsrc, 69632u, mbw);
    }
    if (tid < 64) idx[tid] = idxArr[e0 + tid];
    for (int i = tid; i < (DIR ? 576 : 320); i += 256) {
        float v;
        if (i < 128)      v = b1[i];
        else if (i < 256) v = b2[i - 128];
        else if (i < 320) v = b3[i - 256];
        else {
            int g = i - 320;
            if (g < 128)      v = gbih[g] + gbhh[g];
            else if (g < 192) v = gbih[g];
            else              v = gbhh[g - 64];
        }
        bias_s[i] = v;
    }
    __syncthreads();

    // gather: dup side (skipped entirely when FIRST & state is zero)
    if (!FIRST || DIR == 1) {
        // DIR=1 FIRST: dup side is fac = 0 -> skip; DIR=0 FIRST: dup = fac = 0 -> skip
        if (!FIRST) {
            int r = tid >> 3, q = tid & 7;
            const __nv_bfloat16* srcH = (DIR == 0) ? Ahi : Bhi;
            const __nv_bfloat16* srcL = (DIR == 0) ? Alo : Blo;
            uint4 hv = *(const uint4*)(srcH + (size_t)(p0 + r) * 64 + q * 8);
            uint4 lv = *(const uint4*)(srcL + (size_t)(p0 + r) * 64 + q * 8);
            uint32_t cb = (DIR == 0) ? 0u : 128u;
            uint32_t o0 = (uint32_t)(2 * r)     * ER + cb + q * 16;
            uint32_t o1 = (uint32_t)(2 * r + 1) * ER + cb + q * 16;
            *(uint4*)(sm + o0)         = hv;  *(uint4*)(sm + o1)         = hv;
            *(uint4*)(sm + EA_LO + o0) = lv;  *(uint4*)(sm + EA_LO + o1) = lv;
        }
    }
    // random side (var for DIR=1; skipped for DIR=0 FIRST since var=0 too)
    if (!(FIRST && DIR == 0)) {
        for (int i = tid; i < 512; i += 256) {
            int e = i >> 3, q = i & 7;
            int s = idx[e];
            const __nv_bfloat16* srcH = (DIR == 0) ? Bhi : Ahi;
            const __nv_bfloat16* srcL = (DIR == 0) ? Blo : Alo;
            uint4 hv = *(const uint4*)(srcH + (size_t)s * 64 + q * 8);
            uint4 lv = *(const uint4*)(srcL + (size_t)s * 64 + q * 8);
            uint32_t cb = (DIR == 0) ? 128u : 0u;
            uint32_t o = (uint32_t)e * ER + cb + q * 16;
            *(uint4*)(sm + o)         = hv;
            *(uint4*)(sm + EA_LO + o) = lv;
        }
    }
    if (tid < 64) {
        int e = tid;
        int rowIdx = (DIR == 0) ? (p0 + (e >> 1)) : idx[e];
        int colIdx = (DIR == 0) ? idx[e] : (p0 + (e >> 1));
        uint2 rh = *(const uint2*)(fhi + (size_t)rowIdx * 4);
        uint2 ch = *(const uint2*)(fhi + (size_t)colIdx * 4);
        uint2 rl = *(const uint2*)(flo + (size_t)rowIdx * 4);
        uint2 cl = *(const uint2*)(flo + (size_t)colIdx * 4);
        uint32_t o = (uint32_t)e * ER + 256;
        *(uint4*)(sm + o)         = make_uint4(rh.x, rh.y, ch.x, ch.y);
        *(uint4*)(sm + EA_LO + o) = make_uint4(rl.x, rl.y, cl.x, cl.y);
    }
    __syncthreads();

    const int w = tid >> 5, lane = tid & 31;
    const int mbase = (w & 1) * 32;
    const int nb32  = (w >> 1) * 32;
    const int nb16  = (w >> 1) * 16;
    float acc[32];

    // ---- layer 1 ----
    MBARRIER_WAIT_PARITY(mbw, 0);
    #pragma unroll
    for (int i = 0; i < 32; i++) acc[i] = 0.f;
    if (FIRST && DIR == 0) {
        // states zero: only feat tail contributes
    } else if (FIRST && DIR == 1) {
        layer_mma_s<4, 2>(smb, smb + SM_W, ER, EA_LO, EW_LO128, lane, mbase, nb32, acc);
    } else {
        layer_mma_s<8, 2>(smb, smb + SM_W, ER, EA_LO, EW_LO128, lane, mbase, nb32, acc);
    }
    layer1_tail(smb, smb + SM_W, lane, mbase, nb32, acc);
    __syncthreads();
    if (tid == 0) {
        MBARRIER_EXPECT_TX(mbw, 69632u);
        bulk_copy_g2s(smb + SM_W, wsrc + 69632, 69632u, mbw);
    }
    epi12(sm, bias_s, lane, mbase, nb32, acc);
    __syncthreads();

    // ---- layer 2 ----
    MBARRIER_WAIT_PARITY(mbw, 1);
    #pragma unroll
    for (int i = 0; i < 32; i++) acc[i] = 0.f;
    layer_mma_s<8, 2>(smb, smb + SM_W, ER, EA_LO, EW_LO128, lane, mbase, nb32, acc);
    __syncthreads();
    if (tid == 0) {
        MBARRIER_EXPECT_TX(mbw, 34816u);
        bulk_copy_g2s(smb + SM_W, wsrc + 139264, 34816u, mbw);
    }
    epi12(sm, bias_s + 128, lane, mbase, nb32, acc);
    __syncthreads();

    // ---- layer 3 ----
    MBARRIER_WAIT_PARITY(mbw, 0);
    // overlap: prefetch A2 h-part (fac state) during L3 MMA; region is free
    if (DIR == 1 && !FIRST) {
        unsigned char* A2h = sm + 87040;
        unsigned char* A2l = sm + 95744;
        int p = tid >> 3, q = tid & 7;
        uint4 hv = *(const uint4*)(Bhi + (size_t)(p0 + p) * 64 + q * 8);
        uint4 lv = *(const uint4*)(Blo + (size_t)(p0 + p) * 64 + q * 8);
        uint32_t o = (uint32_t)p * ER + 128 + q * 16;
        *(uint4*)(A2h + o) = hv;
        *(uint4*)(A2l + o) = lv;
    }
    #pragma unroll
    for (int i = 0; i < 16; i++) acc[i] = 0.f;
    layer_mma_s<8, 1>(smb, smb + SM_W, ER, EA_LO, EW_LO64, lane, mbase, nb16, acc);

    if (DIR == 0) {
        #pragma unroll
        for (int m = 0; m < 2; m++)
            #pragma unroll
            for (int h = 0; h < 2; h++) {
                const float* d = acc + (m * 2 + h) * 4;
                int c = nb16 + h * 8 + 2 * (lane & 3);
                int r = mbase + m * 16 + (lane >> 2);
                float b0 = bias_s[256 + c], b1v = bias_s[256 + c + 1];
                float* q0 = nm + (size_t)idx[r] * 64 + c;
                float* q1 = nm + (size_t)idx[r + 8] * 64 + c;
                atomicAdd(q0,     d[0] + b0);
                atomicAdd(q0 + 1, d[1] + b1v);
                atomicAdd(q1,     d[2] + b0);
                atomicAdd(q1 + 1, d[3] + b1v);
            }
    } else {
        // ================= fused factor GRU =================
        __syncthreads();
        if (tid == 0) {
            MBARRIER_EXPECT_TX(mbw, 69632u);
            bulk_copy_g2s(smb, gw, 69632u, mbw);
        }
        float* st = (float*)(sm + 69632);
        #pragma unroll
        for (int m = 0; m < 2; m++)
            #pragma unroll
            for (int h = 0; h < 2; h++) {
                const float* d = acc + (m * 2 + h) * 4;
                int c = nb16 + h * 8 + 2 * (lane & 3);
                int r = mbase + m * 16 + (lane >> 2);
                float b0 = bias_s[256 + c], b1v = bias_s[256 + c + 1];
                st[r * 68 + c]           = d[0] + b0;
                st[r * 68 + c + 1]       = d[1] + b1v;
                st[(r + 8) * 68 + c]     = d[2] + b0;
                st[(r + 8) * 68 + c + 1] = d[3] + b1v;
            }
        unsigned char* A2h = sm + 87040;
        unsigned char* A2l = sm + 95744;
        __syncthreads();   // st complete (A2 h-part already prefetched)
        for (int i = tid; i < 2048; i += 256) {
            int p = i >> 6, c = i & 63;
            float v = st[(2 * p) * 68 + c] + st[(2 * p + 1) * 68 + c];
            __nv_bfloat16 hb = __float2bfloat16(v);
            __nv_bfloat16 lb = __float2bfloat16(v - __bfloat162float(hb));
            uint32_t o = (uint32_t)p * ER + (uint32_t)c * 2;
            *(__nv_bfloat16*)(A2h + o) = hb;
            *(__nv_bfloat16*)(A2l + o) = lb;
        }
        __syncthreads();

        float* acc1 = acc;
        float* acc2 = acc + 16;
        #pragma unroll
        for (int i = 0; i < 32; i++) acc[i] = 0.f;
        const int gnb = w * 16;
        MBARRIER_WAIT_PARITY(mbw, 1);
        if (FIRST) {   // h = 0: rz reads x cols only (K=64)
            layer_mma_2s<4, 1>(smb + 87040, ER, 8704, smb, ER, 34816,
                               lane, 0, gnb, acc1);
        } else {
            layer_mma_2s<8, 1>(smb + 87040, ER, 8704, smb, ER, 34816,
                               lane, 0, gnb, acc1);
        }
        __syncthreads();
        if (tid == 0) {
            MBARRIER_EXPECT_TX(mbw, 36864u);
            bulk_copy_g2s(smb, gw + 69632, 36864u, mbw);
        }
        MBARRIER_WAIT_PARITY(mbw, 0);
        if (!(FIRST && (w >= 4))) {   // FIRST: hn = 0 (h=0), skip those warps
            uint32_t aOff = (gnb >= 64) ? 128u : 0u;
            layer_mma_2s<4, 1>(smb + 87040 + aOff, ER, 8704, smb, 144, 18432,
                               lane, 0, gnb, acc2);
        }
        __syncthreads();

        float* gs = (float*)(sm + 36864);
        #pragma unroll
        for (int m = 0; m < 2; m++)
            #pragma unroll
            for (int hh = 0; hh < 2; hh++) {
                int c = gnb + hh * 8 + 2 * (lane & 3);
                int r = m * 16 + (lane >> 2);
                const float* d1 = acc1 + (m * 2 + hh) * 4;
                const float* d2 = acc2 + (m * 2 + hh) * 4;
                gs[r * 256 + c]                 = d1[0];
                gs[r * 256 + c + 1]             = d1[1];
                gs[(r + 8) * 256 + c]           = d1[2];
                gs[(r + 8) * 256 + c + 1]       = d1[3];
                gs[r * 256 + 128 + c]           = d2[0];
                gs[r * 256 + 128 + c + 1]       = d2[1];
                gs[(r + 8) * 256 + 128 + c]     = d2[2];
                gs[(r + 8) * 256 + 128 + c + 1] = d2[3];
            }
        __syncthreads();

        const float* gb = bias_s + 320;
        for (int i = tid; i < 2048; i += 256) {
            int p = i >> 6, d = i & 63;
            int f = p0 + p;
            const float* g = gs + p * 256;
            float pr = g[d]       + gb[d];
            float pz = g[64 + d]  + gb[64 + d];
            float in = g[128 + d] + gb[128 + d];
            float hn = g[192 + d] + gb[192 + d];
            float rr = 1.f / (1.f + expf(-pr));
            float zz = 1.f / (1.f + expf(-pz));
            float nn = tanhf(in + rr * hn);
            float hv = FIRST ? 0.f : gh[(size_t)f * 64 + d];
            float hnew = (1.f - zz) * nn + zz * hv;
            gh[(size_t)f * 64 + d] = hnew;
            __nv_bfloat16 hb = __float2bfloat16(hnew);
            gh_hi[(size_t)f * 64 + d] = hb;
            gh_lo[(size_t)f * 64 + d] = __float2bfloat16(hnew - __bfloat162float(hb));
        }
    }
}

// ---------------- GRU-64 for var (unchanged from R13) ----------------
#define G64_W    34816
#define G64_BIAS 104448
#define G64_MBW  105472
#define G64_SMEM_BYTES 105504
__global__ __launch_bounds__(256, 2) void gru64_kernel(
    float* __restrict__ h,
    __nv_bfloat16* __restrict__ h_hi, __nv_bfloat16* __restrict__ h_lo,
    float* __restrict__ x,
    const unsigned char* __restrict__ wsrc,
    const float* __restrict__ bih, const float* __restrict__ bhh,
    int nrows)
{
    extern __shared__ __align__(256) unsigned char sm[];
    const uint32_t smb = smem_u32(sm);
    const int tid = threadIdx.x;
    const int r0 = blockIdx.x * 64;

    float* bias_s = (float*)(sm + G64_BIAS);
    const uint32_t mbw = smb + G64_MBW;

    if (tid == 0) MBARRIER_INIT(mbw, 1u);
    __syncthreads();
    if (tid == 0) {
        MBARRIER_EXPECT_TX(mbw, 69632u);
        bulk_copy_g2s(smb + G64_W, wsrc, 69632u, mbw);
    }
    {
        int i = tid;
        float v;
        if (i < 128)      v = bih[i] + bhh[i];
        else if (i < 192) v = bih[i];
        else              v = bhh[i - 64];
        bias_s[i & 255] = v;
    }

    for (int i = tid; i < 64 * 32; i += 256) {
        int e = i >> 5, q = i & 31;
        int rr = r0 + e;
        int rc = rr < nrows ? rr : nrows - 1;
        float4 xv;
        if (q < 16) {
            xv = *(const float4*)(x + (size_t)rc * 64 + q * 4);
            if (rr < nrows) *(float4*)(x + (size_t)rc * 64 + q * 4) = make_float4(0.f, 0.f, 0.f, 0.f);
        } else {
            xv = *(const float4*)(h + (size_t)rc * 64 + (q - 16) * 4);
        }
        __nv_bfloat162 h01 = __floats2bfloat162_rn(xv.x, xv.y);
        __nv_bfloat162 h23 = __floats2bfloat162_rn(xv.z, xv.w);
        __nv_bfloat162 l01 = __floats2bfloat162_rn(xv.x - __low2float(h01), xv.y - __high2float(h01));
        __nv_bfloat162 l23 = __floats2bfloat162_rn(xv.z - __low2float(h23), xv.w - __high2float(h23));
        uint32_t off = (uint32_t)e * ER + (uint32_t)q * 8;
        *(uint2*)(sm + off)         = make_uint2(*(uint32_t*)&h01, *(uint32_t*)&h23);
        *(uint2*)(sm + EA_LO + off) = make_uint2(*(uint32_t*)&l01, *(uint32_t*)&l23);
    }
    __syncthreads();

    const int w = tid >> 5, lane = tid & 31;
    const int mbase = (w & 1) * 32;
    const int nb32  = (w >> 1) * 32;
    float acc1[32], acc2[32];
    #pragma unroll
    for (int i = 0; i < 32; i++) { acc1[i] = 0.f; acc2[i] = 0.f; }

    MBARRIER_WAIT_PARITY(mbw, 0);
    layer_mma_2s<8, 2>(smb, ER, EA_LO, smb + G64_W, ER, 34816, lane, mbase, nb32, acc1);
    __syncthreads();
    if (tid == 0) {
        MBARRIER_EXPECT_TX(mbw, 36864u);
        bulk_copy_g2s(smb + G64_W, wsrc + 69632, 36864u, mbw);
    }
    MBARRIER_WAIT_PARITY(mbw, 1);
    {
        uint32_t aOff = (nb32 >= 64) ? 128u : 0u;
        int nbW = nb32 & 63;
        int wBase = (nb32 >= 64) ? 64 : 0;
        layer_mma_2s<4, 2>(smb + aOff, ER, EA_LO,
                           smb + G64_W, 144, 18432, lane, mbase, wBase + nbW, acc2);
    }
    __syncthreads();

    float* gs = (float*)sm;
    #pragma unroll
    for (int m = 0; m < 2; m++)
        #pragma unroll
        for (int np = 0; np < 2; np++)
            #pragma unroll
            for (int hh = 0; hh < 2; hh++) {
                int c = nb32 + np * 16 + hh * 8 + 2 * (lane & 3);
                int r = mbase + m * 16 + (lane >> 2);
                const float* d1 = acc1 + ((m * 2 + np) * 2 + hh) * 4;
                const float* d2 = acc2 + ((m * 2 + np) * 2 + hh) * 4;
                gs[r * 256 + c]                 = d1[0];
                gs[r * 256 + c + 1]             = d1[1];
                gs[(r + 8) * 256 + c]           = d1[2];
                gs[(r + 8) * 256 + c + 1]       = d1[3];
                gs[r * 256 + 128 + c]           = d2[0];
                gs[r * 256 + 128 + c + 1]       = d2[1];
                gs[(r + 8) * 256 + 128 + c]     = d2[2];
                gs[(r + 8) * 256 + 128 + c + 1] = d2[3];
            }
    __syncthreads();

    for (int i = tid; i < 64 * 64; i += 256) {
        int e = i >> 6, d = i & 63;
        int r = r0 + e;
        if (r >= nrows) continue;
        const float* g = gs + e * 256;
        float pr = g[d]       + bias_s[d];
        float pz = g[64 + d]  + bias_s[64 + d];
        float in = g[128 + d] + bias_s[128 + d];
        float hn = g[192 + d] + bias_s[192 + d];
        float rr = 1.f / (1.f + expf(-pr));
        float zz = 1.f / (1.f + expf(-pz));
        float nn = tanhf(in + rr * hn);
        float hv = h[(size_t)r * 64 + d];
        float hnew = (1.f - zz) * nn + zz * hv;
        h[(size_t)r * 64 + d] = hnew;
        __nv_bfloat16 hb = __float2bfloat16(hnew);
        h_hi[(size_t)r * 64 + d] = hb;
        h_lo[(size_t)r * 64 + d] = __float2bfloat16(hnew - __bfloat162float(hb));
    }
}

// ---------------- readout (unchanged) ----------------
__global__ __launch_bounds__(256) void readout_kernel(
    const float* __restrict__ h,
    const float* __restrict__ W1, const float* __restrict__ b1,
    const float* __restrict__ W2, const float* __restrict__ b2,
    const float* __restrict__ W3, const float* __restrict__ b3,
    float* __restrict__ out, int nrows)
{
    __shared__ float hs[32 * 68];
    __shared__ float l1s[32 * 132];
    __shared__ float l2s[32 * 132];
    __shared__ float lg[64];

    const int tid = threadIdx.x;
    const int r0  = blockIdx.x * 32;

    for (int i = tid; i < 32 * 64; i += 256) {
        int e = i >> 6, k = i & 63;
        int r = r0 + e;
        hs[e * 68 + k] = (r < nrows) ? h[(size_t)r * 64 + k] : 0.f;
    }
    __syncthreads();

    const int warp = tid >> 5, lane = tid & 31;
    #pragma unroll
    for (int jc = 0; jc < 4; jc++) {
        const int j0 = warp * 16 + jc * 4;
        float a[4] = {0.f, 0.f, 0.f, 0.f};
        #pragma unroll
        for (int k = 0; k < 64; k += 4) {
            float4 xv = *(const float4*)(hs + lane * 68 + k);
            #pragma unroll
            for (int jj = 0; jj < 4; jj++) {
                float4 wv = *(const float4*)(W1 + (size_t)(j0 + jj) * 64 + k);
                a[jj] += wv.x * xv.x + wv.y * xv.y + wv.z * xv.z + wv.w * xv.w;
            }
        }
        #pragma unroll
        for (int jj = 0; jj < 4; jj++)
            l1s[lane * 132 + j0 + jj] = fmaxf(a[jj] + b1[j0 + jj], 0.f);
    }
    __syncthreads();
    #pragma unroll
    for (int jc = 0; jc < 4; jc++) {
        const int j0 = warp * 16 + jc * 4;
        float a[4] = {0.f, 0.f, 0.f, 0.f};
        #pragma unroll 2
        for (int k = 0; k < 128; k += 4) {
            float4 xv = *(const float4*)(l1s + lane * 132 + k);
            #pragma unroll
            for (int jj = 0; jj < 4; jj++) {
                float4 wv = *(const float4*)(W2 + (size_t)(j0 + jj) * 128 + k);
                a[jj] += wv.x * xv.x + wv.y * xv.y + wv.z * xv.z + wv.w * xv.w;
            }
        }
        #pragma unroll
        for (int jj = 0; jj < 4; jj++)
            l2s[lane * 132 + j0 + jj] = fmaxf(a[jj] + b2[j0 + jj], 0.f);
    }
    __syncthreads();
    if (tid < 64) {
        int e = tid >> 1, j = tid & 1;
        float a = 0.f;
        #pragma unroll 4
        for (int k = 0; k < 128; k += 4) {
            float4 xv = *(const float4*)(l2s + e * 132 + k);
            float4 wv = *(const float4*)(W3 + (size_t)j * 128 + k);
            a += wv.x * xv.x + wv.y * xv.y + wv.z * xv.z + wv.w * xv.w;
        }
        lg[e * 2 + j] = a + b3[j];
    }
    __syncthreads();
    if (tid < 64) {
        int e = tid >> 1, j = tid & 1;
        int r = r0 + e;
        if (r < nrows) {
            float self  = lg[e * 2 + j];
            float other = lg[e * 2 + (j ^ 1)];
            out[(size_t)r * 2 + j] = 1.f / (1.f + expf(other - self));
        }
    }
}

extern "C" void kernel_launch(void* const* d_in, const int* in_sizes, int n_in,
                              void* d_out, int out_size)
{
    const int*   f2v_col  = (const int*)d_in[1];
    const int*   v2f_row  = (const int*)d_in[2];
    const float* f2v_feat = (const float*)d_in[4];
    const float* v2f_feat = (const float*)d_in[5];
    const float* f2v_w1 = (const float*)d_in[6];   const float* f2v_b1 = (const float*)d_in[7];
    const float* f2v_w2 = (const float*)d_in[8];   const float* f2v_b2 = (const float*)d_in[9];
    const float* f2v_w3 = (const float*)d_in[10];  const float* f2v_b3 = (const float*)d_in[11];
    const float* v2f_w1 = (const float*)d_in[12];  const float* v2f_b1 = (const float*)d_in[13];
    const float* v2f_w2 = (const float*)d_in[14];  const float* v2f_b2 = (const float*)d_in[15];
    const float* v2f_w3 = (const float*)d_in[16];  const float* v2f_b3 = (const float*)d_in[17];
    const float* gf_wih = (const float*)d_in[18];  const float* gf_whh = (const float*)d_in[19];
    const float* gf_bih = (const float*)d_in[20];  const float* gf_bhh = (const float*)d_in[21];
    const float* gv_wih = (const float*)d_in[22];  const float* gv_whh = (const float*)d_in[23];
    const float* gv_bih = (const float*)d_in[24];  const float* gv_bhh = (const float*)d_in[25];
    const float* ro_w1  = (const float*)d_in[26];  const float* ro_b1  = (const float*)d_in[27];
    const float* ro_w2  = (const float*)d_in[28];  const float* ro_b2  = (const float*)d_in[29];
    const float* ro_w3  = (const float*)d_in[30];  const float* ro_b3  = (const float*)d_in[31];
    float* out = (float*)d_out;

    float *var_h, *fac_h, *nm_var;
    __nv_bfloat16 *var_hhi, *var_hlo, *fac_hhi, *fac_hlo;
    __nv_bfloat16 *f2v_fhi, *f2v_flo, *v2f_fhi, *v2f_flo;
    unsigned char *wp_f2v, *wp_v2f, *wg_gf, *wg_gv;
    cudaGetSymbolAddress((void**)&var_h,   g_var_h);
    cudaGetSymbolAddress((void**)&fac_h,   g_fac_h);
    cudaGetSymbolAddress((void**)&nm_var,  g_nm_var);
    cudaGetSymbolAddress((void**)&var_hhi, g_var_hhi);
    cudaGetSymbolAddress((void**)&var_hlo, g_var_hlo);
    cudaGetSymbolAddress((void**)&fac_hhi, g_fac_hhi);
    cudaGetSymbolAddress((void**)&fac_hlo, g_fac_hlo);
    cudaGetSymbolAddress((void**)&f2v_fhi, g_f2v_fhi);
    cudaGetSymbolAddress((void**)&f2v_flo, g_f2v_flo);
    cudaGetSymbolAddress((void**)&v2f_fhi, g_v2f_fhi);
    cudaGetSymbolAddress((void**)&v2f_flo, g_v2f_flo);
    cudaGetSymbolAddress((void**)&wp_f2v,  g_wpack_f2v);
    cudaGetSymbolAddress((void**)&wp_v2f,  g_wpack_v2f);
    cudaGetSymbolAddress((void**)&wg_gf,   g_wgru_gf);
    cudaGetSymbolAddress((void**)&wg_gv,   g_wgru_gv);

    cudaFuncSetAttribute(edge_mma_kernel<0,0>, cudaFuncAttributeMaxDynamicSharedMemorySize, EDGE_SMEM_BYTES);
    cudaFuncSetAttribute(edge_mma_kernel<0,1>, cudaFuncAttributeMaxDynamicSharedMemorySize, EDGE_SMEM_BYTES);
    cudaFuncSetAttribute(edge_mma_kernel<1,0>, cudaFuncAttributeMaxDynamicSharedMemorySize, EDGE_SMEM_BYTES);
    cudaFuncSetAttribute(edge_mma_kernel<1,1>, cudaFuncAttributeMaxDynamicSharedMemorySize, EDGE_SMEM_BYTES);
    cudaFuncSetAttribute(gru64_kernel, cudaFuncAttributeMaxDynamicSharedMemorySize, G64_SMEM_BYTES);

    setup_kernel<<<296, 256>>>(
        f2v_w1, f2v_w2, f2v_w3, v2f_w1, v2f_w2, v2f_w3,
        gf_wih, gf_whh, gv_wih, gv_whh, f2v_feat, v2f_feat);

    for (int s = 0; s < 5; s++) {
        if (s == 0) {
            edge_mma_kernel<0,1><<<NE / 64, 256, EDGE_SMEM_BYTES>>>(
                fac_hhi, fac_hlo, var_hhi, var_hlo, f2v_col, f2v_fhi, f2v_flo,
                wp_f2v, f2v_b1, f2v_b2, f2v_b3, nm_var,
                wg_gf, gf_bih, gf_bhh, var_h, var_hhi, var_hlo);
        } else {
            edge_mma_kernel<0,0><<<NE / 64, 256, EDGE_SMEM_BYTES>>>(
                fac_hhi, fac_hlo, var_hhi, var_hlo, f2v_col, f2v_fhi, f2v_flo,
                wp_f2v, f2v_b1, f2v_b2, f2v_b3, nm_var,
                wg_gf, gf_bih, gf_bhh, var_h, var_hhi, var_hlo);
        }
        gru64_kernel<<<(NV + 63) / 64, 256, G64_SMEM_BYTES>>>(
            var_h, var_hhi, var_hlo, nm_var, wg_gf, gf_bih, gf_bhh, NV);

        if (s < 4) {
            if (s == 0) {
                edge_mma_kernel<1,1><<<NE / 64, 256, EDGE_SMEM_BYTES>>>(
                    var_hhi, var_hlo, fac_hhi, fac_hlo, v2f_row, v2f_fhi, v2f_flo,
                    wp_v2f, v2f_b1, v2f_b2, v2f_b3, nm_var,
                    wg_gv, gv_bih, gv_bhh, fac_h, fac_hhi, fac_hlo);
            } else {
                edge_mma_kernel<1,0><<<NE / 64, 256, EDGE_SMEM_BYTES>>>(
                    var_hhi, var_hlo, fac_hhi, fac_hlo, v2f_row, v2f_fhi, v2f_flo,
                    wp_v2f, v2f_b1, v2f_b2, v2f_b3, nm_var,
                    wg_gv, gv_bih, gv_bhh, fac_h, fac_hhi, fac_hlo);
            }
        }
    }

    readout_kernel<<<(NV + 31) / 32, 256>>>(
        var_h, ro_w1, ro_b1, ro_w2, ro_b2, ro_w3, ro_b3, out, NV);
}

// round 17
// speedup vs baseline: 1.5212x; 1.0120x over previous
#include <cuda_runtime.h>
#include <cuda_bf16.h>
#include <cstdint>
#include <math.h>

#define NV 10000
#define NF 80000
#define NE 160000

#define ER 272
#define EA_LO 17408
#define EW_LO128 34816
#define EW_LO64  17408

__device__ float g_var_h[NV * 64];
__device__ float g_fac_h[NF * 64];
__device__ float g_nm_var[NV * 64];
__device__ __nv_bfloat16 g_var_hhi[NV * 64];
__device__ __nv_bfloat16 g_var_hlo[NV * 64];
__device__ __nv_bfloat16 g_fac_hhi[NF * 64];
__device__ __nv_bfloat16 g_fac_hlo[NF * 64];
__device__ __nv_bfloat16 g_f2v_fhi[NE * 4];
__device__ __nv_bfloat16 g_f2v_flo[NE * 4];
__device__ __nv_bfloat16 g_v2f_fhi[NE * 4];
__device__ __nv_bfloat16 g_v2f_flo[NE * 4];
__device__ __align__(256) unsigned char g_wpack_f2v[174080];
__device__ __align__(256) unsigned char g_wpack_v2f[174080];
// GRU pack: [Wrz hi 34816][Wrz lo 34816][Wn hi 18432][Wn lo 18432] = 106496
__device__ __align__(256) unsigned char g_wgru_gf[106496];
__device__ __align__(256) unsigned char g_wgru_gv[106496];

__device__ __forceinline__ uint32_t smem_u32(const void* p) {
    uint32_t a;
    asm("{ .reg .u64 t; cvta.to.shared.u64 t, %1; cvt.u32.u64 %0, t; }" : "=r"(a) : "l"(p));
    return a;
}
#define MBARRIER_INIT(mbar, cnt) \
    asm volatile("mbarrier.init.shared.b64 [%0], %1;" :: "r"(mbar), "r"(cnt) : "memory")
#define MBARRIER_EXPECT_TX(mbar, bytes) \
    asm volatile("mbarrier.arrive.expect_tx.shared.b64 _, [%0], %1;" :: "r"(mbar), "r"(bytes) : "memory")
#define MBARRIER_WAIT_PARITY(mbar, ph) do { \
    asm volatile("{\n\t.reg .pred P1;\n\t" \
        "W_%=:\n\tmbarrier.try_wait.parity.acquire.cta.shared::cta.b64 P1, [%0], %1, 0x989680;\n\t" \
        "@P1 bra.uni D_%=;\n\tbra.uni W_%=;\n\tD_%=:\n\t}" \
        :: "r"(mbar), "r"(ph) : "memory"); \
} while (0)

__device__ __forceinline__ void bulk_copy_g2s(uint32_t dst, const void* src,
                                              uint32_t bytes, uint32_t mbar) {
    asm volatile(
        "cp.async.bulk.shared::cluster.global.mbarrier::complete_tx::bytes [%0], [%1], %2, [%3];"
        :: "r"(dst), "l"(src), "r"(bytes), "r"(mbar) : "memory");
}
__device__ __forceinline__ void ldsm4(uint32_t addr, uint32_t* r) {
    asm volatile("ldmatrix.sync.aligned.m8n8.x4.shared.b16 {%0,%1,%2,%3}, [%4];"
        : "=r"(r[0]), "=r"(r[1]), "=r"(r[2]), "=r"(r[3]) : "r"(addr));
}
__device__ __forceinline__ void mma16816(float* d, const uint32_t* a, const uint32_t* b) {
    asm volatile("mma.sync.aligned.m16n8k16.row.col.f32.bf16.bf16.f32 "
        "{%0,%1,%2,%3}, {%4,%5,%6,%7}, {%8,%9}, {%0,%1,%2,%3};"
        : "+f"(d[0]), "+f"(d[1]), "+f"(d[2]), "+f"(d[3])
        : "r"(a[0]), "r"(a[1]), "r"(a[2]), "r"(a[3]), "r"(b[0]), "r"(b[1]));
}
__device__ __forceinline__ void mma16808(float* d, const uint32_t* a, uint32_t b) {
    asm volatile("mma.sync.aligned.m16n8k8.row.col.f32.bf16.bf16.f32 "
        "{%0,%1,%2,%3}, {%4,%5}, {%6}, {%0,%1,%2,%3};"
        : "+f"(d[0]), "+f"(d[1]), "+f"(d[2]), "+f"(d[3])
        : "r"(a[0]), "r"(a[1]), "r"(b));
}

// ---------------- fused setup ----------------
__device__ void dev_pack_w(unsigned char* dst, const float* W, int nrows, int kin,
                           int gt, int gs) {
    const int total = nrows * 136;
    const int plane = nrows * ER;
    for (int i = gt; i < total; i += gs) {
        int n = i / 136, k = i - n * 136;
        float v = (k < kin) ? W[n * kin + k] : 0.0f;
        __nv_bfloat16 hi = __float2bfloat16(v);
        __nv_bfloat16 lo = __float2bfloat16(v - __bfloat162float(hi));
        uint32_t off = (uint32_t)n * ER + (uint32_t)k * 2;
        *(__nv_bfloat16*)(dst + off) = hi;
        *(__nv_bfloat16*)(dst + plane + off) = lo;
    }
}
__device__ void dev_pack_gru(unsigned char* dst, const float* wih, const float* whh,
                             int gt, int gs) {
    for (int i = gt; i < 128 * 136; i += gs) {
        int r = i / 136, k = i - r * 136;
        float v = 0.0f;
        if (k < 64)       v = wih[r * 64 + k];
        else if (k < 128) v = whh[r * 64 + (k - 64)];
        __nv_bfloat16 hi = __float2bfloat16(v);
        __nv_bfloat16 lo = __float2bfloat16(v - __bfloat162float(hi));
        uint32_t off = (uint32_t)r * 272 + (uint32_t)k * 2;
        *(__nv_bfloat16*)(dst + off) = hi;
        *(__nv_bfloat16*)(dst + 34816 + off) = lo;
    }
    for (int i = gt; i < 128 * 72; i += gs) {
        int r = i / 72, k = i - r * 72;
        float v = 0.0f;
        if (k < 64)
            v = (r < 64) ? wih[(128 + r) * 64 + k] : whh[(64 + r) * 64 + k];
        __nv_bfloat16 hi = __float2bfloat16(v);
        __nv_bfloat16 lo = __float2bfloat16(v - __bfloat162float(hi));
        uint32_t off = (uint32_t)r * 144 + (uint32_t)k * 2;
        *(__nv_bfloat16*)(dst + 69632 + off) = hi;
        *(__nv_bfloat16*)(dst + 69632 + 18432 + off) = lo;
    }
}
__device__ void dev_split(__nv_bfloat16* hi_out, __nv_bfloat16* lo_out,
                          const float* src, int n, int gt, int gs) {
    for (int i = gt; i < n; i += gs) {
        float v = src[i];
        __nv_bfloat16 hi = __float2bfloat16(v);
        hi_out[i] = hi;
        lo_out[i] = __float2bfloat16(v - __bfloat162float(hi));
    }
}
__device__ void dev_zero_f(float* p, int n, int gt, int gs) {
    for (int i = gt; i < n; i += gs) p[i] = 0.0f;
}

__global__ __launch_bounds__(256) void setup_kernel(
    const float* __restrict__ f2v_w1, const float* __restrict__ f2v_w2,
    const float* __restrict__ f2v_w3,
    const float* __restrict__ v2f_w1, const float* __restrict__ v2f_w2,
    const float* __restrict__ v2f_w3,
    const float* __restrict__ gf_wih, const float* __restrict__ gf_whh,
    const float* __restrict__ gv_wih, const float* __restrict__ gv_whh,
    const float* __restrict__ f2v_feat, const float* __restrict__ v2f_feat)
{
    const int gt = blockIdx.x * blockDim.x + threadIdx.x;
    const int gs = gridDim.x * blockDim.x;

    dev_pack_w(g_wpack_f2v,          f2v_w1, 128, 136, gt, gs);
    dev_pack_w(g_wpack_f2v + 69632,  f2v_w2, 128, 128, gt, gs);
    dev_pack_w(g_wpack_f2v + 139264, f2v_w3,  64, 128, gt, gs);
    dev_pack_w(g_wpack_v2f,          v2f_w1, 128, 136, gt, gs);
    dev_pack_w(g_wpack_v2f + 69632,  v2f_w2, 128, 128, gt, gs);
    dev_pack_w(g_wpack_v2f + 139264, v2f_w3,  64, 128, gt, gs);
    dev_pack_gru(g_wgru_gf, gf_wih, gf_whh, gt, gs);
    dev_pack_gru(g_wgru_gv, gv_wih, gv_whh, gt, gs);
    dev_split(g_f2v_fhi, g_f2v_flo, f2v_feat, NE * 4, gt, gs);
    dev_split(g_v2f_fhi, g_v2f_flo, v2f_feat, NE * 4, gt, gs);
    dev_zero_f(g_var_h,  NV * 64, gt, gs);
    dev_zero_f(g_fac_h,  NF * 64, gt, gs);
    dev_zero_f(g_nm_var, NV * 64, gt, gs);
    dev_zero_f((float*)g_var_hhi, NV * 32, gt, gs);
    dev_zero_f((float*)g_var_hlo, NV * 32, gt, gs);
    dev_zero_f((float*)g_fac_hhi, NF * 32, gt, gs);
    dev_zero_f((float*)g_fac_hlo, NF * 32, gt, gs);
}

// ---------------- HMMA tiles ----------------
template<int KCH, int NPAIR>
__device__ __forceinline__ void layer_mma_s(
    uint32_t aA, uint32_t aW, uint32_t rstr, uint32_t aLo, uint32_t wLo,
    int lane, int mbase, int nbase, float* acc)
{
    const uint32_t aRow = aA + (uint32_t)(mbase + (lane & 15)) * rstr + ((lane >> 4) << 4);
    const uint32_t bRow = aW + (uint32_t)(nbase + (lane & 7) + ((lane >> 4) << 3)) * rstr
                        + (((lane >> 3) & 1) << 4);
    #pragma unroll
    for (int kc = 0; kc < KCH; kc++) {
        uint32_t ah[8], al[8];
        ldsm4(aRow + kc * 32, ah);
        ldsm4(aRow + 16 * rstr + kc * 32, ah + 4);
        ldsm4(aRow + aLo + kc * 32, al);
        ldsm4(aRow + aLo + 16 * rstr + kc * 32, al + 4);
        #pragma unroll
        for (int np = 0; np < NPAIR; np++) {
            uint32_t bh[4], bl[4];
            ldsm4(bRow + np * 16 * rstr + kc * 32, bh);
            ldsm4(bRow + wLo + np * 16 * rstr + kc * 32, bl);
            #pragma unroll
            for (int m = 0; m < 2; m++) {
                #pragma unroll
                for (int h = 0; h < 2; h++) {
                    float* d = acc + ((m * NPAIR + np) * 2 + h) * 4;
                    mma16816(d, ah + m * 4, bh + h * 2);
                    mma16816(d, ah + m * 4, bl + h * 2);
                    mma16816(d, al + m * 4, bh + h * 2);
                }
            }
        }
    }
}

template<int KCH, int NPAIR>
__device__ __forceinline__ void layer_mma_2s(
    uint32_t aA, uint32_t aStr, uint32_t aLo,
    uint32_t aW, uint32_t wStr, uint32_t wLo,
    int lane, int mbase, int nbase, float* acc)
{
    const uint32_t aRow = aA + (uint32_t)(mbase + (lane & 15)) * aStr + ((lane >> 4) << 4);
    const uint32_t bRow = aW + (uint32_t)(nbase + (lane & 7) + ((lane >> 4) << 3)) * wStr
                        + (((lane >> 3) & 1) << 4);
    #pragma unroll
    for (int kc = 0; kc < KCH; kc++) {
        uint32_t ah[8], al[8];
        ldsm4(aRow + kc * 32, ah);
        ldsm4(aRow + 16 * aStr + kc * 32, ah + 4);
        ldsm4(aRow + aLo + kc * 32, al);
        ldsm4(aRow + aLo + 16 * aStr + kc * 32, al + 4);
        #pragma unroll
        for (int np = 0; np < NPAIR; np++) {
            uint32_t bh[4], bl[4];
            ldsm4(bRow + np * 16 * wStr + kc * 32, bh);
            ldsm4(bRow + wLo + np * 16 * wStr + kc * 32, bl);
            #pragma unroll
            for (int m = 0; m < 2; m++) {
                #pragma unroll
                for (int h = 0; h < 2; h++) {
                    float* d = acc + ((m * NPAIR + np) * 2 + h) * 4;
                    mma16816(d, ah + m * 4, bh + h * 2);
                    mma16816(d, ah + m * 4, bl + h * 2);
                    mma16816(d, al + m * 4, bh + h * 2);
                }
            }
        }
    }
}

__device__ __forceinline__ void layer1_tail(
    uint32_t aA, uint32_t aW, int lane, int mbase, int nbase, float* acc)
{
    const uint32_t aAddr = aA + (uint32_t)(mbase + lane) * ER + 256;
    const uint32_t bAddr = aW + (uint32_t)(nbase + lane) * ER + 256;
    uint32_t ah[4], al[4], bh[4], bl[4];
    ldsm4(aAddr, ah);
    ldsm4(aAddr + EA_LO, al);
    ldsm4(bAddr, bh);
    ldsm4(bAddr + EW_LO128, bl);
    #pragma unroll
    for (int m = 0; m < 2; m++)
        #pragma unroll
        for (int n4 = 0; n4 < 4; n4++) {
            float* d = acc + ((m * 2 + (n4 >> 1)) * 2 + (n4 & 1)) * 4;
            mma16808(d, ah + 2 * m, bh[n4]);
            mma16808(d, ah + 2 * m, bl[n4]);
            mma16808(d, al + 2 * m, bh[n4]);
        }
}

__device__ __forceinline__ void epi12(unsigned char* Ab, const float* bias,
                                      int lane, int mbase, int nbase, const float* acc)
{
    #pragma unroll
    for (int m = 0; m < 2; m++)
        #pragma unroll
        for (int np = 0; np < 2; np++)
            #pragma unroll
            for (int h = 0; h < 2; h++) {
                const float* d = acc + ((m * 2 + np) * 2 + h) * 4;
                int c = nbase + np * 16 + h * 8 + 2 * (lane & 3);
                int r = mbase + m * 16 + (lane >> 2);
                float b0 = bias[c], b1 = bias[c + 1];
                float v0 = fmaxf(d[0] + b0, 0.f), v1 = fmaxf(d[1] + b1, 0.f);
                float v2 = fmaxf(d[2] + b0, 0.f), v3 = fmaxf(d[3] + b1, 0.f);
                __nv_bfloat162 hA = __floats2bfloat162_rn(v0, v1);
                __nv_bfloat162 lA = __floats2bfloat162_rn(v0 - __low2float(hA),
                                                          v1 - __high2float(hA));
                __nv_bfloat162 hB = __floats2bfloat162_rn(v2, v3);
                __nv_bfloat162 lB = __floats2bfloat162_rn(v2 - __low2float(hB),
                                                          v3 - __high2float(hB));
                uint32_t o0 = (uint32_t)r * ER + (uint32_t)c * 2;
                uint32_t o1 = o0 + 8u * ER;
                *(uint32_t*)(Ab + o0)         = *(uint32_t*)&hA;
                *(uint32_t*)(Ab + EA_LO + o0) = *(uint32_t*)&lA;
                *(uint32_t*)(Ab + o1)         = *(uint32_t*)&hB;
                *(uint32_t*)(Ab + EA_LO + o1) = *(uint32_t*)&lB;
            }
}

// ---------------- edge MLP; DIR=1 fuses the factor GRU; FIRST=step0 ---------
#define SM_W    34816
#define SM_IDX  104448
#define SM_BIAS 104704
#define SM_MBW  107008
#define EDGE_SMEM_BYTES 107040
template<int DIR, int FIRST>
__global__ __launch_bounds__(256, 2) void edge_mma_kernel(
    const __nv_bfloat16* __restrict__ Ahi, const __nv_bfloat16* __restrict__ Alo,
    const __nv_bfloat16* __restrict__ Bhi, const __nv_bfloat16* __restrict__ Blo,
    const int* __restrict__ idxArr,
    const __nv_bfloat16* __restrict__ fhi, const __nv_bfloat16* __restrict__ flo,
    const unsigned char* __restrict__ wsrc,
    const float* __restrict__ b1, const float* __restrict__ b2,
    const float* __restrict__ b3,
    float* __restrict__ nm,
    const unsigned char* __restrict__ gw,
    const float* __restrict__ gbih, const float* __restrict__ gbhh,
    float* __restrict__ gh,
    __nv_bfloat16* __restrict__ gh_hi, __nv_bfloat16* __restrict__ gh_lo)
{
    extern __shared__ __align__(256) unsigned char sm[];
    const uint32_t smb = smem_u32(sm);
    const int tid = threadIdx.x;
    const int e0 = blockIdx.x * 64;
    const int p0 = e0 >> 1;

    int*   idx    = (int*)(sm + SM_IDX);
    float* bias_s = (float*)(sm + SM_BIAS);
    const uint32_t mbw = smb + SM_MBW;

    if (tid == 0) MBARRIER_INIT(mbw, 1u);
    __syncthreads();
    if (tid == 0) {
        MBARRIER_EXPECT_TX(mbw, 69632u);
        bulk_copy_g2s(smb + SM_W, wsrc, 69632u, mbw);
    }
    if (tid < 64) idx[tid] = idxArr[e0 + tid];
    for (int i = tid; i < (DIR ? 576 : 320); i += 256) {
        float v;
        if (i < 128)      v = b1[i];
        else if (i < 256) v = b2[i - 128];
        else if (i < 320) v = b3[i - 256];
        else {
            int g = i - 320;
            if (g < 128)      v = gbih[g] + gbhh[g];
            else if (g < 192) v = gbih[g];
            else              v = gbhh[g - 64];
        }
        bias_s[i] = v;
    }
    __syncthreads();

    if (!FIRST) {
        int r = tid >> 3, q = tid & 7;
        const __nv_bfloat16* srcH = (DIR == 0) ? Ahi : Bhi;
        const __nv_bfloat16* srcL = (DIR == 0) ? Alo : Blo;
        uint4 hv = *(const uint4*)(srcH + (size_t)(p0 + r) * 64 + q * 8);
        uint4 lv = *(const uint4*)(srcL + (size_t)(p0 + r) * 64 + q * 8);
        uint32_t cb = (DIR == 0) ? 0u : 128u;
        uint32_t o0 = (uint32_t)(2 * r)     * ER + cb + q * 16;
        uint32_t o1 = (uint32_t)(2 * r + 1) * ER + cb + q * 16;
        *(uint4*)(sm + o0)         = hv;  *(uint4*)(sm + o1)         = hv;
        *(uint4*)(sm + EA_LO + o0) = lv;  *(uint4*)(sm + EA_LO + o1) = lv;
    }
    if (!(FIRST && DIR == 0)) {
        for (int i = tid; i < 512; i += 256) {
            int e = i >> 3, q = i & 7;
            int s = idx[e];
            const __nv_bfloat16* srcH = (DIR == 0) ? Bhi : Ahi;
            const __nv_bfloat16* srcL = (DIR == 0) ? Blo : Alo;
            uint4 hv = *(const uint4*)(srcH + (size_t)s * 64 + q * 8);
            uint4 lv = *(const uint4*)(srcL + (size_t)s * 64 + q * 8);
            uint32_t cb = (DIR == 0) ? 128u : 0u;
            uint32_t o = (uint32_t)e * ER + cb + q * 16;
            *(uint4*)(sm + o)         = hv;
            *(uint4*)(sm + EA_LO + o) = lv;
        }
    }
    if (tid < 64) {
        int e = tid;
        int rowIdx = (DIR == 0) ? (p0 + (e >> 1)) : idx[e];
        int colIdx = (DIR == 0) ? idx[e] : (p0 + (e >> 1));
        uint2 rh = *(const uint2*)(fhi + (size_t)rowIdx * 4);
        uint2 ch = *(const uint2*)(fhi + (size_t)colIdx * 4);
        uint2 rl = *(const uint2*)(flo + (size_t)rowIdx * 4);
        uint2 cl = *(const uint2*)(flo + (size_t)colIdx * 4);
        uint32_t o = (uint32_t)e * ER + 256;
        *(uint4*)(sm + o)         = make_uint4(rh.x, rh.y, ch.x, ch.y);
        *(uint4*)(sm + EA_LO + o) = make_uint4(rl.x, rl.y, cl.x, cl.y);
    }
    __syncthreads();

    const int w = tid >> 5, lane = tid & 31;
    const int mbase = (w & 1) * 32;
    const int nb32  = (w >> 1) * 32;
    const int nb16  = (w >> 1) * 16;
    float acc[32];

    // ---- layer 1 ----
    MBARRIER_WAIT_PARITY(mbw, 0);
    #pragma unroll
    for (int i = 0; i < 32; i++) acc[i] = 0.f;
    if (FIRST && DIR == 0) {
    } else if (FIRST && DIR == 1) {
        layer_mma_s<4, 2>(smb, smb + SM_W, ER, EA_LO, EW_LO128, lane, mbase, nb32, acc);
    } else {
        layer_mma_s<8, 2>(smb, smb + SM_W, ER, EA_LO, EW_LO128, lane, mbase, nb32, acc);
    }
    layer1_tail(smb, smb + SM_W, lane, mbase, nb32, acc);
    __syncthreads();
    if (tid == 0) {
        MBARRIER_EXPECT_TX(mbw, 69632u);
        bulk_copy_g2s(smb + SM_W, wsrc + 69632, 69632u, mbw);
    }
    epi12(sm, bias_s, lane, mbase, nb32, acc);
    __syncthreads();

    // ---- layer 2 ----
    MBARRIER_WAIT_PARITY(mbw, 1);
    #pragma unroll
    for (int i = 0; i < 32; i++) acc[i] = 0.f;
    layer_mma_s<8, 2>(smb, smb + SM_W, ER, EA_LO, EW_LO128, lane, mbase, nb32, acc);
    __syncthreads();
    if (tid == 0) {
        MBARRIER_EXPECT_TX(mbw, 34816u);
        bulk_copy_g2s(smb + SM_W, wsrc + 139264, 34816u, mbw);
    }
    epi12(sm, bias_s + 128, lane, mbase, nb32, acc);
    __syncthreads();

    // ---- layer 3 ----
    MBARRIER_WAIT_PARITY(mbw, 0);
    if (DIR == 1 && !FIRST) {   // prefetch A2 h-part during L3 MMA
        unsigned char* A2h = sm + 87040;
        unsigned char* A2l = sm + 95744;
        int p = tid >> 3, q = tid & 7;
        uint4 hv = *(const uint4*)(Bhi + (size_t)(p0 + p) * 64 + q * 8);
        uint4 lv = *(const uint4*)(Blo + (size_t)(p0 + p) * 64 + q * 8);
        uint32_t o = (uint32_t)p * ER + 128 + q * 16;
        *(uint4*)(A2h + o) = hv;
        *(uint4*)(A2l + o) = lv;
    }
    #pragma unroll
    for (int i = 0; i < 16; i++) acc[i] = 0.f;
    layer_mma_s<8, 1>(smb, smb + SM_W, ER, EA_LO, EW_LO64, lane, mbase, nb16, acc);

    if (DIR == 0) {
        #pragma unroll
        for (int m = 0; m < 2; m++)
            #pragma unroll
            for (int h = 0; h < 2; h++) {
                const float* d = acc + (m * 2 + h) * 4;
                int c = nb16 + h * 8 + 2 * (lane & 3);
                int r = mbase + m * 16 + (lane >> 2);
                float b0 = bias_s[256 + c], b1v = bias_s[256 + c + 1];
                float* q0 = nm + (size_t)idx[r] * 64 + c;
                float* q1 = nm + (size_t)idx[r + 8] * 64 + c;
                atomicAdd(q0,     d[0] + b0);
                atomicAdd(q0 + 1, d[1] + b1v);
                atomicAdd(q1,     d[2] + b0);
                atomicAdd(q1 + 1, d[3] + b1v);
            }
    } else {
        // ========== fused factor GRU: shfl pair-sum straight into A2 =======
        unsigned char* A2h = sm + 87040;
        unsigned char* A2l = sm + 95744;
        // pair-sum in registers (rows 2p/2p+1 are lane^4 partners, same cols)
        #pragma unroll
        for (int m = 0; m < 2; m++)
            #pragma unroll
            for (int h = 0; h < 2; h++) {
                const float* d = acc + (m * 2 + h) * 4;
                int c = nb16 + h * 8 + 2 * (lane & 3);
                float b0 = bias_s[256 + c], b1v = bias_s[256 + c + 1];
                float x0 = d[0] + b0, x1 = d[1] + b1v;
                float x2 = d[2] + b0, x3 = d[3] + b1v;
                float y0 = __shfl_xor_sync(0xffffffffu, x0, 4);
                float y1 = __shfl_xor_sync(0xffffffffu, x1, 4);
                float y2 = __shfl_xor_sync(0xffffffffu, x2, 4);
                float y3 = __shfl_xor_sync(0xffffffffu, x3, 4);
                if (((lane >> 2) & 1) == 0) {
                    int p = (mbase + m * 16 + (lane >> 2)) >> 1;  // factors p, p+4
                    float s0 = x0 + y0, s1 = x1 + y1;
                    float s2 = x2 + y2, s3 = x3 + y3;
                    __nv_bfloat162 hA = __floats2bfloat162_rn(s0, s1);
                    __nv_bfloat162 lA = __floats2bfloat162_rn(s0 - __low2float(hA),
                                                              s1 - __high2float(hA));
                    __nv_bfloat162 hB = __floats2bfloat162_rn(s2, s3);
                    __nv_bfloat162 lB = __floats2bfloat162_rn(s2 - __low2float(hB),
                                                              s3 - __high2float(hB));
                    uint32_t o0 = (uint32_t)p * ER + (uint32_t)c * 2;
                    uint32_t o1 = o0 + 4u * ER;
                    *(uint32_t*)(A2h + o0) = *(uint32_t*)&hA;
                    *(uint32_t*)(A2l + o0) = *(uint32_t*)&lA;
                    *(uint32_t*)(A2h + o1) = *(uint32_t*)&hB;
                    *(uint32_t*)(A2l + o1) = *(uint32_t*)&lB;
                }
            }
        __syncthreads();     // all L3 MMA reads + A2 writes done
        if (tid == 0) {      // Wrz -> [0, 69632) (overwrites A + W3)
            MBARRIER_EXPECT_TX(mbw, 69632u);
            bulk_copy_g2s(smb, gw, 69632u, mbw);
        }

        float* acc1 = acc;
        float* acc2 = acc + 16;
        #pragma unroll
        for (int i = 0; i < 32; i++) acc[i] = 0.f;
        const int gnb = w * 16;
        MBARRIER_WAIT_PARITY(mbw, 1);
        if (FIRST) {
            layer_mma_2s<4, 1>(smb + 87040, ER, 8704, smb, ER, 34816,
                               lane, 0, gnb, acc1);
        } else {
            layer_mma_2s<8, 1>(smb + 87040, ER, 8704, smb, ER, 34816,
                               lane, 0, gnb, acc1);
        }
        __syncthreads();
        if (tid == 0) {
            MBARRIER_EXPECT_TX(mbw, 36864u);
            bulk_copy_g2s(smb, gw + 69632, 36864u, mbw);
        }
        MBARRIER_WAIT_PARITY(mbw, 0);
        if (!(FIRST && (w >= 4))) {
            uint32_t aOff = (gnb >= 64) ? 128u : 0u;
            layer_mma_2s<4, 1>(smb + 87040 + aOff, ER, 8704, smb, 144, 18432,
                               lane, 0, gnb, acc2);
        }
        __syncthreads();

        float* gs = (float*)(sm + 36864);
        #pragma unroll
        for (int m = 0; m < 2; m++)
            #pragma unroll
            for (int hh = 0; hh < 2; hh++) {
                int c = gnb + hh * 8 + 2 * (lane & 3);
                int r = m * 16 + (lane >> 2);
                const float* d1 = acc1 + (m * 2 + hh) * 4;
                const float* d2 = acc2 + (m * 2 + hh) * 4;
                gs[r * 256 + c]                 = d1[0];
                gs[r * 256 + c + 1]             = d1[1];
                gs[(r + 8) * 256 + c]           = d1[2];
                gs[(r + 8) * 256 + c + 1]       = d1[3];
                gs[r * 256 + 128 + c]           = d2[0];
                gs[r * 256 + 128 + c + 1]       = d2[1];
                gs[(r + 8) * 256 + 128 + c]     = d2[2];
                gs[(r + 8) * 256 + 128 + c + 1] = d2[3];
            }
        __syncthreads();

        const float* gb = bias_s + 320;
        for (int i = tid; i < 2048; i += 256) {
            int p = i >> 6, d = i & 63;
            int f = p0 + p;
            const float* g = gs + p * 256;
            float pr = g[d]       + gb[d];
            float pz = g[64 + d]  + gb[64 + d];
            float in = g[128 + d] + gb[128 + d];
            float hn = g[192 + d] + gb[192 + d];
            float rr = 1.f / (1.f + expf(-pr));
            float zz = 1.f / (1.f + expf(-pz));
            float nn = tanhf(in + rr * hn);
            float hv = FIRST ? 0.f : gh[(size_t)f * 64 + d];
            float hnew = (1.f - zz) * nn + zz * hv;
            gh[(size_t)f * 64 + d] = hnew;
            __nv_bfloat16 hb = __float2bfloat16(hnew);
            gh_hi[(size_t)f * 64 + d] = hb;
            gh_lo[(size_t)f * 64 + d] = __float2bfloat16(hnew - __bfloat162float(hb));
        }
    }
}

// ---------------- GRU-64 for var; LAST skips dead hi/lo plane writes --------
#define G64_W    34816
#define G64_BIAS 104448
#define G64_MBW  105472
#define G64_SMEM_BYTES 105504
template<int LAST>
__global__ __launch_bounds__(256, 2) void gru64_kernel(
    float* __restrict__ h,
    __nv_bfloat16* __restrict__ h_hi, __nv_bfloat16* __restrict__ h_lo,
    float* __restrict__ x,
    const unsigned char* __restrict__ wsrc,
    const float* __restrict__ bih, const float* __restrict__ bhh,
    int nrows)
{
    extern __shared__ __align__(256) unsigned char sm[];
    const uint32_t smb = smem_u32(sm);
    const int tid = threadIdx.x;
    const int r0 = blockIdx.x * 64;

    float* bias_s = (float*)(sm + G64_BIAS);
    const uint32_t mbw = smb + G64_MBW;

    if (tid == 0) MBARRIER_INIT(mbw, 1u);
    __syncthreads();
    if (tid == 0) {
        MBARRIER_EXPECT_TX(mbw, 69632u);
        bulk_copy_g2s(smb + G64_W, wsrc, 69632u, mbw);
    }
    {
        int i = tid;
        float v;
        if (i < 128)      v = bih[i] + bhh[i];
        else if (i < 192) v = bih[i];
        else              v = bhh[i - 64];
        bias_s[i & 255] = v;
    }

    for (int i = tid; i < 64 * 32; i += 256) {
        int e = i >> 5, q = i & 31;
        int rr = r0 + e;
        int rc = rr < nrows ? rr : nrows - 1;
        float4 xv;
        if (q < 16) {
            xv = *(const float4*)(x + (size_t)rc * 64 + q * 4);
            if (rr < nrows) *(float4*)(x + (size_t)rc * 64 + q * 4) = make_float4(0.f, 0.f, 0.f, 0.f);
        } else {
            xv = *(const float4*)(h + (size_t)rc * 64 + (q - 16) * 4);
        }
        __nv_bfloat162 h01 = __floats2bfloat162_rn(xv.x, xv.y);
        __nv_bfloat162 h23 = __floats2bfloat162_rn(xv.z, xv.w);
        __nv_bfloat162 l01 = __floats2bfloat162_rn(xv.x - __low2float(h01), xv.y - __high2float(h01));
        __nv_bfloat162 l23 = __floats2bfloat162_rn(xv.z - __low2float(h23), xv.w - __high2float(h23));
        uint32_t off = (uint32_t)e * ER + (uint32_t)q * 8;
        *(uint2*)(sm + off)         = make_uint2(*(uint32_t*)&h01, *(uint32_t*)&h23);
        *(uint2*)(sm + EA_LO + off) = make_uint2(*(uint32_t*)&l01, *(uint32_t*)&l23);
    }
    __syncthreads();

    const int w = tid >> 5, lane = tid & 31;
    const int mbase = (w & 1) * 32;
    const int nb32  = (w >> 1) * 32;
    float acc1[32], acc2[32];
    #pragma unroll
    for (int i = 0; i < 32; i++) { acc1[i] = 0.f; acc2[i] = 0.f; }

    MBARRIER_WAIT_PARITY(mbw, 0);
    layer_mma_2s<8, 2>(smb, ER, EA_LO, smb + G64_W, ER, 34816, lane, mbase, nb32, acc1);
    __syncthreads();
    if (tid == 0) {
        MBARRIER_EXPECT_TX(mbw, 36864u);
        bulk_copy_g2s(smb + G64_W, wsrc + 69632, 36864u, mbw);
    }
    MBARRIER_WAIT_PARITY(mbw, 1);
    {
        uint32_t aOff = (nb32 >= 64) ? 128u : 0u;
        int nbW = nb32 & 63;
        int wBase = (nb32 >= 64) ? 64 : 0;
        layer_mma_2s<4, 2>(smb + aOff, ER, EA_LO,
                           smb + G64_W, 144, 18432, lane, mbase, wBase + nbW, acc2);
    }
    __syncthreads();

    float* gs = (float*)sm;
    #pragma unroll
    for (int m = 0; m < 2; m++)
        #pragma unroll
        for (int np = 0; np < 2; np++)
            #pragma unroll
            for (int hh = 0; hh < 2; hh++) {
                int c = nb32 + np * 16 + hh * 8 + 2 * (lane & 3);
                int r = mbase + m * 16 + (lane >> 2);
                const float* d1 = acc1 + ((m * 2 + np) * 2 + hh) * 4;
                const float* d2 = acc2 + ((m * 2 + np) * 2 + hh) * 4;
                gs[r * 256 + c]                 = d1[0];
                gs[r * 256 + c + 1]             = d1[1];
                gs[(r + 8) * 256 + c]           = d1[2];
                gs[(r + 8) * 256 + c + 1]       = d1[3];
                gs[r * 256 + 128 + c]           = d2[0];
                gs[r * 256 + 128 + c + 1]       = d2[1];
                gs[(r + 8) * 256 + 128 + c]     = d2[2];
                gs[(r + 8) * 256 + 128 + c + 1] = d2[3];
            }
    __syncthreads();

    for (int i = tid; i < 64 * 64; i += 256) {
        int e = i >> 6, d = i & 63;
        int r = r0 + e;
        if (r >= nrows) continue;
        const float* g = gs + e * 256;
        float pr = g[d]       + bias_s[d];
        float pz = g[64 + d]  + bias_s[64 + d];
        float in = g[128 + d] + bias_s[128 + d];
        float hn = g[192 + d] + bias_s[192 + d];
        float rr = 1.f / (1.f + expf(-pr));
        float zz = 1.f / (1.f + expf(-pz));
        float nn = tanhf(in + rr * hn);
        float hv = h[(size_t)r * 64 + d];
        float hnew = (1.f - zz) * nn + zz * hv;
        h[(size_t)r * 64 + d] = hnew;
        if (!LAST) {
            __nv_bfloat16 hb = __float2bfloat16(hnew);
            h_hi[(size_t)r * 64 + d] = hb;
            h_lo[(size_t)r * 64 + d] = __float2bfloat16(hnew - __bfloat162float(hb));
        }
    }
}

// ---------------- readout (unchanged) ----------------
__global__ __launch_bounds__(256) void readout_kernel(
    const float* __restrict__ h,
    const float* __restrict__ W1, const float* __restrict__ b1,
    const float* __restrict__ W2, const float* __restrict__ b2,
    const float* __restrict__ W3, const float* __restrict__ b3,
    float* __restrict__ out, int nrows)
{
    __shared__ float hs[32 * 68];
    __shared__ float l1s[32 * 132];
    __shared__ float l2s[32 * 132];
    __shared__ float lg[64];

    const int tid = threadIdx.x;
    const int r0  = blockIdx.x * 32;

    for (int i = tid; i < 32 * 64; i += 256) {
        int e = i >> 6, k = i & 63;
        int r = r0 + e;
        hs[e * 68 + k] = (r < nrows) ? h[(size_t)r * 64 + k] : 0.f;
    }
    __syncthreads();

    const int warp = tid >> 5, lane = tid & 31;
    #pragma unroll
    for (int jc = 0; jc < 4; jc++) {
        const int j0 = warp * 16 + jc * 4;
        float a[4] = {0.f, 0.f, 0.f, 0.f};
        #pragma unroll
        for (int k = 0; k < 64; k += 4) {
            float4 xv = *(const float4*)(hs + lane * 68 + k);
            #pragma unroll
            for (int jj = 0; jj < 4; jj++) {
                float4 wv = *(const float4*)(W1 + (size_t)(j0 + jj) * 64 + k);
                a[jj] += wv.x * xv.x + wv.y * xv.y + wv.z * xv.z + wv.w * xv.w;
            }
        }
        #pragma unroll
        for (int jj = 0; jj < 4; jj++)
            l1s[lane * 132 + j0 + jj] = fmaxf(a[jj] + b1[j0 + jj], 0.f);
    }
    __syncthreads();
    #pragma unroll
    for (int jc = 0; jc < 4; jc++) {
        const int j0 = warp * 16 + jc * 4;
        float a[4] = {0.f, 0.f, 0.f, 0.f};
        #pragma unroll 2
        for (int k = 0; k < 128; k += 4) {
            float4 xv = *(const float4*)(l1s + lane * 132 + k);
            #pragma unroll
            for (int jj = 0; jj < 4; jj++) {
                float4 wv = *(const float4*)(W2 + (size_t)(j0 + jj) * 128 + k);
                a[jj] += wv.x * xv.x + wv.y * xv.y + wv.z * xv.z + wv.w * xv.w;
            }
        }
        #pragma unroll
        for (int jj = 0; jj < 4; jj++)
            l2s[lane * 132 + j0 + jj] = fmaxf(a[jj] + b2[j0 + jj], 0.f);
    }
    __syncthreads();
    if (tid < 64) {
        int e = tid >> 1, j = tid & 1;
        float a = 0.f;
        #pragma unroll 4
        for (int k = 0; k < 128; k += 4) {
            float4 xv = *(const float4*)(l2s + e * 132 + k);
            float4 wv = *(const float4*)(W3 + (size_t)j * 128 + k);
            a += wv.x * xv.x + wv.y * xv.y + wv.z * xv.z + wv.w * xv.w;
        }
        lg[e * 2 + j] = a + b3[j];
    }
    __syncthreads();
    if (tid < 64) {
        int e = tid >> 1, j = tid & 1;
        int r = r0 + e;
        if (r < nrows) {
            float self  = lg[e * 2 + j];
            float other = lg[e * 2 + (j ^ 1)];
            out[(size_t)r * 2 + j] = 1.f / (1.f + expf(other - self));
        }
    }
}

extern "C" void kernel_launch(void* const* d_in, const int* in_sizes, int n_in,
                              void* d_out, int out_size)
{
    const int*   f2v_col  = (const int*)d_in[1];
    const int*   v2f_row  = (const int*)d_in[2];
    const float* f2v_feat = (const float*)d_in[4];
    const float* v2f_feat = (const float*)d_in[5];
    const float* f2v_w1 = (const float*)d_in[6];   const float* f2v_b1 = (const float*)d_in[7];
    const float* f2v_w2 = (const float*)d_in[8];   const float* f2v_b2 = (const float*)d_in[9];
    const float* f2v_w3 = (const float*)d_in[10];  const float* f2v_b3 = (const float*)d_in[11];
    const float* v2f_w1 = (const float*)d_in[12];  const float* v2f_b1 = (const float*)d_in[13];
    const float* v2f_w2 = (const float*)d_in[14];  const float* v2f_b2 = (const float*)d_in[15];
    const float* v2f_w3 = (const float*)d_in[16];  const float* v2f_b3 = (const float*)d_in[17];
    const float* gf_wih = (const float*)d_in[18];  const float* gf_whh = (const float*)d_in[19];
    const float* gf_bih = (const float*)d_in[20];  const float* gf_bhh = (const float*)d_in[21];
    const float* gv_wih = (const float*)d_in[22];  const float* gv_whh = (const float*)d_in[23];
    const float* gv_bih = (const float*)d_in[24];  const float* gv_bhh = (const float*)d_in[25];
    const float* ro_w1  = (const float*)d_in[26];  const float* ro_b1  = (const float*)d_in[27];
    const float* ro_w2  = (const float*)d_in[28];  const float* ro_b2  = (const float*)d_in[29];
    const float* ro_w3  = (const float*)d_in[30];  const float* ro_b3  = (const float*)d_in[31];
    float* out = (float*)d_out;

    float *var_h, *fac_h, *nm_var;
    __nv_bfloat16 *var_hhi, *var_hlo, *fac_hhi, *fac_hlo;
    __nv_bfloat16 *f2v_fhi, *f2v_flo, *v2f_fhi, *v2f_flo;
    unsigned char *wp_f2v, *wp_v2f, *wg_gf, *wg_gv;
    cudaGetSymbolAddress((void**)&var_h,   g_var_h);
    cudaGetSymbolAddress((void**)&fac_h,   g_fac_h);
    cudaGetSymbolAddress((void**)&nm_var,  g_nm_var);
    cudaGetSymbolAddress((void**)&var_hhi, g_var_hhi);
    cudaGetSymbolAddress((void**)&var_hlo, g_var_hlo);
    cudaGetSymbolAddress((void**)&fac_hhi, g_fac_hhi);
    cudaGetSymbolAddress((void**)&fac_hlo, g_fac_hlo);
    cudaGetSymbolAddress((void**)&f2v_fhi, g_f2v_fhi);
    cudaGetSymbolAddress((void**)&f2v_flo, g_f2v_flo);
    cudaGetSymbolAddress((void**)&v2f_fhi, g_v2f_fhi);
    cudaGetSymbolAddress((void**)&v2f_flo, g_v2f_flo);
    cudaGetSymbolAddress((void**)&wp_f2v,  g_wpack_f2v);
    cudaGetSymbolAddress((void**)&wp_v2f,  g_wpack_v2f);
    cudaGetSymbolAddress((void**)&wg_gf,   g_wgru_gf);
    cudaGetSymbolAddress((void**)&wg_gv,   g_wgru_gv);

    cudaFuncSetAttribute(edge_mma_kernel<0,0>, cudaFuncAttributeMaxDynamicSharedMemorySize, EDGE_SMEM_BYTES);
    cudaFuncSetAttribute(edge_mma_kernel<0,1>, cudaFuncAttributeMaxDynamicSharedMemorySize, EDGE_SMEM_BYTES);
    cudaFuncSetAttribute(edge_mma_kernel<1,0>, cudaFuncAttributeMaxDynamicSharedMemorySize, EDGE_SMEM_BYTES);
    cudaFuncSetAttribute(edge_mma_kernel<1,1>, cudaFuncAttributeMaxDynamicSharedMemorySize, EDGE_SMEM_BYTES);
    cudaFuncSetAttribute(gru64_kernel<0>, cudaFuncAttributeMaxDynamicSharedMemorySize, G64_SMEM_BYTES);
    cudaFuncSetAttribute(gru64_kernel<1>, cudaFuncAttributeMaxDynamicSharedMemorySize, G64_SMEM_BYTES);

    setup_kernel<<<296, 256>>>(
        f2v_w1, f2v_w2, f2v_w3, v2f_w1, v2f_w2, v2f_w3,
        gf_wih, gf_whh, gv_wih, gv_whh, f2v_feat, v2f_feat);

    for (int s = 0; s < 5; s++) {
        if (s == 0) {
            edge_mma_kernel<0,1><<<NE / 64, 256, EDGE_SMEM_BYTES>>>(
                fac_hhi, fac_hlo, var_hhi, var_hlo, f2v_col, f2v_fhi, f2v_flo,
                wp_f2v, f2v_b1, f2v_b2, f2v_b3, nm_var,
                wg_gf, gf_bih, gf_bhh, var_h, var_hhi, var_hlo);
        } else {
            edge_mma_kernel<0,0><<<NE / 64, 256, EDGE_SMEM_BYTES>>>(
                fac_hhi, fac_hlo, var_hhi, var_hlo, f2v_col, f2v_fhi, f2v_flo,
                wp_f2v, f2v_b1, f2v_b2, f2v_b3, nm_var,
                wg_gf, gf_bih, gf_bhh, var_h, var_hhi, var_hlo);
        }
        if (s < 4) {
            gru64_kernel<0><<<(NV + 63) / 64, 256, G64_SMEM_BYTES>>>(
                var_h, var_hhi, var_hlo, nm_var, wg_gf, gf_bih, gf_bhh, NV);
            if (s == 0) {
                edge_mma_kernel<1,1><<<NE / 64, 256, EDGE_SMEM_BYTES>>>(
                    var_hhi, var_hlo, fac_hhi, fac_hlo, v2f_row, v2f_fhi, v2f_flo,
                    wp_v2f, v2f_b1, v2f_b2, v2f_b3, nm_var,
                    wg_gv, gv_bih, gv_bhh, fac_h, fac_hhi, fac_hlo);
            } else {
                edge_mma_kernel<1,0><<<NE / 64, 256, EDGE_SMEM_BYTES>>>(
                    var_hhi, var_hlo, fac_hhi, fac_hlo, v2f_row, v2f_fhi, v2f_flo,
                    wp_v2f, v2f_b1, v2f_b2, v2f_b3, nm_var,
                    wg_gv, gv_bih, gv_bhh, fac_h, fac_hhi, fac_hlo);
            }
        } else {
            gru64_kernel<1><<<(NV + 63) / 64, 256, G64_SMEM_BYTES>>>(
                var_h, var_hhi, var_hlo, nm_var, wg_gf, gf_bih, gf_bhh, NV);
        }
    }

    readout_kernel<<<(NV + 31) / 32, 256>>>(
        var_h, ro_w1, ro_b1, ro_w2, ro_b2, ro_w3, ro_b3, out, NV);
}